// round 2
// baseline (speedup 1.0000x reference)
#include <cuda_runtime.h>
#include <cuda_bf16.h>
#include <math.h>

// ---------------------------------------------------------------------------
// Problem constants
// ---------------------------------------------------------------------------
#define B_    2
#define Q_    16
#define BQ_   32
#define N0_   4096
#define N1_   1024
#define N2_   256
#define DIM_  296
#define CTX_  288
#define HEADS_ 8
#define I1_   144
#define I2_   72
#define I3_   36
#define EPS_  1e-5f

// ---------------------------------------------------------------------------
// Scratch (device globals; no allocation allowed)
// ---------------------------------------------------------------------------
__device__ float g_h0[BQ_ * DIM_ * N2_];        // concat(x, mask)           (32,296,256)
__device__ float g_h1[BQ_ * DIM_ * N2_];        // layer1 out                (32,296,256)
__device__ float g_h2[BQ_ * I1_ * N2_];         // layer2 out                (32,144,256)
__device__ float g_f0[B_ * I2_ * N0_];          // adapter1 out              (2,72,4096)
__device__ float g_f1[B_ * I1_ * N1_];          // adapter2 out              (2,144,1024)
__device__ float g_c1[BQ_ * (2 * I1_) * N1_];   // concat for FP1            (32,288,1024)
__device__ float g_h3[BQ_ * I1_ * N1_];         // fp1 l1 out                (32,144,1024)
__device__ float g_h4[BQ_ * I2_ * N1_];         // fp1 l2 out                (32,72,1024)
__device__ float g_c2[BQ_ * (2 * I2_) * N0_];   // concat for FP2            (32,144,4096)
__device__ float g_h5[BQ_ * I2_ * N0_];         // fp2 l1 out                (32,72,4096)
__device__ float g_h6[BQ_ * I3_ * N0_];         // fp2 l2 out                (32,36,4096)

__device__ int   g_idx1[B_ * N1_ * 3];
__device__ float g_wt1 [B_ * N1_ * 3];
__device__ int   g_idx2[B_ * N0_ * 3];
__device__ float g_wt2 [B_ * N0_ * 3];

__device__ float g_W1f[DIM_ * DIM_],  g_b1f[DIM_];
__device__ float g_W2f[I1_ * DIM_],   g_b2f[I1_];
__device__ float g_fW1f[I1_ * 2 * I1_], g_fb1f[I1_];
__device__ float g_fW2f[I2_ * I1_],     g_fb2f[I2_];
__device__ float g_gW1f[I2_ * 2 * I2_], g_gb1f[I2_];
__device__ float g_gW2f[I3_ * I2_],     g_gb2f[I3_];

// ---------------------------------------------------------------------------
// Fold BN into conv weights:  W' = s*W,  b' = s*(b - mean) + beta,
// s = gamma * rsqrt(var + eps).  bn rows: [gamma, beta, mean, var]
// ---------------------------------------------------------------------------
__global__ void fold_bn_kernel(const float* __restrict__ W,
                               const float* __restrict__ b,
                               const float* __restrict__ bn,
                               float* __restrict__ Wf,
                               float* __restrict__ bf,
                               int M, int K) {
    int t = blockIdx.x * blockDim.x + threadIdx.x;
    if (t < M * K) {
        int m = t / K;
        float s = bn[m] * rsqrtf(bn[3 * M + m] + EPS_);
        Wf[t] = W[t] * s;
    }
    if (t < M) {
        float s = bn[t] * rsqrtf(bn[3 * M + t] + EPS_);
        bf[t] = s * (b[t] - bn[2 * M + t]) + bn[M + t];
    }
}

// ---------------------------------------------------------------------------
// Build h0 = concat([expand(x, q), bbox_mask.reshape(BQ,8,N2)], channel)
// ---------------------------------------------------------------------------
__global__ void build_h0_kernel(const float* __restrict__ x,
                                const float* __restrict__ mask,
                                float* __restrict__ h0) {
    int t = blockIdx.x * blockDim.x + threadIdx.x;
    const int total = BQ_ * DIM_ * N2_;
    if (t >= total) return;
    int n = t % N2_;
    int r = t / N2_;
    int c = r % DIM_;
    int bq = r / DIM_;
    int b = bq >> 4;  // Q=16
    float v;
    if (c < CTX_) v = x[((size_t)b * CTX_ + c) * N2_ + n];
    else          v = mask[((size_t)bq * HEADS_ + (c - CTX_)) * N2_ + n];
    h0[t] = v;
}

// ---------------------------------------------------------------------------
// Generic tiled SGEMM:  Y[b][m][n] = act( sum_k W[m][k] * X[b][k][n] + bias[m] )
// BM=64, BN=128, BK=16, 256 threads, 4x8 per-thread micro-tile.
// ---------------------------------------------------------------------------
#define BM 64
#define BN 128
#define BK 16
#define TM 4
#define TN 8

__global__ __launch_bounds__(256)
void gemm_bias_act_kernel(const float* __restrict__ W,
                          const float* __restrict__ bias,
                          const float* __restrict__ X,
                          float* __restrict__ Y,
                          int M, int N, int K, int relu) {
    const int b  = blockIdx.z;
    const int m0 = blockIdx.y * BM;
    const int n0 = blockIdx.x * BN;

    const float* Xb = X + (size_t)b * K * N;
    float*       Yb = Y + (size_t)b * M * N;

    __shared__ float Ws[BK][BM];
    __shared__ float Xs[BK][BN];

    const int tid = threadIdx.x;
    const int tm = (tid / 16) * TM;   // 0..60
    const int tn = (tid % 16) * TN;   // 0..120

    float acc[TM][TN];
#pragma unroll
    for (int i = 0; i < TM; i++)
#pragma unroll
        for (int j = 0; j < TN; j++) acc[i][j] = 0.f;

    for (int k0 = 0; k0 < K; k0 += BK) {
        // load W tile (BM x BK) transposed into Ws[k][m]
#pragma unroll
        for (int i = tid; i < BM * BK; i += 256) {
            int m = i / BK, k = i % BK;
            float v = 0.f;
            int gm = m0 + m, gk = k0 + k;
            if (gm < M && gk < K) v = W[(size_t)gm * K + gk];
            Ws[k][m] = v;
        }
        // load X tile (BK x BN)
#pragma unroll
        for (int i = tid; i < BK * BN; i += 256) {
            int k = i / BN, n = i % BN;
            float v = 0.f;
            int gk = k0 + k, gn = n0 + n;
            if (gk < K && gn < N) v = Xb[(size_t)gk * N + gn];
            Xs[k][n] = v;
        }
        __syncthreads();

#pragma unroll
        for (int kk = 0; kk < BK; kk++) {
            float a[TM], xv[TN];
#pragma unroll
            for (int i = 0; i < TM; i++) a[i] = Ws[kk][tm + i];
#pragma unroll
            for (int j = 0; j < TN; j++) xv[j] = Xs[kk][tn + j];
#pragma unroll
            for (int i = 0; i < TM; i++)
#pragma unroll
                for (int j = 0; j < TN; j++) acc[i][j] = fmaf(a[i], xv[j], acc[i][j]);
        }
        __syncthreads();
    }

#pragma unroll
    for (int i = 0; i < TM; i++) {
        int m = m0 + tm + i;
        if (m >= M) break;
        float bv = bias ? bias[m] : 0.f;
#pragma unroll
        for (int j = 0; j < TN; j++) {
            int n = n0 + tn + j;
            if (n < N) {
                float v = acc[i][j] + bv;
                if (relu) v = fmaxf(v, 0.f);
                Yb[(size_t)m * N + n] = v;
            }
        }
    }
}

// ---------------------------------------------------------------------------
// three_nn: per batch, each unknown point finds 3 nearest known points
// (stable tie-break: lower index wins, matching jax top_k on -d2)
// ---------------------------------------------------------------------------
template <int NK>
__global__ void three_nn_kernel(const float* __restrict__ unknown,  // (B, Nu, 3)
                                const float* __restrict__ known,    // (B, NK, 3)
                                int Nu,
                                int* __restrict__ idx,              // (B, Nu, 3)
                                float* __restrict__ w) {             // (B, Nu, 3)
    const int b = blockIdx.y;
    __shared__ float kx[NK], ky[NK], kz[NK];
    const float* kb = known + (size_t)b * NK * 3;
    for (int i = threadIdx.x; i < NK; i += blockDim.x) {
        kx[i] = kb[i * 3 + 0];
        ky[i] = kb[i * 3 + 1];
        kz[i] = kb[i * 3 + 2];
    }
    __syncthreads();

    int u = blockIdx.x * blockDim.x + threadIdx.x;
    if (u >= Nu) return;
    const float* up = unknown + ((size_t)b * Nu + u) * 3;
    float ux = up[0], uy = up[1], uz = up[2];

    float d0 = 3.4e38f, d1 = 3.4e38f, d2 = 3.4e38f;
    int i0 = 0, i1 = 0, i2 = 0;
    for (int i = 0; i < NK; i++) {
        float dx = ux - kx[i], dy = uy - ky[i], dz = uz - kz[i];
        float d = dx * dx + dy * dy + dz * dz;
        if (d < d0)       { d2 = d1; i2 = i1; d1 = d0; i1 = i0; d0 = d; i0 = i; }
        else if (d < d1)  { d2 = d1; i2 = i1; d1 = d;  i1 = i; }
        else if (d < d2)  { d2 = d;  i2 = i; }
    }
    float w0 = 1.f / (d0 + 1e-8f);
    float w1 = 1.f / (d1 + 1e-8f);
    float w2 = 1.f / (d2 + 1e-8f);
    float ws = w0 + w1 + w2;
    size_t o = ((size_t)b * Nu + u) * 3;
    idx[o] = i0; idx[o + 1] = i1; idx[o + 2] = i2;
    w[o] = w0 / ws; w[o + 1] = w1 / ws; w[o + 2] = w2 / ws;
}

// ---------------------------------------------------------------------------
// Fused interpolate + concat skip:
//   out[bq][c][nu]       = sum_j w[b][nu][j] * feat[bq][c][idx[b][nu][j]]   (c <  C)
//   out[bq][C + cs][nu]  = skip[b][cs][nu]                                  (else)
// ---------------------------------------------------------------------------
__global__ void interp_concat_kernel(const float* __restrict__ feat, // (BQ, C, Nk)
                                     const int* __restrict__ idx,    // (B, Nu, 3)
                                     const float* __restrict__ w,    // (B, Nu, 3)
                                     const float* __restrict__ skip, // (B, Cs, Nu)
                                     float* __restrict__ out,        // (BQ, C+Cs, Nu)
                                     int C, int Cs, int Nu, int Nk) {
    long t = (long)blockIdx.x * blockDim.x + threadIdx.x;
    long total = (long)BQ_ * (C + Cs) * Nu;
    if (t >= total) return;
    int nu = (int)(t % Nu);
    long r = t / Nu;
    int c = (int)(r % (C + Cs));
    int bq = (int)(r / (C + Cs));
    int b = bq >> 4;
    float v;
    if (c < C) {
        size_t o = ((size_t)b * Nu + nu) * 3;
        const float* fb = feat + ((size_t)bq * C + c) * Nk;
        v = w[o]     * fb[idx[o]]
          + w[o + 1] * fb[idx[o + 1]]
          + w[o + 2] * fb[idx[o + 2]];
    } else {
        v = skip[((size_t)b * Cs + (c - C)) * Nu + nu];
    }
    out[t] = v;
}

// ---------------------------------------------------------------------------
// Final projection: out[bq][n] = out_b + sum_c out_w[c] * h6[bq][c][n]
// ---------------------------------------------------------------------------
__global__ void final_out_kernel(const float* __restrict__ h,   // (BQ, 36, N0)
                                 const float* __restrict__ ow,  // (36,)
                                 const float* __restrict__ ob,  // (1,)
                                 float* __restrict__ out) {      // (BQ, N0)
    int t = blockIdx.x * blockDim.x + threadIdx.x;
    if (t >= BQ_ * N0_) return;
    int n = t % N0_;
    int bq = t / N0_;
    const float* hb = h + (size_t)bq * I3_ * N0_ + n;
    float acc = ob[0];
#pragma unroll
    for (int c = 0; c < I3_; c++) acc = fmaf(ow[c], hb[(size_t)c * N0_], acc);
    out[t] = acc;
}

// ---------------------------------------------------------------------------
// Launch
// ---------------------------------------------------------------------------
static inline int cdiv(int a, int b) { return (a + b - 1) / b; }

extern "C" void kernel_launch(void* const* d_in, const int* in_sizes, int n_in,
                              void* d_out, int out_size) {
    const float* x        = (const float*)d_in[0];
    const float* mask     = (const float*)d_in[1];
    const float* sa0_feat = (const float*)d_in[2];
    const float* sa1_feat = (const float*)d_in[3];
    const float* sa0_xyz  = (const float*)d_in[4];
    const float* sa1_xyz  = (const float*)d_in[5];
    const float* sa2_xyz  = (const float*)d_in[6];
    const float* w1       = (const float*)d_in[7];
    const float* b1       = (const float*)d_in[8];
    const float* bn1      = (const float*)d_in[9];
    const float* w2       = (const float*)d_in[10];
    const float* b2       = (const float*)d_in[11];
    const float* bn2      = (const float*)d_in[12];
    const float* a1_w     = (const float*)d_in[13];
    const float* a1_b     = (const float*)d_in[14];
    const float* a2_w     = (const float*)d_in[15];
    const float* a2_b     = (const float*)d_in[16];
    const float* fp1_w1   = (const float*)d_in[17];
    const float* fp1_b1   = (const float*)d_in[18];
    const float* fp1_bn1  = (const float*)d_in[19];
    const float* fp1_w2   = (const float*)d_in[20];
    const float* fp1_b2   = (const float*)d_in[21];
    const float* fp1_bn2  = (const float*)d_in[22];
    const float* fp2_w1   = (const float*)d_in[23];
    const float* fp2_b1   = (const float*)d_in[24];
    const float* fp2_bn1  = (const float*)d_in[25];
    const float* fp2_w2   = (const float*)d_in[26];
    const float* fp2_b2   = (const float*)d_in[27];
    const float* fp2_bn2  = (const float*)d_in[28];
    const float* out_w    = (const float*)d_in[29];
    const float* out_b    = (const float*)d_in[30];
    float* out = (float*)d_out;

    // Resolve scratch symbol addresses (host-side, capture-safe)
    float *h0, *h1, *h2, *f0, *f1, *c1, *h3, *h4, *c2, *h5, *h6;
    int *idx1, *idx2;
    float *wt1, *wt2;
    float *W1f, *b1f, *W2f, *b2f, *fW1f, *fb1f, *fW2f, *fb2f, *gW1f, *gb1f, *gW2f, *gb2f;
    cudaGetSymbolAddress((void**)&h0, g_h0);
    cudaGetSymbolAddress((void**)&h1, g_h1);
    cudaGetSymbolAddress((void**)&h2, g_h2);
    cudaGetSymbolAddress((void**)&f0, g_f0);
    cudaGetSymbolAddress((void**)&f1, g_f1);
    cudaGetSymbolAddress((void**)&c1, g_c1);
    cudaGetSymbolAddress((void**)&h3, g_h3);
    cudaGetSymbolAddress((void**)&h4, g_h4);
    cudaGetSymbolAddress((void**)&c2, g_c2);
    cudaGetSymbolAddress((void**)&h5, g_h5);
    cudaGetSymbolAddress((void**)&h6, g_h6);
    cudaGetSymbolAddress((void**)&idx1, g_idx1);
    cudaGetSymbolAddress((void**)&wt1, g_wt1);
    cudaGetSymbolAddress((void**)&idx2, g_idx2);
    cudaGetSymbolAddress((void**)&wt2, g_wt2);
    cudaGetSymbolAddress((void**)&W1f, g_W1f);
    cudaGetSymbolAddress((void**)&b1f, g_b1f);
    cudaGetSymbolAddress((void**)&W2f, g_W2f);
    cudaGetSymbolAddress((void**)&b2f, g_b2f);
    cudaGetSymbolAddress((void**)&fW1f, g_fW1f);
    cudaGetSymbolAddress((void**)&fb1f, g_fb1f);
    cudaGetSymbolAddress((void**)&fW2f, g_fW2f);
    cudaGetSymbolAddress((void**)&fb2f, g_fb2f);
    cudaGetSymbolAddress((void**)&gW1f, g_gW1f);
    cudaGetSymbolAddress((void**)&gb1f, g_gb1f);
    cudaGetSymbolAddress((void**)&gW2f, g_gW2f);
    cudaGetSymbolAddress((void**)&gb2f, g_gb2f);

    // ---- fold BN into weights ----
    fold_bn_kernel<<<cdiv(DIM_ * DIM_, 256), 256>>>(w1, b1, bn1, W1f, b1f, DIM_, DIM_);
    fold_bn_kernel<<<cdiv(I1_ * DIM_, 256), 256>>>(w2, b2, bn2, W2f, b2f, I1_, DIM_);
    fold_bn_kernel<<<cdiv(I1_ * 2 * I1_, 256), 256>>>(fp1_w1, fp1_b1, fp1_bn1, fW1f, fb1f, I1_, 2 * I1_);
    fold_bn_kernel<<<cdiv(I2_ * I1_, 256), 256>>>(fp1_w2, fp1_b2, fp1_bn2, fW2f, fb2f, I2_, I1_);
    fold_bn_kernel<<<cdiv(I2_ * 2 * I2_, 256), 256>>>(fp2_w1, fp2_b1, fp2_bn1, gW1f, gb1f, I2_, 2 * I2_);
    fold_bn_kernel<<<cdiv(I3_ * I2_, 256), 256>>>(fp2_w2, fp2_b2, fp2_bn2, gW2f, gb2f, I3_, I2_);

    // ---- build h0, layer1, layer2 ----
    build_h0_kernel<<<cdiv(BQ_ * DIM_ * N2_, 256), 256>>>(x, mask, h0);
    {
        dim3 grid(cdiv(N2_, BN), cdiv(DIM_, BM), BQ_);
        gemm_bias_act_kernel<<<grid, 256>>>(W1f, b1f, h0, h1, DIM_, N2_, DIM_, 1);
    }
    {
        dim3 grid(cdiv(N2_, BN), cdiv(I1_, BM), BQ_);
        gemm_bias_act_kernel<<<grid, 256>>>(W2f, b2f, h1, h2, I1_, N2_, DIM_, 1);
    }

    // ---- adapters (per original batch B=2, no BN, no relu) ----
    {
        dim3 grid(cdiv(N0_, BN), cdiv(I2_, BM), B_);
        gemm_bias_act_kernel<<<grid, 256>>>(a1_w, a1_b, sa0_feat, f0, I2_, N0_, 3, 0);
    }
    {
        dim3 grid(cdiv(N1_, BN), cdiv(I1_, BM), B_);
        gemm_bias_act_kernel<<<grid, 256>>>(a2_w, a2_b, sa1_feat, f1, I1_, N1_, 128, 0);
    }

    // ---- three_nn (per batch) ----
    {
        dim3 grid(cdiv(N1_, 256), B_);
        three_nn_kernel<N2_><<<grid, 256>>>(sa1_xyz, sa2_xyz, N1_, idx1, wt1);
    }
    {
        dim3 grid(cdiv(N0_, 256), B_);
        three_nn_kernel<N1_><<<grid, 256>>>(sa0_xyz, sa1_xyz, N0_, idx2, wt2);
    }

    // ---- FP1: interp(sa2->sa1) + concat f1, then two layers ----
    {
        long total = (long)BQ_ * (2 * I1_) * N1_;
        interp_concat_kernel<<<(int)((total + 255) / 256), 256>>>(h2, idx1, wt1, f1, c1, I1_, I1_, N1_, N2_);
    }
    {
        dim3 grid(cdiv(N1_, BN), cdiv(I1_, BM), BQ_);
        gemm_bias_act_kernel<<<grid, 256>>>(fW1f, fb1f, c1, h3, I1_, N1_, 2 * I1_, 1);
    }
    {
        dim3 grid(cdiv(N1_, BN), cdiv(I2_, BM), BQ_);
        gemm_bias_act_kernel<<<grid, 256>>>(fW2f, fb2f, h3, h4, I2_, N1_, I1_, 1);
    }

    // ---- FP2: interp(sa1->sa0) + concat f0, then two layers ----
    {
        long total = (long)BQ_ * (2 * I2_) * N0_;
        interp_concat_kernel<<<(int)((total + 255) / 256), 256>>>(h4, idx2, wt2, f0, c2, I2_, I2_, N0_, N1_);
    }
    {
        dim3 grid(cdiv(N0_, BN), cdiv(I2_, BM), BQ_);
        gemm_bias_act_kernel<<<grid, 256>>>(gW1f, gb1f, c2, h5, I2_, N0_, 2 * I2_, 1);
    }
    {
        dim3 grid(cdiv(N0_, BN), cdiv(I3_, BM), BQ_);
        gemm_bias_act_kernel<<<grid, 256>>>(gW2f, gb2f, h5, h6, I3_, N0_, I2_, 1);
    }

    // ---- final projection ----
    final_out_kernel<<<cdiv(BQ_ * N0_, 256), 256>>>(h6, out_w, out_b, out);
}

// round 3
// speedup vs baseline: 1.9988x; 1.9988x over previous
#include <cuda_runtime.h>
#include <cuda_bf16.h>
#include <math.h>

// ---------------------------------------------------------------------------
// Problem constants
// ---------------------------------------------------------------------------
#define B_    2
#define Q_    16
#define BQ_   32
#define N0_   4096
#define N1_   1024
#define N2_   256
#define DIM_  296
#define CTX_  288
#define HEADS_ 8
#define I1_   144
#define I2_   72
#define I3_   36
#define EPS_  1e-5f

// ---------------------------------------------------------------------------
// Scratch (device globals)
// ---------------------------------------------------------------------------
__device__ float g_W1f[DIM_ * DIM_],  g_b1f[DIM_];
__device__ float g_W2f[I1_ * DIM_],   g_b2f[I1_];
__device__ float g_fW1f[I1_ * 2 * I1_], g_fb1f[I1_];
__device__ float g_fW2f[I2_ * I1_],     g_fb2f[I2_];
__device__ float g_gW1f[I2_ * 2 * I2_], g_gb1f[I2_];
__device__ float g_gW2f[I3_ * I2_],     g_gb2f[I3_];

__device__ float g_C1[I1_ * 128], g_d1[I1_];   // fW1_B-part folded into adapter2
__device__ float g_C0[I2_ * 3],   g_d0[I2_];   // gW1_B-part folded into adapter1

__device__ float g_Tx[B_ * DIM_ * N2_];        // W1x * x  per batch   (2,296,256)
__device__ float g_h1[BQ_ * DIM_ * N2_];       // layer1 out           (32,296,256)
__device__ float g_h2[BQ_ * I1_ * N2_];        // layer2 out           (32,144,256)
__device__ float g_T2t[BQ_ * N2_ * I1_];       // fW1_A * h2, n-major  (32,256,144)
__device__ float g_s1[B_ * I1_ * N1_];         // skip term FP1        (2,144,1024)
__device__ float g_h3[BQ_ * I1_ * N1_];        // fp1 l1 out           (32,144,1024)
__device__ float g_h4[BQ_ * I2_ * N1_];        // fp1 l2 out           (32,72,1024)
__device__ float g_T4t[BQ_ * N1_ * I2_];       // gW1_A * h4, n-major  (32,1024,72)
__device__ float g_h5[BQ_ * I2_ * N0_];        // fp2 l1 out           (32,72,4096)

__device__ int   g_idx1[B_ * N1_ * 3];
__device__ float g_wt1 [B_ * N1_ * 3];
__device__ int   g_idx2[B_ * N0_ * 3];
__device__ float g_wt2 [B_ * N0_ * 3];

// ---------------------------------------------------------------------------
// Fold BN into conv weights (all 6 weight sets in ONE kernel)
// ---------------------------------------------------------------------------
__device__ __forceinline__ void fold_one(const float* __restrict__ W,
                                         const float* __restrict__ b,
                                         const float* __restrict__ bn,
                                         float* __restrict__ Wf,
                                         float* __restrict__ bf,
                                         int M, int K, int t) {
    if (t < M * K) {
        int m = t / K;
        float s = bn[m] * rsqrtf(bn[3 * M + m] + EPS_);
        Wf[t] = W[t] * s;
    }
    if (t < M) {
        float s = bn[t] * rsqrtf(bn[3 * M + t] + EPS_);
        bf[t] = s * (b[t] - bn[2 * M + t]) + bn[M + t];
    }
}

__global__ void fold_all_kernel(
    const float* w1, const float* b1, const float* bn1,
    const float* w2, const float* b2, const float* bn2,
    const float* fw1, const float* fb1, const float* fbn1,
    const float* fw2, const float* fb2, const float* fbn2,
    const float* gw1, const float* gb1, const float* gbn1,
    const float* gw2, const float* gb2, const float* gbn2,
    float* W1f, float* b1f, float* W2f, float* b2f,
    float* fW1f, float* fb1f, float* fW2f, float* fb2f,
    float* gW1f, float* gb1f, float* gW2f, float* gb2f) {
    int t = blockIdx.x * blockDim.x + threadIdx.x;
    switch (blockIdx.y) {
        case 0: fold_one(w1, b1, bn1, W1f, b1f, DIM_, DIM_, t); break;
        case 1: fold_one(w2, b2, bn2, W2f, b2f, I1_, DIM_, t); break;
        case 2: fold_one(fw1, fb1, fbn1, fW1f, fb1f, I1_, 2 * I1_, t); break;
        case 3: fold_one(fw2, fb2, fbn2, fW2f, fb2f, I2_, I1_, t); break;
        case 4: fold_one(gw1, gb1, gbn1, gW1f, gb1f, I2_, 2 * I2_, t); break;
        case 5: fold_one(gw2, gb2, gbn2, gW2f, gb2f, I3_, I2_, t); break;
    }
}

// ---------------------------------------------------------------------------
// Combine folded B-part weights with adapters:
//  C1 = fW1_B * a2_w (144x128),  d1 = fW1_B * a2_b
//  C0 = gW1_B * a1_w (72x3),     d0 = gW1_B * a1_b
// ---------------------------------------------------------------------------
__global__ void combine_kernel(const float* __restrict__ fW1f,
                               const float* __restrict__ a2_w,
                               const float* __restrict__ a2_b,
                               const float* __restrict__ gW1f,
                               const float* __restrict__ a1_w,
                               const float* __restrict__ a1_b,
                               float* __restrict__ C1, float* __restrict__ d1,
                               float* __restrict__ C0, float* __restrict__ d0) {
    int t = blockIdx.x * blockDim.x + threadIdx.x;
    const int T1 = I1_ * 128;
    if (t < T1) {
        int o = t / 128, k = t % 128;
        float s = 0.f;
        for (int c = 0; c < I1_; c++)
            s += fW1f[o * (2 * I1_) + I1_ + c] * a2_w[c * 128 + k];
        C1[t] = s;
    }
    if (t < I1_) {
        float s = 0.f;
        for (int c = 0; c < I1_; c++)
            s += fW1f[t * (2 * I1_) + I1_ + c] * a2_b[c];
        d1[t] = s;
    }
    int t2 = t - T1;
    if (t2 >= 0 && t2 < I2_ * 3) {
        int o = t2 / 3, k = t2 % 3;
        float s = 0.f;
        for (int c = 0; c < I2_; c++)
            s += gW1f[o * (2 * I2_) + I2_ + c] * a1_w[c * 3 + k];
        C0[t2] = s;
    }
    if (t2 >= I2_ * 3 && t2 < I2_ * 3 + I2_) {
        int o = t2 - I2_ * 3;
        float s = 0.f;
        for (int c = 0; c < I2_; c++)
            s += gW1f[o * (2 * I2_) + I2_ + c] * a1_b[c];
        d0[o] = s;
    }
}

// ---------------------------------------------------------------------------
// Generic tiled SGEMM with W leading-dim, optional transposed output
//   Y[b][m][n] (or Y[b][n][m]) = act( sum_k W[m*ldw+k]*X[b][k][n] + bias[m] )
// ---------------------------------------------------------------------------
template <int BM, int BN, int BK, int TX, int TY, int TM, int TN, bool TOUT>
__global__ __launch_bounds__(TX * TY)
void gemm_k(const float* __restrict__ W, int ldw,
            const float* __restrict__ bias,
            const float* __restrict__ X,
            float* __restrict__ Y,
            int M, int N, int K, int relu) {
    const int b  = blockIdx.z;
    const int m0 = blockIdx.y * BM;
    const int n0 = blockIdx.x * BN;
    const float* Xb = X + (size_t)b * K * N;
    float* Yb = Y + (size_t)b * M * N;

    __shared__ float Ws[BK][BM];
    __shared__ float Xs[BK][BN];

    const int tid = threadIdx.x;
    const int tx = tid % TX, ty = tid / TX;
    const int tm = ty * TM, tn = tx * TN;
    const int NT = TX * TY;

    float acc[TM][TN];
#pragma unroll
    for (int i = 0; i < TM; i++)
#pragma unroll
        for (int j = 0; j < TN; j++) acc[i][j] = 0.f;

    for (int k0 = 0; k0 < K; k0 += BK) {
#pragma unroll
        for (int i = tid; i < BM * BK; i += NT) {
            int m = i / BK, k = i % BK;
            int gm = m0 + m, gk = k0 + k;
            Ws[k][m] = (gm < M && gk < K) ? W[(size_t)gm * ldw + gk] : 0.f;
        }
#pragma unroll
        for (int i = tid; i < BK * BN; i += NT) {
            int k = i / BN, n = i % BN;
            int gk = k0 + k, gn = n0 + n;
            Xs[k][n] = (gk < K && gn < N) ? Xb[(size_t)gk * N + gn] : 0.f;
        }
        __syncthreads();
#pragma unroll
        for (int kk = 0; kk < BK; kk++) {
            float a[TM], xv[TN];
#pragma unroll
            for (int i = 0; i < TM; i++) a[i] = Ws[kk][tm + i];
#pragma unroll
            for (int j = 0; j < TN; j++) xv[j] = Xs[kk][tn + j];
#pragma unroll
            for (int i = 0; i < TM; i++)
#pragma unroll
                for (int j = 0; j < TN; j++) acc[i][j] = fmaf(a[i], xv[j], acc[i][j]);
        }
        __syncthreads();
    }

#pragma unroll
    for (int i = 0; i < TM; i++) {
        int m = m0 + tm + i;
        if (m >= M) break;
        float bv = bias ? bias[m] : 0.f;
#pragma unroll
        for (int j = 0; j < TN; j++) {
            int n = n0 + tn + j;
            if (n < N) {
                float v = acc[i][j] + bv;
                if (relu) v = fmaxf(v, 0.f);
                if (TOUT) Yb[(size_t)n * M + m] = v;
                else      Yb[(size_t)m * N + n] = v;
            }
        }
    }
}

// ---------------------------------------------------------------------------
// h1 = ReLU(Tx[b] + W1m * mask[bq] + b1f)   (fused mask term, K=8)
// ---------------------------------------------------------------------------
__global__ __launch_bounds__(256)
void h1_fuse_kernel(const float* __restrict__ Tx,
                    const float* __restrict__ mask,
                    const float* __restrict__ W1f,
                    const float* __restrict__ b1f,
                    float* __restrict__ h1) {
    __shared__ float Wm[DIM_ * 8];
    __shared__ float bsm[DIM_];
    int tid = threadIdx.x;
    for (int i = tid; i < DIM_ * 8; i += 256) {
        int m = i / 8, k = i % 8;
        Wm[i] = W1f[(size_t)m * DIM_ + CTX_ + k];
    }
    for (int i = tid; i < DIM_; i += 256) bsm[i] = b1f[i];
    __syncthreads();

    int bq = blockIdx.x;
    int b = bq >> 4;
    int n = tid;  // N2 = 256 = blockDim
    float mv[8];
#pragma unroll
    for (int k = 0; k < 8; k++) mv[k] = mask[((size_t)bq * 8 + k) * N2_ + n];
    const float* txb = Tx + (size_t)b * DIM_ * N2_ + n;
    float* outb = h1 + (size_t)bq * DIM_ * N2_ + n;
    for (int m = 0; m < DIM_; m++) {
        const float4* w4 = (const float4*)&Wm[m * 8];
        float4 wa = w4[0], wb = w4[1];
        float acc = txb[(size_t)m * N2_] + bsm[m];
        acc += wa.x * mv[0] + wa.y * mv[1] + wa.z * mv[2] + wa.w * mv[3];
        acc += wb.x * mv[4] + wb.y * mv[5] + wb.z * mv[6] + wb.w * mv[7];
        outb[(size_t)m * N2_] = fmaxf(acc, 0.f);
    }
}

// ---------------------------------------------------------------------------
// three_nn (per batch): branch-skipped streaming top-3
// ---------------------------------------------------------------------------
template <int NK>
__global__ void three_nn_kernel(const float* __restrict__ unknown,
                                const float* __restrict__ known,
                                int Nu,
                                int* __restrict__ idx,
                                float* __restrict__ w) {
    const int b = blockIdx.y;
    __shared__ float kx[NK], ky[NK], kz[NK];
    const float* kb = known + (size_t)b * NK * 3;
    for (int i = threadIdx.x; i < NK; i += blockDim.x) {
        kx[i] = kb[i * 3 + 0];
        ky[i] = kb[i * 3 + 1];
        kz[i] = kb[i * 3 + 2];
    }
    __syncthreads();

    int u = blockIdx.x * blockDim.x + threadIdx.x;
    if (u >= Nu) return;
    const float* up = unknown + ((size_t)b * Nu + u) * 3;
    float ux = up[0], uy = up[1], uz = up[2];

    float d0 = 3.4e38f, d1 = 3.4e38f, d2 = 3.4e38f;
    int i0 = 0, i1 = 0, i2 = 0;
    for (int i = 0; i < NK; i++) {
        float dx = ux - kx[i], dy = uy - ky[i], dz = uz - kz[i];
        float d = fmaf(dx, dx, fmaf(dy, dy, dz * dz));
        if (d < d2) {
            if (d < d0)      { d2 = d1; i2 = i1; d1 = d0; i1 = i0; d0 = d; i0 = i; }
            else if (d < d1) { d2 = d1; i2 = i1; d1 = d;  i1 = i; }
            else             { d2 = d;  i2 = i; }
        }
    }
    float w0 = 1.f / (d0 + 1e-8f);
    float w1 = 1.f / (d1 + 1e-8f);
    float w2 = 1.f / (d2 + 1e-8f);
    float ws = w0 + w1 + w2;
    size_t o = ((size_t)b * Nu + u) * 3;
    idx[o] = i0; idx[o + 1] = i1; idx[o + 2] = i2;
    w[o] = w0 / ws; w[o + 1] = w1 / ws; w[o + 2] = w2 / ws;
}

// ---------------------------------------------------------------------------
// FP1 fused: h3[bq][c][nu] = ReLU( sum_j w_j*T2t[bq][idx_j][c] + s1[b][c][nu]
//                                  + fb1[c] + d1[c] )
// ---------------------------------------------------------------------------
__global__ __launch_bounds__(256)
void interp_fuse1_kernel(const float* __restrict__ T2t,
                         const int* __restrict__ idx,
                         const float* __restrict__ wt,
                         const float* __restrict__ s1,
                         const float* __restrict__ fb1,
                         const float* __restrict__ d1,
                         float* __restrict__ h3) {
    __shared__ float bs[I1_];
    int tid = threadIdx.x;
    if (tid < I1_) bs[tid] = fb1[tid] + d1[tid];
    __syncthreads();

    int bq = blockIdx.y, b = bq >> 4;
    int nu = blockIdx.x * 256 + tid;
    size_t o = ((size_t)b * N1_ + nu) * 3;
    int j0 = idx[o], j1 = idx[o + 1], j2 = idx[o + 2];
    float w0 = wt[o], w1 = wt[o + 1], w2 = wt[o + 2];
    const float* p0 = T2t + ((size_t)bq * N2_ + j0) * I1_;
    const float* p1 = T2t + ((size_t)bq * N2_ + j1) * I1_;
    const float* p2 = T2t + ((size_t)bq * N2_ + j2) * I1_;
    const float* s1b = s1 + (size_t)b * I1_ * N1_ + nu;
    float* outb = h3 + (size_t)bq * I1_ * N1_ + nu;
#pragma unroll 4
    for (int c = 0; c < I1_; c++) {
        float v = w0 * p0[c] + w1 * p1[c] + w2 * p2[c]
                + s1b[(size_t)c * N1_] + bs[c];
        outb[(size_t)c * N1_] = fmaxf(v, 0.f);
    }
}

// ---------------------------------------------------------------------------
// FP2 fused: h5[bq][c][nu] = ReLU( sum_j w_j*T4t[bq][idx_j][c]
//                                  + C0[c]*sa0f[b][:,nu] + d0[c] + gb1[c] )
// ---------------------------------------------------------------------------
__global__ __launch_bounds__(256)
void interp_fuse2_kernel(const float* __restrict__ T4t,
                         const int* __restrict__ idx,
                         const float* __restrict__ wt,
                         const float* __restrict__ sa0f,
                         const float* __restrict__ C0,
                         const float* __restrict__ d0,
                         const float* __restrict__ gb1,
                         float* __restrict__ h5) {
    __shared__ float c0s[I2_ * 3];
    __shared__ float bs[I2_];
    int tid = threadIdx.x;
    if (tid < I2_ * 3) c0s[tid] = C0[tid];
    if (tid < I2_) bs[tid] = d0[tid] + gb1[tid];
    __syncthreads();

    int bq = blockIdx.y, b = bq >> 4;
    int nu = blockIdx.x * 256 + tid;
    size_t o = ((size_t)b * N0_ + nu) * 3;
    int j0 = idx[o], j1 = idx[o + 1], j2 = idx[o + 2];
    float w0 = wt[o], w1 = wt[o + 1], w2 = wt[o + 2];
    const float* p0 = T4t + ((size_t)bq * N1_ + j0) * I2_;
    const float* p1 = T4t + ((size_t)bq * N1_ + j1) * I2_;
    const float* p2 = T4t + ((size_t)bq * N1_ + j2) * I2_;
    float f0 = sa0f[((size_t)b * 3 + 0) * N0_ + nu];
    float f1 = sa0f[((size_t)b * 3 + 1) * N0_ + nu];
    float f2 = sa0f[((size_t)b * 3 + 2) * N0_ + nu];
    float* outb = h5 + (size_t)bq * I2_ * N0_ + nu;
#pragma unroll 4
    for (int c = 0; c < I2_; c++) {
        float v = w0 * p0[c] + w1 * p1[c] + w2 * p2[c]
                + c0s[c * 3] * f0 + c0s[c * 3 + 1] * f1 + c0s[c * 3 + 2] * f2
                + bs[c];
        outb[(size_t)c * N0_] = fmaxf(v, 0.f);
    }
}

// ---------------------------------------------------------------------------
// Fused FP2-L2 + final projection:
//   out[bq][nu] = ob + sum_m ow[m] * ReLU( sum_c gW2[m][c]*h5[bq][c][nu] + gb2[m] )
// ---------------------------------------------------------------------------
__global__ __launch_bounds__(256)
void fp2_final_kernel(const float* __restrict__ h5,
                      const float* __restrict__ gW2,
                      const float* __restrict__ gb2,
                      const float* __restrict__ ow,
                      const float* __restrict__ ob,
                      float* __restrict__ out) {
    __shared__ float Ws[I3_ * I2_];
    __shared__ float bsm[I3_], ows[I3_];
    int tid = threadIdx.x;
    for (int i = tid; i < I3_ * I2_; i += 256) Ws[i] = gW2[i];
    if (tid < I3_) { bsm[tid] = gb2[tid]; ows[tid] = ow[tid]; }
    __syncthreads();

    int bq = blockIdx.y;
    int nu = blockIdx.x * 256 + tid;
    const float* xb = h5 + (size_t)bq * I2_ * N0_ + nu;
    float acc[I3_];
#pragma unroll
    for (int m = 0; m < I3_; m++) acc[m] = bsm[m];
    for (int c = 0; c < I2_; c++) {
        float xv = xb[(size_t)c * N0_];
#pragma unroll
        for (int m = 0; m < I3_; m++) acc[m] = fmaf(Ws[m * I2_ + c], xv, acc[m]);
    }
    float r = ob[0];
#pragma unroll
    for (int m = 0; m < I3_; m++) r = fmaf(ows[m], fmaxf(acc[m], 0.f), r);
    out[(size_t)bq * N0_ + nu] = r;
}

// ---------------------------------------------------------------------------
// Launch
// ---------------------------------------------------------------------------
static inline int cdiv(int a, int b) { return (a + b - 1) / b; }

extern "C" void kernel_launch(void* const* d_in, const int* in_sizes, int n_in,
                              void* d_out, int out_size) {
    const float* x        = (const float*)d_in[0];
    const float* mask     = (const float*)d_in[1];
    const float* sa0_feat = (const float*)d_in[2];
    const float* sa1_feat = (const float*)d_in[3];
    const float* sa0_xyz  = (const float*)d_in[4];
    const float* sa1_xyz  = (const float*)d_in[5];
    const float* sa2_xyz  = (const float*)d_in[6];
    const float* w1       = (const float*)d_in[7];
    const float* b1       = (const float*)d_in[8];
    const float* bn1      = (const float*)d_in[9];
    const float* w2       = (const float*)d_in[10];
    const float* b2       = (const float*)d_in[11];
    const float* bn2      = (const float*)d_in[12];
    const float* a1_w     = (const float*)d_in[13];
    const float* a1_b     = (const float*)d_in[14];
    const float* a2_w     = (const float*)d_in[15];
    const float* a2_b     = (const float*)d_in[16];
    const float* fp1_w1   = (const float*)d_in[17];
    const float* fp1_b1   = (const float*)d_in[18];
    const float* fp1_bn1  = (const float*)d_in[19];
    const float* fp1_w2   = (const float*)d_in[20];
    const float* fp1_b2   = (const float*)d_in[21];
    const float* fp1_bn2  = (const float*)d_in[22];
    const float* fp2_w1   = (const float*)d_in[23];
    const float* fp2_b1   = (const float*)d_in[24];
    const float* fp2_bn1  = (const float*)d_in[25];
    const float* fp2_w2   = (const float*)d_in[26];
    const float* fp2_b2   = (const float*)d_in[27];
    const float* fp2_bn2  = (const float*)d_in[28];
    const float* out_w    = (const float*)d_in[29];
    const float* out_b    = (const float*)d_in[30];
    float* out = (float*)d_out;

    float *W1f, *b1f, *W2f, *b2f, *fW1f, *fb1f, *fW2f, *fb2f, *gW1f, *gb1f, *gW2f, *gb2f;
    float *C1, *d1, *C0, *d0;
    float *Tx, *h1, *h2, *T2t, *s1, *h3, *h4, *T4t, *h5;
    int *idx1, *idx2;
    float *wt1, *wt2;
    cudaGetSymbolAddress((void**)&W1f, g_W1f);   cudaGetSymbolAddress((void**)&b1f, g_b1f);
    cudaGetSymbolAddress((void**)&W2f, g_W2f);   cudaGetSymbolAddress((void**)&b2f, g_b2f);
    cudaGetSymbolAddress((void**)&fW1f, g_fW1f); cudaGetSymbolAddress((void**)&fb1f, g_fb1f);
    cudaGetSymbolAddress((void**)&fW2f, g_fW2f); cudaGetSymbolAddress((void**)&fb2f, g_fb2f);
    cudaGetSymbolAddress((void**)&gW1f, g_gW1f); cudaGetSymbolAddress((void**)&gb1f, g_gb1f);
    cudaGetSymbolAddress((void**)&gW2f, g_gW2f); cudaGetSymbolAddress((void**)&gb2f, g_gb2f);
    cudaGetSymbolAddress((void**)&C1, g_C1);     cudaGetSymbolAddress((void**)&d1, g_d1);
    cudaGetSymbolAddress((void**)&C0, g_C0);     cudaGetSymbolAddress((void**)&d0, g_d0);
    cudaGetSymbolAddress((void**)&Tx, g_Tx);
    cudaGetSymbolAddress((void**)&h1, g_h1);
    cudaGetSymbolAddress((void**)&h2, g_h2);
    cudaGetSymbolAddress((void**)&T2t, g_T2t);
    cudaGetSymbolAddress((void**)&s1, g_s1);
    cudaGetSymbolAddress((void**)&h3, g_h3);
    cudaGetSymbolAddress((void**)&h4, g_h4);
    cudaGetSymbolAddress((void**)&T4t, g_T4t);
    cudaGetSymbolAddress((void**)&h5, g_h5);
    cudaGetSymbolAddress((void**)&idx1, g_idx1); cudaGetSymbolAddress((void**)&wt1, g_wt1);
    cudaGetSymbolAddress((void**)&idx2, g_idx2); cudaGetSymbolAddress((void**)&wt2, g_wt2);

    // 1) fold all BN weights
    {
        dim3 grid(cdiv(DIM_ * DIM_, 256), 6);
        fold_all_kernel<<<grid, 256>>>(w1, b1, bn1, w2, b2, bn2,
                                       fp1_w1, fp1_b1, fp1_bn1, fp1_w2, fp1_b2, fp1_bn2,
                                       fp2_w1, fp2_b1, fp2_bn1, fp2_w2, fp2_b2, fp2_bn2,
                                       W1f, b1f, W2f, b2f, fW1f, fb1f, fW2f, fb2f,
                                       gW1f, gb1f, gW2f, gb2f);
    }
    // 2) combine skip weights with adapters
    combine_kernel<<<cdiv(I1_ * 128 + I2_ * 4, 256), 256>>>(
        fW1f, a2_w, a2_b, gW1f, a1_w, a1_b, C1, d1, C0, d0);

    // 3) three_nn (per batch)
    {
        dim3 grid(cdiv(N1_, 128), B_);
        three_nn_kernel<N2_><<<grid, 128>>>(sa1_xyz, sa2_xyz, N1_, idx1, wt1);
    }
    {
        dim3 grid(cdiv(N0_, 128), B_);
        three_nn_kernel<N1_><<<grid, 128>>>(sa0_xyz, sa1_xyz, N0_, idx2, wt2);
    }

    // 4) Tx = W1x * x (per batch, K=288)
    {
        dim3 grid(cdiv(N2_, 128), cdiv(DIM_, 64), B_);
        gemm_k<64, 128, 16, 16, 16, 4, 8, false><<<grid, 256>>>(
            W1f, DIM_, nullptr, x, Tx, DIM_, N2_, CTX_, 0);
    }
    // 5) h1 = ReLU(Tx + W1m*mask + b1f)
    h1_fuse_kernel<<<BQ_, 256>>>(Tx, mask, W1f, b1f, h1);

    // 6) h2 = ReLU(W2f*h1 + b2f)
    {
        dim3 grid(cdiv(N2_, 128), cdiv(I1_, 48), BQ_);
        gemm_k<48, 128, 16, 16, 16, 3, 8, false><<<grid, 256>>>(
            W2f, DIM_, b2f, h1, h2, I1_, N2_, DIM_, 1);
    }
    // 7) T2t = (fW1_A * h2)^T  (n-major)
    {
        dim3 grid(cdiv(N2_, 128), cdiv(I1_, 48), BQ_);
        gemm_k<48, 128, 16, 16, 16, 3, 8, true><<<grid, 256>>>(
            fW1f, 2 * I1_, nullptr, h2, T2t, I1_, N2_, I1_, 0);
    }
    // 8) s1 = C1 * sa1_feat (per batch)
    {
        dim3 grid(cdiv(N1_, 128), cdiv(I1_, 48), B_);
        gemm_k<48, 128, 16, 16, 16, 3, 8, false><<<grid, 256>>>(
            C1, 128, nullptr, sa1_feat, s1, I1_, N1_, 128, 0);
    }
    // 9) h3 = ReLU(interp(T2) + s1 + bias)
    {
        dim3 grid(N1_ / 256, BQ_);
        interp_fuse1_kernel<<<grid, 256>>>(T2t, idx1, wt1, s1, fb1f, d1, h3);
    }
    // 10) h4 = ReLU(fW2f*h3 + fb2f)
    {
        dim3 grid(cdiv(N1_, 128), 1, BQ_);
        gemm_k<72, 128, 8, 32, 8, 9, 4, false><<<grid, 256>>>(
            fW2f, I1_, fb2f, h3, h4, I2_, N1_, I1_, 1);
    }
    // 11) T4t = (gW1_A * h4)^T (n-major)
    {
        dim3 grid(cdiv(N1_, 128), 1, BQ_);
        gemm_k<72, 128, 8, 32, 8, 9, 4, true><<<grid, 256>>>(
            gW1f, 2 * I2_, nullptr, h4, T4t, I2_, N1_, I2_, 0);
    }
    // 12) h5 = ReLU(interp(T4) + C0*sa0_feat + bias)
    {
        dim3 grid(N0_ / 256, BQ_);
        interp_fuse2_kernel<<<grid, 256>>>(T4t, idx2, wt2, sa0_feat, C0, d0, gb1f, h5);
    }
    // 13) out = ob + ow . ReLU(gW2f*h5 + gb2f)
    {
        dim3 grid(N0_ / 256, BQ_);
        fp2_final_kernel<<<grid, 256>>>(h5, gW2f, gb2f, out_w, out_b, out);
    }
}

// round 4
// speedup vs baseline: 3.2492x; 1.6255x over previous
#include <cuda_runtime.h>
#include <cuda_bf16.h>
#include <math.h>

// ---------------------------------------------------------------------------
// Problem constants
// ---------------------------------------------------------------------------
#define B_    2
#define Q_    16
#define BQ_   32
#define N0_   4096
#define N1_   1024
#define N2_   256
#define DIM_  296
#define CTX_  288
#define HEADS_ 8
#define I1_   144
#define I2_   72
#define I3_   36
#define EPS_  1e-5f

// ---------------------------------------------------------------------------
// Scratch (device globals)
// ---------------------------------------------------------------------------
__device__ float g_W1f[DIM_ * DIM_],  g_b1f[DIM_];
__device__ float g_W2f[I1_ * DIM_],   g_b2f[I1_];
__device__ float g_fW1f[I1_ * 2 * I1_], g_fb1f[I1_];
__device__ float g_fW2f[I2_ * I1_],     g_fb2f[I2_];
__device__ float g_gW1f[I2_ * 2 * I2_], g_gb1f[I2_];
__device__ float g_gW2f[I3_ * I2_],     g_gb2f[I3_];

// k-major (transposed) weights
__device__ float g_W2t[DIM_ * I1_];      // (296,144)
__device__ float g_fW1At[I1_ * I1_];     // (144,144)
__device__ float g_fW2t[I1_ * I2_];      // (144,72)
__device__ float g_gW1At[I2_ * I2_];     // (72,72)

__device__ float g_C1[I1_ * 128], g_d1[I1_];
__device__ float g_C0[I2_ * 3],   g_d0[I2_];

__device__ float g_Tx[B_ * DIM_ * N2_];        // W1x * x  per batch   (2,296,256)
__device__ float g_h1[BQ_ * DIM_ * N2_];       // layer1 out           (32,296,256)
__device__ float g_T2t[BQ_ * N2_ * I1_];       // fW1A*h2, n-major     (32,256,144)
__device__ float g_s1[B_ * I1_ * N1_];         // skip term FP1        (2,144,1024)
__device__ float g_h3[BQ_ * I1_ * N1_];        // fp1 l1 out           (32,144,1024)
__device__ float g_T4t[BQ_ * N1_ * I2_];       // gW1A*h4, n-major     (32,1024,72)

__device__ int   g_idx1[B_ * N1_ * 3];
__device__ float g_wt1 [B_ * N1_ * 3];
__device__ int   g_idx2[B_ * N0_ * 3];
__device__ float g_wt2 [B_ * N0_ * 3];

// ---------------------------------------------------------------------------
// Fold BN into conv weights (all 6 sets in one kernel)
// ---------------------------------------------------------------------------
__device__ __forceinline__ void fold_one(const float* __restrict__ W,
                                         const float* __restrict__ b,
                                         const float* __restrict__ bn,
                                         float* __restrict__ Wf,
                                         float* __restrict__ bf,
                                         int M, int K, int t) {
    if (t < M * K) {
        int m = t / K;
        float s = bn[m] * rsqrtf(bn[3 * M + m] + EPS_);
        Wf[t] = W[t] * s;
    }
    if (t < M) {
        float s = bn[t] * rsqrtf(bn[3 * M + t] + EPS_);
        bf[t] = s * (b[t] - bn[2 * M + t]) + bn[M + t];
    }
}

__global__ void fold_all_kernel(
    const float* w1, const float* b1, const float* bn1,
    const float* w2, const float* b2, const float* bn2,
    const float* fw1, const float* fb1, const float* fbn1,
    const float* fw2, const float* fb2, const float* fbn2,
    const float* gw1, const float* gb1, const float* gbn1,
    const float* gw2, const float* gb2, const float* gbn2,
    float* W1f, float* b1f, float* W2f, float* b2f,
    float* fW1f, float* fb1f, float* fW2f, float* fb2f,
    float* gW1f, float* gb1f, float* gW2f, float* gb2f) {
    int t = blockIdx.x * blockDim.x + threadIdx.x;
    switch (blockIdx.y) {
        case 0: fold_one(w1, b1, bn1, W1f, b1f, DIM_, DIM_, t); break;
        case 1: fold_one(w2, b2, bn2, W2f, b2f, I1_, DIM_, t); break;
        case 2: fold_one(fw1, fb1, fbn1, fW1f, fb1f, I1_, 2 * I1_, t); break;
        case 3: fold_one(fw2, fb2, fbn2, fW2f, fb2f, I2_, I1_, t); break;
        case 4: fold_one(gw1, gb1, gbn1, gW1f, gb1f, I2_, 2 * I2_, t); break;
        case 5: fold_one(gw2, gb2, gbn2, gW2f, gb2f, I3_, I2_, t); break;
    }
}

// ---------------------------------------------------------------------------
// Transpose weights to k-major
// ---------------------------------------------------------------------------
__global__ void transpose_kernel(const float* __restrict__ W2f,
                                 const float* __restrict__ fW1f,
                                 const float* __restrict__ fW2f,
                                 const float* __restrict__ gW1f,
                                 float* __restrict__ W2t,
                                 float* __restrict__ fW1At,
                                 float* __restrict__ fW2t,
                                 float* __restrict__ gW1At) {
    int t = blockIdx.x * blockDim.x + threadIdx.x;
    switch (blockIdx.y) {
        case 0: if (t < DIM_ * I1_) { int k = t / I1_, m = t % I1_; W2t[t]   = W2f[m * DIM_ + k]; } break;
        case 1: if (t < I1_ * I1_)  { int k = t / I1_, m = t % I1_; fW1At[t] = fW1f[m * (2 * I1_) + k]; } break;
        case 2: if (t < I1_ * I2_)  { int k = t / I2_, m = t % I2_; fW2t[t]  = fW2f[m * I1_ + k]; } break;
        case 3: if (t < I2_ * I2_)  { int k = t / I2_, m = t % I2_; gW1At[t] = gW1f[m * (2 * I2_) + k]; } break;
    }
}

// ---------------------------------------------------------------------------
// Combine folded skip-branch weights with adapters
// ---------------------------------------------------------------------------
__global__ void combine_kernel(const float* __restrict__ fW1f,
                               const float* __restrict__ a2_w,
                               const float* __restrict__ a2_b,
                               const float* __restrict__ gW1f,
                               const float* __restrict__ a1_w,
                               const float* __restrict__ a1_b,
                               float* __restrict__ C1, float* __restrict__ d1,
                               float* __restrict__ C0, float* __restrict__ d0) {
    int t = blockIdx.x * blockDim.x + threadIdx.x;
    const int T1 = I1_ * 128;
    if (t < T1) {
        int o = t / 128, k = t % 128;
        float s = 0.f;
        for (int c = 0; c < I1_; c++)
            s += fW1f[o * (2 * I1_) + I1_ + c] * a2_w[c * 128 + k];
        C1[t] = s;
    }
    if (t < I1_) {
        float s = 0.f;
        for (int c = 0; c < I1_; c++)
            s += fW1f[t * (2 * I1_) + I1_ + c] * a2_b[c];
        d1[t] = s;
    }
    int t2 = t - T1;
    if (t2 >= 0 && t2 < I2_ * 3) {
        int o = t2 / 3, k = t2 % 3;
        float s = 0.f;
        for (int c = 0; c < I2_; c++)
            s += gW1f[o * (2 * I2_) + I2_ + c] * a1_w[c * 3 + k];
        C0[t2] = s;
    }
    if (t2 >= I2_ * 3 && t2 < I2_ * 3 + I2_) {
        int o = t2 - I2_ * 3;
        float s = 0.f;
        for (int c = 0; c < I2_; c++)
            s += gW1f[o * (2 * I2_) + I2_ + c] * a1_b[c];
        d0[o] = s;
    }
}

// ---------------------------------------------------------------------------
// Generic tiled SGEMM (used for the two small GEMMs: Tx, s1)
// ---------------------------------------------------------------------------
template <int BM, int BN, int BK, int TX, int TY, int TM, int TN>
__global__ __launch_bounds__(TX * TY)
void gemm_k(const float* __restrict__ W, int ldw,
            const float* __restrict__ bias,
            const float* __restrict__ X,
            float* __restrict__ Y,
            int M, int N, int K, int relu) {
    const int b  = blockIdx.z;
    const int m0 = blockIdx.y * BM;
    const int n0 = blockIdx.x * BN;
    const float* Xb = X + (size_t)b * K * N;
    float* Yb = Y + (size_t)b * M * N;

    __shared__ float Ws[BK][BM];
    __shared__ float Xs[BK][BN];

    const int tid = threadIdx.x;
    const int tx = tid % TX, ty = tid / TX;
    const int tm = ty * TM, tn = tx * TN;
    const int NT = TX * TY;

    float acc[TM][TN];
#pragma unroll
    for (int i = 0; i < TM; i++)
#pragma unroll
        for (int j = 0; j < TN; j++) acc[i][j] = 0.f;

    for (int k0 = 0; k0 < K; k0 += BK) {
#pragma unroll
        for (int i = tid; i < BM * BK; i += NT) {
            int m = i / BK, k = i % BK;
            int gm = m0 + m, gk = k0 + k;
            Ws[k][m] = (gm < M && gk < K) ? W[(size_t)gm * ldw + gk] : 0.f;
        }
#pragma unroll
        for (int i = tid; i < BK * BN; i += NT) {
            int k = i / BN, n = i % BN;
            int gk = k0 + k, gn = n0 + n;
            Xs[k][n] = (gk < K && gn < N) ? Xb[(size_t)gk * N + gn] : 0.f;
        }
        __syncthreads();
#pragma unroll
        for (int kk = 0; kk < BK; kk++) {
            float a[TM], xv[TN];
#pragma unroll
            for (int i = 0; i < TM; i++) a[i] = Ws[kk][tm + i];
#pragma unroll
            for (int j = 0; j < TN; j++) xv[j] = Xs[kk][tn + j];
#pragma unroll
            for (int i = 0; i < TM; i++)
#pragma unroll
                for (int j = 0; j < TN; j++) acc[i][j] = fmaf(a[i], xv[j], acc[i][j]);
        }
        __syncthreads();
    }

#pragma unroll
    for (int i = 0; i < TM; i++) {
        int m = m0 + tm + i;
        if (m >= M) break;
        float bv = bias ? bias[m] : 0.f;
#pragma unroll
        for (int j = 0; j < TN; j++) {
            int n = n0 + tn + j;
            if (n < N) {
                float v = acc[i][j] + bv;
                if (relu) v = fmaxf(v, 0.f);
                Yb[(size_t)m * N + n] = v;
            }
        }
    }
}

// ---------------------------------------------------------------------------
// h1 = ReLU(Tx[b] + W1m * mask[bq] + b1f)
// ---------------------------------------------------------------------------
__global__ __launch_bounds__(256)
void h1_fuse_kernel(const float* __restrict__ Tx,
                    const float* __restrict__ mask,
                    const float* __restrict__ W1f,
                    const float* __restrict__ b1f,
                    float* __restrict__ h1) {
    __shared__ float Wm[DIM_ * 8];
    __shared__ float bsm[DIM_];
    int tid = threadIdx.x;
    for (int i = tid; i < DIM_ * 8; i += 256) {
        int m = i / 8, k = i % 8;
        Wm[i] = W1f[(size_t)m * DIM_ + CTX_ + k];
    }
    for (int i = tid; i < DIM_; i += 256) bsm[i] = b1f[i];
    __syncthreads();

    int bq = blockIdx.x;
    int b = bq >> 4;
    int n = tid;
    float mv[8];
#pragma unroll
    for (int k = 0; k < 8; k++) mv[k] = mask[((size_t)bq * 8 + k) * N2_ + n];
    const float* txb = Tx + (size_t)b * DIM_ * N2_ + n;
    float* outb = h1 + (size_t)bq * DIM_ * N2_ + n;
    for (int m = 0; m < DIM_; m++) {
        const float4* w4 = (const float4*)&Wm[m * 8];
        float4 wa = w4[0], wb = w4[1];
        float acc = txb[(size_t)m * N2_] + bsm[m];
        acc += wa.x * mv[0] + wa.y * mv[1] + wa.z * mv[2] + wa.w * mv[3];
        acc += wb.x * mv[4] + wb.y * mv[5] + wb.z * mv[6] + wb.w * mv[7];
        outb[(size_t)m * N2_] = fmaxf(acc, 0.f);
    }
}

// ---------------------------------------------------------------------------
// three_nn, chunk-parallel: 256 threads = 64 unknowns x 4 chunks; block merge
// ---------------------------------------------------------------------------
template <int NK>
__global__ __launch_bounds__(256)
void three_nn2_kernel(const float* __restrict__ unknown,
                      const float* __restrict__ known,
                      int Nu,
                      int* __restrict__ idx,
                      float* __restrict__ w) {
    const int CS = NK / 4;
    const int b = blockIdx.y;
    __shared__ float kx[NK], ky[NK], kz[NK];
    __shared__ float cd[64][4][3];
    __shared__ int   ci[64][4][3];

    const float* kb = known + (size_t)b * NK * 3;
    for (int i = threadIdx.x; i < NK; i += 256) {
        kx[i] = kb[i * 3 + 0];
        ky[i] = kb[i * 3 + 1];
        kz[i] = kb[i * 3 + 2];
    }
    __syncthreads();

    int ul = threadIdx.x & 63;
    int ch = threadIdx.x >> 6;
    int u = blockIdx.x * 64 + ul;
    const float* up = unknown + ((size_t)b * Nu + u) * 3;
    float ux = up[0], uy = up[1], uz = up[2];

    float d0 = 3.4e38f, d1 = 3.4e38f, d2 = 3.4e38f;
    int i0 = 0, i1 = 0, i2 = 0;
    int base = ch * CS;
#pragma unroll 4
    for (int t = 0; t < CS; t++) {
        int i = base + t;
        float dx = ux - kx[i], dy = uy - ky[i], dz = uz - kz[i];
        float d = fmaf(dx, dx, fmaf(dy, dy, dz * dz));
        if (d < d2) {
            if (d < d0)      { d2 = d1; i2 = i1; d1 = d0; i1 = i0; d0 = d; i0 = i; }
            else if (d < d1) { d2 = d1; i2 = i1; d1 = d;  i1 = i; }
            else             { d2 = d;  i2 = i; }
        }
    }
    cd[ul][ch][0] = d0; cd[ul][ch][1] = d1; cd[ul][ch][2] = d2;
    ci[ul][ch][0] = i0; ci[ul][ch][1] = i1; ci[ul][ch][2] = i2;
    __syncthreads();

    if (threadIdx.x < 64) {
        int uu = blockIdx.x * 64 + threadIdx.x;
        float m0 = 3.4e38f, m1 = 3.4e38f, m2 = 3.4e38f;
        int j0 = 0, j1 = 0, j2 = 0;
#pragma unroll
        for (int c = 0; c < 4; c++) {
#pragma unroll
            for (int t = 0; t < 3; t++) {
                float d = cd[threadIdx.x][c][t];
                int i = ci[threadIdx.x][c][t];
                if (d < m2) {
                    if (d < m0)      { m2 = m1; j2 = j1; m1 = m0; j1 = j0; m0 = d; j0 = i; }
                    else if (d < m1) { m2 = m1; j2 = j1; m1 = d;  j1 = i; }
                    else             { m2 = d;  j2 = i; }
                }
            }
        }
        float w0 = 1.f / (m0 + 1e-8f);
        float w1 = 1.f / (m1 + 1e-8f);
        float w2 = 1.f / (m2 + 1e-8f);
        float ws = w0 + w1 + w2;
        size_t o = ((size_t)b * Nu + uu) * 3;
        idx[o] = j0; idx[o + 1] = j1; idx[o + 2] = j2;
        w[o] = w0 / ws; w[o + 1] = w1 / ws; w[o + 2] = w2 / ws;
    }
}

// ---------------------------------------------------------------------------
// fusedA: per bq, T2t = fW1A * ReLU(W2 * h1 + b2), output n-major (32,256,144)
// grid (4, 32), 256 threads: TX=16 (TN=4 over n), TY=16 (TM=9 over m)
// ---------------------------------------------------------------------------
__global__ __launch_bounds__(256)
void fusedA_kernel(const float* __restrict__ W2t,    // (296,144) k-major
                   const float* __restrict__ b2f,
                   const float* __restrict__ fW1At,  // (144,144) k-major
                   const float* __restrict__ h1,     // (32,296,256)
                   float* __restrict__ T2t) {        // (32,256,144)
    __shared__ float Ws[8 * 144];                    // [k][m]
    __shared__ float Xs[8 * 64];                     // [k][n]
    __shared__ float Hs[144][68];                    // [c][n], padded

    const int bq = blockIdx.y;
    const int n0 = blockIdx.x * 64;
    const int tid = threadIdx.x;
    const int tx = tid % 16, ty = tid / 16;
    const int tm = ty * 9, tn = tx * 4;

    const float* h1b = h1 + (size_t)bq * DIM_ * N2_;

    float acc[9][4];
#pragma unroll
    for (int i = 0; i < 9; i++)
#pragma unroll
        for (int j = 0; j < 4; j++) acc[i][j] = 0.f;

    // ---------------- phase 1: H = ReLU(W2*h1 + b2), K=296 (37 chunks of 8)
    float wr[5], xr[2];
    // prefetch chunk 0
#pragma unroll
    for (int r = 0; r < 5; r++) {
        int e = tid + r * 256;
        wr[r] = (e < 1152) ? W2t[e] : 0.f;
    }
#pragma unroll
    for (int r = 0; r < 2; r++) {
        int e = tid + r * 256;
        xr[r] = h1b[(size_t)(e >> 6) * N2_ + n0 + (e & 63)];
    }

    for (int kc = 0; kc < 37; kc++) {
        __syncthreads();
#pragma unroll
        for (int r = 0; r < 5; r++) {
            int e = tid + r * 256;
            if (e < 1152) Ws[e] = wr[r];
        }
#pragma unroll
        for (int r = 0; r < 2; r++) {
            int e = tid + r * 256;
            Xs[e] = xr[r];
        }
        __syncthreads();
        if (kc + 1 < 37) {
            int k0n = (kc + 1) * 8;
#pragma unroll
            for (int r = 0; r < 5; r++) {
                int e = tid + r * 256;
                wr[r] = (e < 1152) ? W2t[(size_t)k0n * 144 + e] : 0.f;
            }
#pragma unroll
            for (int r = 0; r < 2; r++) {
                int e = tid + r * 256;
                xr[r] = h1b[(size_t)(k0n + (e >> 6)) * N2_ + n0 + (e & 63)];
            }
        }
#pragma unroll
        for (int kk = 0; kk < 8; kk++) {
            float a[9];
#pragma unroll
            for (int i = 0; i < 9; i++) a[i] = Ws[kk * 144 + tm + i];
            float4 xv = *(const float4*)&Xs[kk * 64 + tn];
#pragma unroll
            for (int i = 0; i < 9; i++) {
                acc[i][0] = fmaf(a[i], xv.x, acc[i][0]);
                acc[i][1] = fmaf(a[i], xv.y, acc[i][1]);
                acc[i][2] = fmaf(a[i], xv.z, acc[i][2]);
                acc[i][3] = fmaf(a[i], xv.w, acc[i][3]);
            }
        }
    }
    // bias + relu -> Hs
#pragma unroll
    for (int i = 0; i < 9; i++) {
        float bv = b2f[tm + i];
        float4 hv;
        hv.x = fmaxf(acc[i][0] + bv, 0.f);
        hv.y = fmaxf(acc[i][1] + bv, 0.f);
        hv.z = fmaxf(acc[i][2] + bv, 0.f);
        hv.w = fmaxf(acc[i][3] + bv, 0.f);
        *(float4*)&Hs[tm + i][tn] = hv;
    }

    // ---------------- phase 2: T2 = fW1A * H, K=144 (18 chunks of 8)
    float acc2[9][4];
#pragma unroll
    for (int i = 0; i < 9; i++)
#pragma unroll
        for (int j = 0; j < 4; j++) acc2[i][j] = 0.f;

#pragma unroll
    for (int r = 0; r < 5; r++) {
        int e = tid + r * 256;
        wr[r] = (e < 1152) ? fW1At[e] : 0.f;
    }
    for (int kc = 0; kc < 18; kc++) {
        __syncthreads();   // covers Hs writes before first read, Ws reuse after
#pragma unroll
        for (int r = 0; r < 5; r++) {
            int e = tid + r * 256;
            if (e < 1152) Ws[e] = wr[r];
        }
        __syncthreads();
        if (kc + 1 < 18) {
#pragma unroll
            for (int r = 0; r < 5; r++) {
                int e = tid + r * 256;
                wr[r] = (e < 1152) ? fW1At[(size_t)(kc + 1) * 1152 + e] : 0.f;
            }
        }
        int kb = kc * 8;
#pragma unroll
        for (int kk = 0; kk < 8; kk++) {
            float a[9];
#pragma unroll
            for (int i = 0; i < 9; i++) a[i] = Ws[kk * 144 + tm + i];
            float4 xv = *(const float4*)&Hs[kb + kk][tn];
#pragma unroll
            for (int i = 0; i < 9; i++) {
                acc2[i][0] = fmaf(a[i], xv.x, acc2[i][0]);
                acc2[i][1] = fmaf(a[i], xv.y, acc2[i][1]);
                acc2[i][2] = fmaf(a[i], xv.z, acc2[i][2]);
                acc2[i][3] = fmaf(a[i], xv.w, acc2[i][3]);
            }
        }
    }
    // store n-major
#pragma unroll
    for (int j = 0; j < 4; j++) {
        size_t base = ((size_t)bq * N2_ + n0 + tn + j) * I1_ + tm;
#pragma unroll
        for (int i = 0; i < 9; i++) T2t[base + i] = acc2[i][j];
    }
}

// ---------------------------------------------------------------------------
// fusedB: per bq, T4t = gW1A * ReLU(fW2 * h3 + fb2), output n-major (32,1024,72)
// grid (8, 32), 256 threads: TX=32 (TN=4 over n, BN=128), TY=8 (TM=9 over m)
// ---------------------------------------------------------------------------
__global__ __launch_bounds__(256)
void fusedB_kernel(const float* __restrict__ fW2t,   // (144,72) k-major
                   const float* __restrict__ fb2f,
                   const float* __restrict__ gW1At,  // (72,72) k-major
                   const float* __restrict__ h3,     // (32,144,1024)
                   float* __restrict__ T4t) {        // (32,1024,72)
    __shared__ float Ws[8 * 72];
    __shared__ float Xs[8 * 128];
    __shared__ float Hs[72][132];

    const int bq = blockIdx.y;
    const int n0 = blockIdx.x * 128;
    const int tid = threadIdx.x;
    const int tx = tid % 32, ty = tid / 32;
    const int tm = ty * 9, tn = tx * 4;

    const float* h3b = h3 + (size_t)bq * I1_ * N1_;

    float acc[9][4];
#pragma unroll
    for (int i = 0; i < 9; i++)
#pragma unroll
        for (int j = 0; j < 4; j++) acc[i][j] = 0.f;

    // phase 1: K=144, 18 chunks of 8
    float wr[3], xr[4];
#pragma unroll
    for (int r = 0; r < 3; r++) {
        int e = tid + r * 256;
        wr[r] = (e < 576) ? fW2t[e] : 0.f;
    }
#pragma unroll
    for (int r = 0; r < 4; r++) {
        int e = tid + r * 256;
        xr[r] = h3b[(size_t)(e >> 7) * N1_ + n0 + (e & 127)];
    }
    for (int kc = 0; kc < 18; kc++) {
        __syncthreads();
#pragma unroll
        for (int r = 0; r < 3; r++) {
            int e = tid + r * 256;
            if (e < 576) Ws[e] = wr[r];
        }
#pragma unroll
        for (int r = 0; r < 4; r++) {
            int e = tid + r * 256;
            Xs[e] = xr[r];
        }
        __syncthreads();
        if (kc + 1 < 18) {
            int k0n = (kc + 1) * 8;
#pragma unroll
            for (int r = 0; r < 3; r++) {
                int e = tid + r * 256;
                wr[r] = (e < 576) ? fW2t[(size_t)k0n * 72 + e] : 0.f;
            }
#pragma unroll
            for (int r = 0; r < 4; r++) {
                int e = tid + r * 256;
                xr[r] = h3b[(size_t)(k0n + (e >> 7)) * N1_ + n0 + (e & 127)];
            }
        }
#pragma unroll
        for (int kk = 0; kk < 8; kk++) {
            float a[9];
#pragma unroll
            for (int i = 0; i < 9; i++) a[i] = Ws[kk * 72 + tm + i];
            float4 xv = *(const float4*)&Xs[kk * 128 + tn];
#pragma unroll
            for (int i = 0; i < 9; i++) {
                acc[i][0] = fmaf(a[i], xv.x, acc[i][0]);
                acc[i][1] = fmaf(a[i], xv.y, acc[i][1]);
                acc[i][2] = fmaf(a[i], xv.z, acc[i][2]);
                acc[i][3] = fmaf(a[i], xv.w, acc[i][3]);
            }
        }
    }
#pragma unroll
    for (int i = 0; i < 9; i++) {
        float bv = fb2f[tm + i];
        float4 hv;
        hv.x = fmaxf(acc[i][0] + bv, 0.f);
        hv.y = fmaxf(acc[i][1] + bv, 0.f);
        hv.z = fmaxf(acc[i][2] + bv, 0.f);
        hv.w = fmaxf(acc[i][3] + bv, 0.f);
        *(float4*)&Hs[tm + i][tn] = hv;
    }

    // phase 2: K=72, 9 chunks of 8
    float acc2[9][4];
#pragma unroll
    for (int i = 0; i < 9; i++)
#pragma unroll
        for (int j = 0; j < 4; j++) acc2[i][j] = 0.f;

#pragma unroll
    for (int r = 0; r < 3; r++) {
        int e = tid + r * 256;
        wr[r] = (e < 576) ? gW1At[e] : 0.f;
    }
    for (int kc = 0; kc < 9; kc++) {
        __syncthreads();
#pragma unroll
        for (int r = 0; r < 3; r++) {
            int e = tid + r * 256;
            if (e < 576) Ws[e] = wr[r];
        }
        __syncthreads();
        if (kc + 1 < 9) {
#pragma unroll
            for (int r = 0; r < 3; r++) {
                int e = tid + r * 256;
                wr[r] = (e < 576) ? gW1At[(size_t)(kc + 1) * 576 + e] : 0.f;
            }
        }
        int kb = kc * 8;
#pragma unroll
        for (int kk = 0; kk < 8; kk++) {
            float a[9];
#pragma unroll
            for (int i = 0; i < 9; i++) a[i] = Ws[kk * 72 + tm + i];
            float4 xv = *(const float4*)&Hs[kb + kk][tn];
#pragma unroll
            for (int i = 0; i < 9; i++) {
                acc2[i][0] = fmaf(a[i], xv.x, acc2[i][0]);
                acc2[i][1] = fmaf(a[i], xv.y, acc2[i][1]);
                acc2[i][2] = fmaf(a[i], xv.z, acc2[i][2]);
                acc2[i][3] = fmaf(a[i], xv.w, acc2[i][3]);
            }
        }
    }
#pragma unroll
    for (int j = 0; j < 4; j++) {
        size_t base = ((size_t)bq * N1_ + n0 + tn + j) * I2_ + tm;
#pragma unroll
        for (int i = 0; i < 9; i++) T4t[base + i] = acc2[i][j];
    }
}

// ---------------------------------------------------------------------------
// FP1 fused: h3 = ReLU(interp(T2t) + s1 + fb1 + d1), channel-major output
// ---------------------------------------------------------------------------
__global__ __launch_bounds__(256)
void interp_fuse1_kernel(const float* __restrict__ T2t,
                         const int* __restrict__ idx,
                         const float* __restrict__ wt,
                         const float* __restrict__ s1,
                         const float* __restrict__ fb1,
                         const float* __restrict__ d1,
                         float* __restrict__ h3) {
    __shared__ float bs[I1_];
    int tid = threadIdx.x;
    if (tid < I1_) bs[tid] = fb1[tid] + d1[tid];
    __syncthreads();

    int bq = blockIdx.y, b = bq >> 4;
    int nu = blockIdx.x * 256 + tid;
    size_t o = ((size_t)b * N1_ + nu) * 3;
    int j0 = idx[o], j1 = idx[o + 1], j2 = idx[o + 2];
    float w0 = wt[o], w1 = wt[o + 1], w2 = wt[o + 2];
    const float4* p0 = (const float4*)(T2t + ((size_t)bq * N2_ + j0) * I1_);
    const float4* p1 = (const float4*)(T2t + ((size_t)bq * N2_ + j1) * I1_);
    const float4* p2 = (const float4*)(T2t + ((size_t)bq * N2_ + j2) * I1_);
    const float* s1b = s1 + (size_t)b * I1_ * N1_ + nu;
    float* outb = h3 + (size_t)bq * I1_ * N1_ + nu;
#pragma unroll 9
    for (int cc = 0; cc < 36; cc++) {
        float4 a0 = p0[cc], a1 = p1[cc], a2 = p2[cc];
        int c = cc * 4;
        outb[(size_t)(c + 0) * N1_] = fmaxf(w0 * a0.x + w1 * a1.x + w2 * a2.x + s1b[(size_t)(c + 0) * N1_] + bs[c + 0], 0.f);
        outb[(size_t)(c + 1) * N1_] = fmaxf(w0 * a0.y + w1 * a1.y + w2 * a2.y + s1b[(size_t)(c + 1) * N1_] + bs[c + 1], 0.f);
        outb[(size_t)(c + 2) * N1_] = fmaxf(w0 * a0.z + w1 * a1.z + w2 * a2.z + s1b[(size_t)(c + 2) * N1_] + bs[c + 2], 0.f);
        outb[(size_t)(c + 3) * N1_] = fmaxf(w0 * a0.w + w1 * a1.w + w2 * a2.w + s1b[(size_t)(c + 3) * N1_] + bs[c + 3], 0.f);
    }
}

// ---------------------------------------------------------------------------
// Fused FP2: interp(T4t) + skip + FP2-L1 relu done inline, FP2-L2 + out proj
//   h5_c = ReLU(interp_c + C0[c]·f + d0[c] + gb1[c])
//   out  = ob + sum_m ow[m] * ReLU( sum_c gW2[m][c]*h5_c + gb2[m] )
// ---------------------------------------------------------------------------
__global__ __launch_bounds__(256)
void final_fuse_kernel(const float* __restrict__ T4t,
                       const int* __restrict__ idx,
                       const float* __restrict__ wt,
                       const float* __restrict__ sa0f,
                       const float* __restrict__ C0,
                       const float* __restrict__ d0v,
                       const float* __restrict__ gb1,
                       const float* __restrict__ gW2,
                       const float* __restrict__ gb2,
                       const float* __restrict__ ow,
                       const float* __restrict__ ob,
                       float* __restrict__ out) {
    __shared__ float gT[I2_ * I3_];   // gT[c*36+m] = gW2[m][c]
    __shared__ float c0s[I2_ * 3];
    __shared__ float bs[I2_];
    __shared__ float gbs[I3_], ows[I3_];
    int tid = threadIdx.x;
    for (int e = tid; e < I2_ * I3_; e += 256) {
        int c = e / I3_, m = e % I3_;
        gT[e] = gW2[m * I2_ + c];
    }
    if (tid < I2_ * 3) c0s[tid] = C0[tid];
    if (tid < I2_) bs[tid] = d0v[tid] + gb1[tid];
    if (tid < I3_) { gbs[tid] = gb2[tid]; ows[tid] = ow[tid]; }
    __syncthreads();

    int bq = blockIdx.y, b = bq >> 4;
    int nu = blockIdx.x * 256 + tid;
    size_t o = ((size_t)b * N0_ + nu) * 3;
    int j0 = idx[o], j1 = idx[o + 1], j2 = idx[o + 2];
    float w0 = wt[o], w1 = wt[o + 1], w2 = wt[o + 2];
    const float4* p0 = (const float4*)(T4t + ((size_t)bq * N1_ + j0) * I2_);
    const float4* p1 = (const float4*)(T4t + ((size_t)bq * N1_ + j1) * I2_);
    const float4* p2 = (const float4*)(T4t + ((size_t)bq * N1_ + j2) * I2_);
    float f0 = sa0f[((size_t)b * 3 + 0) * N0_ + nu];
    float f1 = sa0f[((size_t)b * 3 + 1) * N0_ + nu];
    float f2 = sa0f[((size_t)b * 3 + 2) * N0_ + nu];

    float acc[I3_];
#pragma unroll
    for (int m = 0; m < I3_; m++) acc[m] = 0.f;

#pragma unroll 3
    for (int cc = 0; cc < 18; cc++) {
        float4 a0 = p0[cc], a1 = p1[cc], a2 = p2[cc];
        int c = cc * 4;
        float hv[4];
        hv[0] = fmaxf(w0 * a0.x + w1 * a1.x + w2 * a2.x + c0s[(c + 0) * 3] * f0 + c0s[(c + 0) * 3 + 1] * f1 + c0s[(c + 0) * 3 + 2] * f2 + bs[c + 0], 0.f);
        hv[1] = fmaxf(w0 * a0.y + w1 * a1.y + w2 * a2.y + c0s[(c + 1) * 3] * f0 + c0s[(c + 1) * 3 + 1] * f1 + c0s[(c + 1) * 3 + 2] * f2 + bs[c + 1], 0.f);
        hv[2] = fmaxf(w0 * a0.z + w1 * a1.z + w2 * a2.z + c0s[(c + 2) * 3] * f0 + c0s[(c + 2) * 3 + 1] * f1 + c0s[(c + 2) * 3 + 2] * f2 + bs[c + 2], 0.f);
        hv[3] = fmaxf(w0 * a0.w + w1 * a1.w + w2 * a2.w + c0s[(c + 3) * 3] * f0 + c0s[(c + 3) * 3 + 1] * f1 + c0s[(c + 3) * 3 + 2] * f2 + bs[c + 3], 0.f);
#pragma unroll
        for (int q = 0; q < 4; q++) {
            const float4* g4 = (const float4*)&gT[(c + q) * I3_];
#pragma unroll
            for (int mm = 0; mm < 9; mm++) {
                float4 g = g4[mm];
                acc[mm * 4 + 0] = fmaf(g.x, hv[q], acc[mm * 4 + 0]);
                acc[mm * 4 + 1] = fmaf(g.y, hv[q], acc[mm * 4 + 1]);
                acc[mm * 4 + 2] = fmaf(g.z, hv[q], acc[mm * 4 + 2]);
                acc[mm * 4 + 3] = fmaf(g.w, hv[q], acc[mm * 4 + 3]);
            }
        }
    }
    float r = ob[0];
#pragma unroll
    for (int m = 0; m < I3_; m++) r = fmaf(ows[m], fmaxf(acc[m] + gbs[m], 0.f), r);
    out[(size_t)bq * N0_ + nu] = r;
}

// ---------------------------------------------------------------------------
// Launch
// ---------------------------------------------------------------------------
static inline int cdiv(int a, int b) { return (a + b - 1) / b; }

extern "C" void kernel_launch(void* const* d_in, const int* in_sizes, int n_in,
                              void* d_out, int out_size) {
    const float* x        = (const float*)d_in[0];
    const float* mask     = (const float*)d_in[1];
    const float* sa0_feat = (const float*)d_in[2];
    const float* sa1_feat = (const float*)d_in[3];
    const float* sa0_xyz  = (const float*)d_in[4];
    const float* sa1_xyz  = (const float*)d_in[5];
    const float* sa2_xyz  = (const float*)d_in[6];
    const float* w1       = (const float*)d_in[7];
    const float* b1       = (const float*)d_in[8];
    const float* bn1      = (const float*)d_in[9];
    const float* w2       = (const float*)d_in[10];
    const float* b2       = (const float*)d_in[11];
    const float* bn2      = (const float*)d_in[12];
    const float* a1_w     = (const float*)d_in[13];
    const float* a1_b     = (const float*)d_in[14];
    const float* a2_w     = (const float*)d_in[15];
    const float* a2_b     = (const float*)d_in[16];
    const float* fp1_w1   = (const float*)d_in[17];
    const float* fp1_b1   = (const float*)d_in[18];
    const float* fp1_bn1  = (const float*)d_in[19];
    const float* fp1_w2   = (const float*)d_in[20];
    const float* fp1_b2   = (const float*)d_in[21];
    const float* fp1_bn2  = (const float*)d_in[22];
    const float* fp2_w1   = (const float*)d_in[23];
    const float* fp2_b1   = (const float*)d_in[24];
    const float* fp2_bn1  = (const float*)d_in[25];
    const float* fp2_w2   = (const float*)d_in[26];
    const float* fp2_b2   = (const float*)d_in[27];
    const float* fp2_bn2  = (const float*)d_in[28];
    const float* out_w    = (const float*)d_in[29];
    const float* out_b    = (const float*)d_in[30];
    float* out = (float*)d_out;

    float *W1f, *b1f, *W2f, *b2f, *fW1f, *fb1f, *fW2f, *fb2f, *gW1f, *gb1f, *gW2f, *gb2f;
    float *W2t, *fW1At, *fW2t, *gW1At;
    float *C1, *d1, *C0, *d0;
    float *Tx, *h1, *T2t, *s1, *h3, *T4t;
    int *idx1, *idx2;
    float *wt1, *wt2;
    cudaGetSymbolAddress((void**)&W1f, g_W1f);   cudaGetSymbolAddress((void**)&b1f, g_b1f);
    cudaGetSymbolAddress((void**)&W2f, g_W2f);   cudaGetSymbolAddress((void**)&b2f, g_b2f);
    cudaGetSymbolAddress((void**)&fW1f, g_fW1f); cudaGetSymbolAddress((void**)&fb1f, g_fb1f);
    cudaGetSymbolAddress((void**)&fW2f, g_fW2f); cudaGetSymbolAddress((void**)&fb2f, g_fb2f);
    cudaGetSymbolAddress((void**)&gW1f, g_gW1f); cudaGetSymbolAddress((void**)&gb1f, g_gb1f);
    cudaGetSymbolAddress((void**)&gW2f, g_gW2f); cudaGetSymbolAddress((void**)&gb2f, g_gb2f);
    cudaGetSymbolAddress((void**)&W2t, g_W2t);   cudaGetSymbolAddress((void**)&fW1At, g_fW1At);
    cudaGetSymbolAddress((void**)&fW2t, g_fW2t); cudaGetSymbolAddress((void**)&gW1At, g_gW1At);
    cudaGetSymbolAddress((void**)&C1, g_C1);     cudaGetSymbolAddress((void**)&d1, g_d1);
    cudaGetSymbolAddress((void**)&C0, g_C0);     cudaGetSymbolAddress((void**)&d0, g_d0);
    cudaGetSymbolAddress((void**)&Tx, g_Tx);
    cudaGetSymbolAddress((void**)&h1, g_h1);
    cudaGetSymbolAddress((void**)&T2t, g_T2t);
    cudaGetSymbolAddress((void**)&s1, g_s1);
    cudaGetSymbolAddress((void**)&h3, g_h3);
    cudaGetSymbolAddress((void**)&T4t, g_T4t);
    cudaGetSymbolAddress((void**)&idx1, g_idx1); cudaGetSymbolAddress((void**)&wt1, g_wt1);
    cudaGetSymbolAddress((void**)&idx2, g_idx2); cudaGetSymbolAddress((void**)&wt2, g_wt2);

    // 1) fold BN
    {
        dim3 grid(cdiv(DIM_ * DIM_, 256), 6);
        fold_all_kernel<<<grid, 256>>>(w1, b1, bn1, w2, b2, bn2,
                                       fp1_w1, fp1_b1, fp1_bn1, fp1_w2, fp1_b2, fp1_bn2,
                                       fp2_w1, fp2_b1, fp2_bn1, fp2_w2, fp2_b2, fp2_bn2,
                                       W1f, b1f, W2f, b2f, fW1f, fb1f, fW2f, fb2f,
                                       gW1f, gb1f, gW2f, gb2f);
    }
    // 2) transpose to k-major
    {
        dim3 grid(cdiv(DIM_ * I1_, 256), 4);
        transpose_kernel<<<grid, 256>>>(W2f, fW1f, fW2f, gW1f, W2t, fW1At, fW2t, gW1At);
    }
    // 3) combine adapters into skip weights
    combine_kernel<<<cdiv(I1_ * 128 + I2_ * 4, 256), 256>>>(
        fW1f, a2_w, a2_b, gW1f, a1_w, a1_b, C1, d1, C0, d0);

    // 4) three_nn (chunk-parallel)
    {
        dim3 grid(N1_ / 64, B_);
        three_nn2_kernel<N2_><<<grid, 256>>>(sa1_xyz, sa2_xyz, N1_, idx1, wt1);
    }
    {
        dim3 grid(N0_ / 64, B_);
        three_nn2_kernel<N1_><<<grid, 256>>>(sa0_xyz, sa1_xyz, N0_, idx2, wt2);
    }

    // 5) Tx = W1x * x (per batch)
    {
        dim3 grid(cdiv(N2_, 128), cdiv(DIM_, 64), B_);
        gemm_k<64, 128, 16, 16, 16, 4, 8><<<grid, 256>>>(
            W1f, DIM_, nullptr, x, Tx, DIM_, N2_, CTX_, 0);
    }
    // 6) h1 = ReLU(Tx + W1m*mask + b1)
    h1_fuse_kernel<<<BQ_, 256>>>(Tx, mask, W1f, b1f, h1);

    // 7) fusedA: T2t = fW1A * ReLU(W2*h1 + b2)
    {
        dim3 grid(N2_ / 64, BQ_);
        fusedA_kernel<<<grid, 256>>>(W2t, b2f, fW1At, h1, T2t);
    }
    // 8) s1 = C1 * sa1_feat (per batch)
    {
        dim3 grid(cdiv(N1_, 128), cdiv(I1_, 48), B_);
        gemm_k<48, 128, 16, 16, 16, 3, 8><<<grid, 256>>>(
            C1, 128, nullptr, sa1_feat, s1, I1_, N1_, 128, 0);
    }
    // 9) h3 = ReLU(interp(T2t) + s1 + bias)
    {
        dim3 grid(N1_ / 256, BQ_);
        interp_fuse1_kernel<<<grid, 256>>>(T2t, idx1, wt1, s1, fb1f, d1, h3);
    }
    // 10) fusedB: T4t = gW1A * ReLU(fW2*h3 + fb2)
    {
        dim3 grid(N1_ / 128, BQ_);
        fusedB_kernel<<<grid, 256>>>(fW2t, fb2f, gW1At, h3, T4t);
    }
    // 11) fused final: interp + skip + L1-relu + L2 + projection
    {
        dim3 grid(N0_ / 256, BQ_);
        final_fuse_kernel<<<grid, 256>>>(T4t, idx2, wt2, sa0_feat, C0, d0, gb1f,
                                         gW2f, gb2f, out_w, out_b, out);
    }
}

// round 5
// speedup vs baseline: 3.7676x; 1.1595x over previous
#include <cuda_runtime.h>
#include <cuda_bf16.h>
#include <math.h>

// ---------------------------------------------------------------------------
// Problem constants
// ---------------------------------------------------------------------------
#define B_    2
#define Q_    16
#define BQ_   32
#define N0_   4096
#define N1_   1024
#define N2_   256
#define DIM_  296
#define CTX_  288
#define HEADS_ 8
#define I1_   144
#define I2_   72
#define I3_   36
#define EPS_  1e-5f

// ---------------------------------------------------------------------------
// Scratch (device globals)
// ---------------------------------------------------------------------------
__device__ float g_W1f[DIM_ * DIM_], g_b1f[DIM_];
__device__ float g_b2f[I1_], g_fb1f[I1_], g_fb2f[I2_], g_gb1f[I2_], g_gb2f[I3_];
__device__ float g_gW2f[I3_ * I2_];

// chunked k-major weights: [kc][m][k8]
__device__ float g_W2c[37 * I1_ * 8];     // W2 folded, K=296
__device__ float g_fW1Ac[18 * I1_ * 8];   // fW1 A-part, K=144
__device__ float g_fW2c[18 * I2_ * 8];    // fW2, K=144
__device__ float g_gW1Ac[9 * I2_ * 8];    // gW1 A-part, K=72

__device__ float g_C1[I1_ * 128], g_d1[I1_];
__device__ float g_C0[I2_ * 3],   g_d0[I2_];

__device__ float g_Tx[B_ * DIM_ * N2_];    // W1x * x per batch      (2,296,256)
__device__ float g_T2t[BQ_ * N2_ * I1_];   // fW1A*h2, n-major       (32,256,144)
__device__ float g_s1[B_ * I1_ * N1_];     // skip term FP1          (2,144,1024)
__device__ float g_h3[BQ_ * I1_ * N1_];    // fp1 l1 out             (32,144,1024)
__device__ float g_T4t[BQ_ * N1_ * I2_];   // gW1A*h4, n-major       (32,1024,72)

__device__ int   g_idx1[B_ * N1_ * 3];
__device__ float g_wt1 [B_ * N1_ * 3];
__device__ int   g_idx2[B_ * N0_ * 3];
__device__ float g_wt2 [B_ * N0_ * 3];

// ---------------------------------------------------------------------------
// Single prep kernel: BN fold + chunked layouts + adapter combines.
// All cases read RAW inputs -> fully independent, one launch.
// ---------------------------------------------------------------------------
__global__ void prep_kernel(
    const float* __restrict__ w1, const float* __restrict__ b1, const float* __restrict__ bn1,
    const float* __restrict__ w2, const float* __restrict__ b2, const float* __restrict__ bn2,
    const float* __restrict__ fw1, const float* __restrict__ fb1, const float* __restrict__ fbn1,
    const float* __restrict__ fw2, const float* __restrict__ fb2, const float* __restrict__ fbn2,
    const float* __restrict__ gw1, const float* __restrict__ gb1, const float* __restrict__ gbn1,
    const float* __restrict__ gw2, const float* __restrict__ gb2, const float* __restrict__ gbn2,
    const float* __restrict__ a1_w, const float* __restrict__ a1_b,
    const float* __restrict__ a2_w, const float* __restrict__ a2_b,
    float* __restrict__ W1f, float* __restrict__ b1f,
    float* __restrict__ W2c, float* __restrict__ b2f,
    float* __restrict__ fW1Ac, float* __restrict__ fb1f,
    float* __restrict__ fW2c, float* __restrict__ fb2f,
    float* __restrict__ gW1Ac, float* __restrict__ gb1f,
    float* __restrict__ gW2f, float* __restrict__ gb2f,
    float* __restrict__ C1, float* __restrict__ d1,
    float* __restrict__ C0, float* __restrict__ d0)
{
    int t = blockIdx.x * 256 + threadIdx.x;
    switch (blockIdx.y) {
    case 0: {
        if (t < DIM_ * DIM_) {
            int m = t / DIM_;
            float s = bn1[m] * rsqrtf(bn1[3 * DIM_ + m] + EPS_);
            W1f[t] = w1[t] * s;
        }
        if (t < DIM_) {
            float s = bn1[t] * rsqrtf(bn1[3 * DIM_ + t] + EPS_);
            b1f[t] = s * (b1[t] - bn1[2 * DIM_ + t]) + bn1[DIM_ + t];
        }
    } break;
    case 1: {
        if (t < 37 * I1_ * 8) {
            int kc = t / (I1_ * 8), r = t % (I1_ * 8), m = r / 8, k = r % 8;
            int gk = kc * 8 + k;
            float s = bn2[m] * rsqrtf(bn2[3 * I1_ + m] + EPS_);
            W2c[t] = w2[m * DIM_ + gk] * s;
        }
        if (t < I1_) {
            float s = bn2[t] * rsqrtf(bn2[3 * I1_ + t] + EPS_);
            b2f[t] = s * (b2[t] - bn2[2 * I1_ + t]) + bn2[I1_ + t];
        }
    } break;
    case 2: {
        if (t < 18 * I1_ * 8) {
            int kc = t / (I1_ * 8), r = t % (I1_ * 8), m = r / 8, k = r % 8;
            int gk = kc * 8 + k;
            float s = fbn1[m] * rsqrtf(fbn1[3 * I1_ + m] + EPS_);
            fW1Ac[t] = fw1[m * (2 * I1_) + gk] * s;
        }
        if (t < I1_) {
            float s = fbn1[t] * rsqrtf(fbn1[3 * I1_ + t] + EPS_);
            fb1f[t] = s * (fb1[t] - fbn1[2 * I1_ + t]) + fbn1[I1_ + t];
        }
    } break;
    case 3: {
        if (t < 18 * I2_ * 8) {
            int kc = t / (I2_ * 8), r = t % (I2_ * 8), m = r / 8, k = r % 8;
            int gk = kc * 8 + k;
            float s = fbn2[m] * rsqrtf(fbn2[3 * I2_ + m] + EPS_);
            fW2c[t] = fw2[m * I1_ + gk] * s;
        }
        if (t < I2_) {
            float s = fbn2[t] * rsqrtf(fbn2[3 * I2_ + t] + EPS_);
            fb2f[t] = s * (fb2[t] - fbn2[2 * I2_ + t]) + fbn2[I2_ + t];
        }
    } break;
    case 4: {
        if (t < 9 * I2_ * 8) {
            int kc = t / (I2_ * 8), r = t % (I2_ * 8), m = r / 8, k = r % 8;
            int gk = kc * 8 + k;
            float s = gbn1[m] * rsqrtf(gbn1[3 * I2_ + m] + EPS_);
            gW1Ac[t] = gw1[m * (2 * I2_) + gk] * s;
        }
        if (t < I2_) {
            float s = gbn1[t] * rsqrtf(gbn1[3 * I2_ + t] + EPS_);
            gb1f[t] = s * (gb1[t] - gbn1[2 * I2_ + t]) + gbn1[I2_ + t];
        }
    } break;
    case 5: {
        if (t < I3_ * I2_) {
            int m = t / I2_;
            float s = gbn2[m] * rsqrtf(gbn2[3 * I3_ + m] + EPS_);
            gW2f[t] = gw2[t] * s;
        }
        if (t < I3_) {
            float s = gbn2[t] * rsqrtf(gbn2[3 * I3_ + t] + EPS_);
            gb2f[t] = s * (gb2[t] - gbn2[2 * I3_ + t]) + gbn2[I3_ + t];
        }
    } break;
    case 6: {
        if (t < I1_ * 128) {
            int o = t / 128, k = t % 128;
            float s = fbn1[o] * rsqrtf(fbn1[3 * I1_ + o] + EPS_);
            float acc = 0.f;
            for (int c = 0; c < I1_; c++)
                acc += fw1[o * (2 * I1_) + I1_ + c] * a2_w[c * 128 + k];
            C1[t] = acc * s;
        }
        if (t < I1_) {
            float s = fbn1[t] * rsqrtf(fbn1[3 * I1_ + t] + EPS_);
            float acc = 0.f;
            for (int c = 0; c < I1_; c++)
                acc += fw1[t * (2 * I1_) + I1_ + c] * a2_b[c];
            d1[t] = acc * s;
        }
    } break;
    case 7: {
        if (t < I2_ * 3) {
            int o = t / 3, k = t % 3;
            float s = gbn1[o] * rsqrtf(gbn1[3 * I2_ + o] + EPS_);
            float acc = 0.f;
            for (int c = 0; c < I2_; c++)
                acc += gw1[o * (2 * I2_) + I2_ + c] * a1_w[c * 3 + k];
            C0[t] = acc * s;
        }
        if (t >= I2_ * 3 && t < I2_ * 4) {
            int o = t - I2_ * 3;
            float s = gbn1[o] * rsqrtf(gbn1[3 * I2_ + o] + EPS_);
            float acc = 0.f;
            for (int c = 0; c < I2_; c++)
                acc += gw1[o * (2 * I2_) + I2_ + c] * a1_b[c];
            d0[o] = acc * s;
        }
    } break;
    }
}

// ---------------------------------------------------------------------------
// Both three_nn levels in ONE launch. z=0: sa1<-sa2 (Nu=1024, NK=256)
//                                     z=1: sa0<-sa1 (Nu=4096, NK=1024)
// ---------------------------------------------------------------------------
__global__ __launch_bounds__(256)
void three_nn_all_kernel(const float* __restrict__ sa0_xyz,
                         const float* __restrict__ sa1_xyz,
                         const float* __restrict__ sa2_xyz,
                         int* __restrict__ idx1, float* __restrict__ wt1,
                         int* __restrict__ idx2, float* __restrict__ wt2) {
    __shared__ float kx[1024], ky[1024], kz[1024];
    __shared__ float cd[64][4][3];
    __shared__ int   ci[64][4][3];

    const int lvl = blockIdx.z;
    if (!lvl && blockIdx.x >= 16) return;
    const int NK = lvl ? 1024 : 256;
    const int Nu = lvl ? N0_ : N1_;
    const int CS = NK / 4;
    const float* unknown = lvl ? sa0_xyz : sa1_xyz;
    const float* known   = lvl ? sa1_xyz : sa2_xyz;
    int*   idx = lvl ? idx2 : idx1;
    float* w   = lvl ? wt2  : wt1;
    const int b = blockIdx.y;

    const float* kb = known + (size_t)b * NK * 3;
    for (int i = threadIdx.x; i < NK; i += 256) {
        kx[i] = kb[i * 3 + 0];
        ky[i] = kb[i * 3 + 1];
        kz[i] = kb[i * 3 + 2];
    }
    __syncthreads();

    int ul = threadIdx.x & 63;
    int ch = threadIdx.x >> 6;
    int u = blockIdx.x * 64 + ul;
    const float* up = unknown + ((size_t)b * Nu + u) * 3;
    float ux = up[0], uy = up[1], uz = up[2];

    float d0 = 3.4e38f, d1 = 3.4e38f, d2 = 3.4e38f;
    int i0 = 0, i1 = 0, i2 = 0;
    int base = ch * CS;
#pragma unroll 4
    for (int t = 0; t < CS; t++) {
        int i = base + t;
        float dx = ux - kx[i], dy = uy - ky[i], dz = uz - kz[i];
        float d = fmaf(dx, dx, fmaf(dy, dy, dz * dz));
        if (d < d2) {
            if (d < d0)      { d2 = d1; i2 = i1; d1 = d0; i1 = i0; d0 = d; i0 = i; }
            else if (d < d1) { d2 = d1; i2 = i1; d1 = d;  i1 = i; }
            else             { d2 = d;  i2 = i; }
        }
    }
    cd[ul][ch][0] = d0; cd[ul][ch][1] = d1; cd[ul][ch][2] = d2;
    ci[ul][ch][0] = i0; ci[ul][ch][1] = i1; ci[ul][ch][2] = i2;
    __syncthreads();

    if (threadIdx.x < 64) {
        int uu = blockIdx.x * 64 + threadIdx.x;
        float m0 = 3.4e38f, m1 = 3.4e38f, m2 = 3.4e38f;
        int j0 = 0, j1 = 0, j2 = 0;
#pragma unroll
        for (int c = 0; c < 4; c++) {
#pragma unroll
            for (int t = 0; t < 3; t++) {
                float d = cd[threadIdx.x][c][t];
                int i = ci[threadIdx.x][c][t];
                if (d < m2) {
                    if (d < m0)      { m2 = m1; j2 = j1; m1 = m0; j1 = j0; m0 = d; j0 = i; }
                    else if (d < m1) { m2 = m1; j2 = j1; m1 = d;  j1 = i; }
                    else             { m2 = d;  j2 = i; }
                }
            }
        }
        float w0 = 1.f / (m0 + 1e-8f);
        float w1 = 1.f / (m1 + 1e-8f);
        float w2 = 1.f / (m2 + 1e-8f);
        float ws = w0 + w1 + w2;
        size_t o = ((size_t)b * Nu + uu) * 3;
        idx[o] = j0; idx[o + 1] = j1; idx[o + 2] = j2;
        w[o] = w0 / ws; w[o + 1] = w1 / ws; w[o + 2] = w2 / ws;
    }
}

// ---------------------------------------------------------------------------
// Generic tiled SGEMM (Tx and s1)
// ---------------------------------------------------------------------------
template <int BM, int BN, int BK, int TX, int TY, int TM, int TN>
__global__ __launch_bounds__(TX * TY)
void gemm_k(const float* __restrict__ W, int ldw,
            const float* __restrict__ bias,
            const float* __restrict__ X,
            float* __restrict__ Y,
            int M, int N, int K, int relu) {
    const int b  = blockIdx.z;
    const int m0 = blockIdx.y * BM;
    const int n0 = blockIdx.x * BN;
    const float* Xb = X + (size_t)b * K * N;
    float* Yb = Y + (size_t)b * M * N;

    __shared__ float Ws[BK][BM];
    __shared__ float Xs[BK][BN];

    const int tid = threadIdx.x;
    const int tx = tid % TX, ty = tid / TX;
    const int tm = ty * TM, tn = tx * TN;
    const int NT = TX * TY;

    float acc[TM][TN];
#pragma unroll
    for (int i = 0; i < TM; i++)
#pragma unroll
        for (int j = 0; j < TN; j++) acc[i][j] = 0.f;

    for (int k0 = 0; k0 < K; k0 += BK) {
#pragma unroll
        for (int i = tid; i < BM * BK; i += NT) {
            int m = i / BK, k = i % BK;
            int gm = m0 + m, gk = k0 + k;
            Ws[k][m] = (gm < M && gk < K) ? W[(size_t)gm * ldw + gk] : 0.f;
        }
#pragma unroll
        for (int i = tid; i < BK * BN; i += NT) {
            int k = i / BN, n = i % BN;
            int gk = k0 + k, gn = n0 + n;
            Xs[k][n] = (gk < K && gn < N) ? Xb[(size_t)gk * N + gn] : 0.f;
        }
        __syncthreads();
#pragma unroll
        for (int kk = 0; kk < BK; kk++) {
            float a[TM], xv[TN];
#pragma unroll
            for (int i = 0; i < TM; i++) a[i] = Ws[kk][tm + i];
#pragma unroll
            for (int j = 0; j < TN; j++) xv[j] = Xs[kk][tn + j];
#pragma unroll
            for (int i = 0; i < TM; i++)
#pragma unroll
                for (int j = 0; j < TN; j++) acc[i][j] = fmaf(a[i], xv[j], acc[i][j]);
        }
        __syncthreads();
    }

#pragma unroll
    for (int i = 0; i < TM; i++) {
        int m = m0 + tm + i;
        if (m >= M) break;
        float bv = bias ? bias[m] : 0.f;
#pragma unroll
        for (int j = 0; j < TN; j++) {
            int n = n0 + tn + j;
            if (n < N) {
                float v = acc[i][j] + bv;
                if (relu) v = fmaxf(v, 0.f);
                Yb[(size_t)m * N + n] = v;
            }
        }
    }
}

// ---------------------------------------------------------------------------
// fusedA: T2t = fW1A * ReLU(W2 * h1 + b2),  h1 computed on the fly:
//   h1[k][n] = ReLU(Tx[b][k][n] + W1f[k][288:296]·mask[bq][:][n] + b1[k])
// grid (N2/64, BQ), 256 threads, micro-tile 9x4, 4-k-step vectorized inner.
// ---------------------------------------------------------------------------
__global__ __launch_bounds__(256)
void fusedA_kernel(const float* __restrict__ W2c,    // (37,144,8)
                   const float* __restrict__ b2f,
                   const float* __restrict__ fW1Ac,  // (18,144,8)
                   const float* __restrict__ Tx,     // (2,296,256)
                   const float* __restrict__ maskg,  // (32,8,256)
                   const float* __restrict__ W1f,    // (296,296)
                   const float* __restrict__ b1f,
                   float* __restrict__ T2t) {        // (32,256,144)
    __shared__ float Ws[1152];        // [m][k8]
    __shared__ float Xs[512];         // [k][n]
    __shared__ float Hs[144 * 68];    // [c][n] padded

    const int bq = blockIdx.y, b = bq >> 4;
    const int n0 = blockIdx.x * 64;
    const int tid = threadIdx.x;
    const int tx = tid & 15, ty = tid >> 4;
    const int tm = ty * 9, tn = tx * 4;

    // per-thread constants: each Xs slot has fixed (k_local, n)
    int nl0 = tid & 63, nl1 = (tid + 256) & 63;
    int kl0 = tid >> 6, kl1 = (tid + 256) >> 6;
    float mv0[8], mv1[8];
#pragma unroll
    for (int j = 0; j < 8; j++) {
        mv0[j] = __ldg(maskg + ((size_t)bq * 8 + j) * N2_ + n0 + nl0);
        mv1[j] = __ldg(maskg + ((size_t)bq * 8 + j) * N2_ + n0 + nl1);
    }
    const float* Txb = Tx + (size_t)b * DIM_ * N2_ + n0;

    // ---- phase 1: H = ReLU(W2*h1 + b2), 37 chunks of 8 k
    float acc[9][4];
#pragma unroll
    for (int i = 0; i < 9; i++)
#pragma unroll
        for (int j = 0; j < 4; j++) acc[i][j] = 0.f;

    float4 w4[2];
    float xv0, xv1;
    {   // prefetch chunk 0
        int e4a = tid, e4b = tid + 256;
        w4[0] = ((const float4*)W2c)[e4a];
        if (e4b < 288) w4[1] = ((const float4*)W2c)[e4b];
        int gk0 = kl0, gk1 = kl1;
        const float4* wp0 = (const float4*)(W1f + (size_t)gk0 * DIM_ + CTX_);
        const float4* wp1 = (const float4*)(W1f + (size_t)gk1 * DIM_ + CTX_);
        float4 wa = __ldg(wp0), wb = __ldg(wp0 + 1);
        float v = __ldg(Txb + (size_t)gk0 * N2_ + nl0) + __ldg(b1f + gk0);
        v += wa.x * mv0[0] + wa.y * mv0[1] + wa.z * mv0[2] + wa.w * mv0[3]
           + wb.x * mv0[4] + wb.y * mv0[5] + wb.z * mv0[6] + wb.w * mv0[7];
        xv0 = fmaxf(v, 0.f);
        wa = __ldg(wp1); wb = __ldg(wp1 + 1);
        v = __ldg(Txb + (size_t)gk1 * N2_ + nl1) + __ldg(b1f + gk1);
        v += wa.x * mv1[0] + wa.y * mv1[1] + wa.z * mv1[2] + wa.w * mv1[3]
           + wb.x * mv1[4] + wb.y * mv1[5] + wb.z * mv1[6] + wb.w * mv1[7];
        xv1 = fmaxf(v, 0.f);
    }

    for (int kc = 0; kc < 37; kc++) {
        __syncthreads();
        {
            int e4b = tid + 256;
            ((float4*)Ws)[tid] = w4[0];
            if (e4b < 288) ((float4*)Ws)[e4b] = w4[1];
            Xs[tid] = xv0;
            Xs[tid + 256] = xv1;
        }
        __syncthreads();
        if (kc + 1 < 37) {
            const float4* wc = (const float4*)(W2c + (size_t)(kc + 1) * 1152);
            int e4b = tid + 256;
            w4[0] = wc[tid];
            if (e4b < 288) w4[1] = wc[e4b];
            int gk0 = (kc + 1) * 8 + kl0, gk1 = (kc + 1) * 8 + kl1;
            const float4* wp0 = (const float4*)(W1f + (size_t)gk0 * DIM_ + CTX_);
            const float4* wp1 = (const float4*)(W1f + (size_t)gk1 * DIM_ + CTX_);
            float4 wa = __ldg(wp0), wb = __ldg(wp0 + 1);
            float v = __ldg(Txb + (size_t)gk0 * N2_ + nl0) + __ldg(b1f + gk0);
            v += wa.x * mv0[0] + wa.y * mv0[1] + wa.z * mv0[2] + wa.w * mv0[3]
               + wb.x * mv0[4] + wb.y * mv0[5] + wb.z * mv0[6] + wb.w * mv0[7];
            xv0 = fmaxf(v, 0.f);
            wa = __ldg(wp1); wb = __ldg(wp1 + 1);
            v = __ldg(Txb + (size_t)gk1 * N2_ + nl1) + __ldg(b1f + gk1);
            v += wa.x * mv1[0] + wa.y * mv1[1] + wa.z * mv1[2] + wa.w * mv1[3]
               + wb.x * mv1[4] + wb.y * mv1[5] + wb.z * mv1[6] + wb.w * mv1[7];
            xv1 = fmaxf(v, 0.f);
        }
#pragma unroll
        for (int g = 0; g < 2; g++) {
            float4 a4[9];
#pragma unroll
            for (int i = 0; i < 9; i++)
                a4[i] = *(const float4*)&Ws[(tm + i) * 8 + g * 4];
            float4 x0 = *(const float4*)&Xs[(g * 4 + 0) * 64 + tn];
            float4 x1 = *(const float4*)&Xs[(g * 4 + 1) * 64 + tn];
            float4 x2 = *(const float4*)&Xs[(g * 4 + 2) * 64 + tn];
            float4 x3 = *(const float4*)&Xs[(g * 4 + 3) * 64 + tn];
#pragma unroll
            for (int i = 0; i < 9; i++) {
                acc[i][0] = fmaf(a4[i].x, x0.x, acc[i][0]);
                acc[i][1] = fmaf(a4[i].x, x0.y, acc[i][1]);
                acc[i][2] = fmaf(a4[i].x, x0.z, acc[i][2]);
                acc[i][3] = fmaf(a4[i].x, x0.w, acc[i][3]);
                acc[i][0] = fmaf(a4[i].y, x1.x, acc[i][0]);
                acc[i][1] = fmaf(a4[i].y, x1.y, acc[i][1]);
                acc[i][2] = fmaf(a4[i].y, x1.z, acc[i][2]);
                acc[i][3] = fmaf(a4[i].y, x1.w, acc[i][3]);
                acc[i][0] = fmaf(a4[i].z, x2.x, acc[i][0]);
                acc[i][1] = fmaf(a4[i].z, x2.y, acc[i][1]);
                acc[i][2] = fmaf(a4[i].z, x2.z, acc[i][2]);
                acc[i][3] = fmaf(a4[i].z, x2.w, acc[i][3]);
                acc[i][0] = fmaf(a4[i].w, x3.x, acc[i][0]);
                acc[i][1] = fmaf(a4[i].w, x3.y, acc[i][1]);
                acc[i][2] = fmaf(a4[i].w, x3.z, acc[i][2]);
                acc[i][3] = fmaf(a4[i].w, x3.w, acc[i][3]);
            }
        }
    }
    // bias + relu -> Hs
#pragma unroll
    for (int i = 0; i < 9; i++) {
        float bv = __ldg(b2f + tm + i);
        float4 hv;
        hv.x = fmaxf(acc[i][0] + bv, 0.f);
        hv.y = fmaxf(acc[i][1] + bv, 0.f);
        hv.z = fmaxf(acc[i][2] + bv, 0.f);
        hv.w = fmaxf(acc[i][3] + bv, 0.f);
        *(float4*)&Hs[(tm + i) * 68 + tn] = hv;
    }

    // ---- phase 2: T2 = fW1A * H, 18 chunks of 8
    float acc2[9][4];
#pragma unroll
    for (int i = 0; i < 9; i++)
#pragma unroll
        for (int j = 0; j < 4; j++) acc2[i][j] = 0.f;

    {
        int e4b = tid + 256;
        w4[0] = ((const float4*)fW1Ac)[tid];
        if (e4b < 288) w4[1] = ((const float4*)fW1Ac)[e4b];
    }
    for (int kc = 0; kc < 18; kc++) {
        __syncthreads();
        {
            int e4b = tid + 256;
            ((float4*)Ws)[tid] = w4[0];
            if (e4b < 288) ((float4*)Ws)[e4b] = w4[1];
        }
        __syncthreads();
        if (kc + 1 < 18) {
            const float4* wc = (const float4*)(fW1Ac + (size_t)(kc + 1) * 1152);
            int e4b = tid + 256;
            w4[0] = wc[tid];
            if (e4b < 288) w4[1] = wc[e4b];
        }
        int kb = kc * 8;
#pragma unroll
        for (int g = 0; g < 2; g++) {
            float4 a4[9];
#pragma unroll
            for (int i = 0; i < 9; i++)
                a4[i] = *(const float4*)&Ws[(tm + i) * 8 + g * 4];
            float4 x0 = *(const float4*)&Hs[(kb + g * 4 + 0) * 68 + tn];
            float4 x1 = *(const float4*)&Hs[(kb + g * 4 + 1) * 68 + tn];
            float4 x2 = *(const float4*)&Hs[(kb + g * 4 + 2) * 68 + tn];
            float4 x3 = *(const float4*)&Hs[(kb + g * 4 + 3) * 68 + tn];
#pragma unroll
            for (int i = 0; i < 9; i++) {
                acc2[i][0] = fmaf(a4[i].x, x0.x, acc2[i][0]);
                acc2[i][1] = fmaf(a4[i].x, x0.y, acc2[i][1]);
                acc2[i][2] = fmaf(a4[i].x, x0.z, acc2[i][2]);
                acc2[i][3] = fmaf(a4[i].x, x0.w, acc2[i][3]);
                acc2[i][0] = fmaf(a4[i].y, x1.x, acc2[i][0]);
                acc2[i][1] = fmaf(a4[i].y, x1.y, acc2[i][1]);
                acc2[i][2] = fmaf(a4[i].y, x1.z, acc2[i][2]);
                acc2[i][3] = fmaf(a4[i].y, x1.w, acc2[i][3]);
                acc2[i][0] = fmaf(a4[i].z, x2.x, acc2[i][0]);
                acc2[i][1] = fmaf(a4[i].z, x2.y, acc2[i][1]);
                acc2[i][2] = fmaf(a4[i].z, x2.z, acc2[i][2]);
                acc2[i][3] = fmaf(a4[i].z, x2.w, acc2[i][3]);
                acc2[i][0] = fmaf(a4[i].w, x3.x, acc2[i][0]);
                acc2[i][1] = fmaf(a4[i].w, x3.y, acc2[i][1]);
                acc2[i][2] = fmaf(a4[i].w, x3.z, acc2[i][2]);
                acc2[i][3] = fmaf(a4[i].w, x3.w, acc2[i][3]);
            }
        }
    }
    // store n-major
#pragma unroll
    for (int j = 0; j < 4; j++) {
        size_t base = ((size_t)bq * N2_ + n0 + tn + j) * I1_ + tm;
#pragma unroll
        for (int i = 0; i < 9; i++) T2t[base + i] = acc2[i][j];
    }
}

// ---------------------------------------------------------------------------
// fusedB: T4t = gW1A * ReLU(fW2 * h3 + fb2), n-major out (32,1024,72)
// grid (N1/128, BQ), 256 threads, micro-tile 9x4
// ---------------------------------------------------------------------------
__global__ __launch_bounds__(256)
void fusedB_kernel(const float* __restrict__ fW2c,   // (18,72,8)
                   const float* __restrict__ fb2f,
                   const float* __restrict__ gW1Ac,  // (9,72,8)
                   const float* __restrict__ h3,     // (32,144,1024)
                   float* __restrict__ T4t) {        // (32,1024,72)
    __shared__ float Ws[576];
    __shared__ float Xs[1024];
    __shared__ float Hs[72 * 132];

    const int bq = blockIdx.y;
    const int n0 = blockIdx.x * 128;
    const int tid = threadIdx.x;
    const int tx = tid & 31, ty = tid >> 5;
    const int tm = ty * 9, tn = tx * 4;

    const float* h3b = h3 + (size_t)bq * I1_ * N1_ + n0;

    float acc[9][4];
#pragma unroll
    for (int i = 0; i < 9; i++)
#pragma unroll
        for (int j = 0; j < 4; j++) acc[i][j] = 0.f;

    float4 w4;
    float xr[4];
    if (tid < 144) w4 = ((const float4*)fW2c)[tid];
#pragma unroll
    for (int r = 0; r < 4; r++) {
        int e = tid + r * 256;
        xr[r] = __ldg(h3b + (size_t)(e >> 7) * N1_ + (e & 127));
    }

    for (int kc = 0; kc < 18; kc++) {
        __syncthreads();
        if (tid < 144) ((float4*)Ws)[tid] = w4;
#pragma unroll
        for (int r = 0; r < 4; r++) Xs[tid + r * 256] = xr[r];
        __syncthreads();
        if (kc + 1 < 18) {
            if (tid < 144) w4 = ((const float4*)(fW2c + (size_t)(kc + 1) * 576))[tid];
            int k0n = (kc + 1) * 8;
#pragma unroll
            for (int r = 0; r < 4; r++) {
                int e = tid + r * 256;
                xr[r] = __ldg(h3b + (size_t)(k0n + (e >> 7)) * N1_ + (e & 127));
            }
        }
#pragma unroll
        for (int g = 0; g < 2; g++) {
            float4 a4[9];
#pragma unroll
            for (int i = 0; i < 9; i++)
                a4[i] = *(const float4*)&Ws[(tm + i) * 8 + g * 4];
            float4 x0 = *(const float4*)&Xs[(g * 4 + 0) * 128 + tn];
            float4 x1 = *(const float4*)&Xs[(g * 4 + 1) * 128 + tn];
            float4 x2 = *(const float4*)&Xs[(g * 4 + 2) * 128 + tn];
            float4 x3 = *(const float4*)&Xs[(g * 4 + 3) * 128 + tn];
#pragma unroll
            for (int i = 0; i < 9; i++) {
                acc[i][0] = fmaf(a4[i].x, x0.x, acc[i][0]);
                acc[i][1] = fmaf(a4[i].x, x0.y, acc[i][1]);
                acc[i][2] = fmaf(a4[i].x, x0.z, acc[i][2]);
                acc[i][3] = fmaf(a4[i].x, x0.w, acc[i][3]);
                acc[i][0] = fmaf(a4[i].y, x1.x, acc[i][0]);
                acc[i][1] = fmaf(a4[i].y, x1.y, acc[i][1]);
                acc[i][2] = fmaf(a4[i].y, x1.z, acc[i][2]);
                acc[i][3] = fmaf(a4[i].y, x1.w, acc[i][3]);
                acc[i][0] = fmaf(a4[i].z, x2.x, acc[i][0]);
                acc[i][1] = fmaf(a4[i].z, x2.y, acc[i][1]);
                acc[i][2] = fmaf(a4[i].z, x2.z, acc[i][2]);
                acc[i][3] = fmaf(a4[i].z, x2.w, acc[i][3]);
                acc[i][0] = fmaf(a4[i].w, x3.x, acc[i][0]);
                acc[i][1] = fmaf(a4[i].w, x3.y, acc[i][1]);
                acc[i][2] = fmaf(a4[i].w, x3.z, acc[i][2]);
                acc[i][3] = fmaf(a4[i].w, x3.w, acc[i][3]);
            }
        }
    }
#pragma unroll
    for (int i = 0; i < 9; i++) {
        float bv = __ldg(fb2f + tm + i);
        float4 hv;
        hv.x = fmaxf(acc[i][0] + bv, 0.f);
        hv.y = fmaxf(acc[i][1] + bv, 0.f);
        hv.z = fmaxf(acc[i][2] + bv, 0.f);
        hv.w = fmaxf(acc[i][3] + bv, 0.f);
        *(float4*)&Hs[(tm + i) * 132 + tn] = hv;
    }

    float acc2[9][4];
#pragma unroll
    for (int i = 0; i < 9; i++)
#pragma unroll
        for (int j = 0; j < 4; j++) acc2[i][j] = 0.f;

    if (tid < 144) w4 = ((const float4*)gW1Ac)[tid];
    for (int kc = 0; kc < 9; kc++) {
        __syncthreads();
        if (tid < 144) ((float4*)Ws)[tid] = w4;
        __syncthreads();
        if (kc + 1 < 9) {
            if (tid < 144) w4 = ((const float4*)(gW1Ac + (size_t)(kc + 1) * 576))[tid];
        }
        int kb = kc * 8;
#pragma unroll
        for (int g = 0; g < 2; g++) {
            float4 a4[9];
#pragma unroll
            for (int i = 0; i < 9; i++)
                a4[i] = *(const float4*)&Ws[(tm + i) * 8 + g * 4];
            float4 x0 = *(const float4*)&Hs[(kb + g * 4 + 0) * 132 + tn];
            float4 x1 = *(const float4*)&Hs[(kb + g * 4 + 1) * 132 + tn];
            float4 x2 = *(const float4*)&Hs[(kb + g * 4 + 2) * 132 + tn];
            float4 x3 = *(const float4*)&Hs[(kb + g * 4 + 3) * 132 + tn];
#pragma unroll
            for (int i = 0; i < 9; i++) {
                acc2[i][0] = fmaf(a4[i].x, x0.x, acc2[i][0]);
                acc2[i][1] = fmaf(a4[i].x, x0.y, acc2[i][1]);
                acc2[i][2] = fmaf(a4[i].x, x0.z, acc2[i][2]);
                acc2[i][3] = fmaf(a4[i].x, x0.w, acc2[i][3]);
                acc2[i][0] = fmaf(a4[i].y, x1.x, acc2[i][0]);
                acc2[i][1] = fmaf(a4[i].y, x1.y, acc2[i][1]);
                acc2[i][2] = fmaf(a4[i].y, x1.z, acc2[i][2]);
                acc2[i][3] = fmaf(a4[i].y, x1.w, acc2[i][3]);
                acc2[i][0] = fmaf(a4[i].z, x2.x, acc2[i][0]);
                acc2[i][1] = fmaf(a4[i].z, x2.y, acc2[i][1]);
                acc2[i][2] = fmaf(a4[i].z, x2.z, acc2[i][2]);
                acc2[i][3] = fmaf(a4[i].z, x2.w, acc2[i][3]);
                acc2[i][0] = fmaf(a4[i].w, x3.x, acc2[i][0]);
                acc2[i][1] = fmaf(a4[i].w, x3.y, acc2[i][1]);
                acc2[i][2] = fmaf(a4[i].w, x3.z, acc2[i][2]);
                acc2[i][3] = fmaf(a4[i].w, x3.w, acc2[i][3]);
            }
        }
    }
#pragma unroll
    for (int j = 0; j < 4; j++) {
        size_t base = ((size_t)bq * N1_ + n0 + tn + j) * I2_ + tm;
#pragma unroll
        for (int i = 0; i < 9; i++) T4t[base + i] = acc2[i][j];
    }
}

// ---------------------------------------------------------------------------
// FP1 fused: h3 = ReLU(interp(T2t) + s1 + fb1 + d1)
// ---------------------------------------------------------------------------
__global__ __launch_bounds__(256)
void interp_fuse1_kernel(const float* __restrict__ T2t,
                         const int* __restrict__ idx,
                         const float* __restrict__ wt,
                         const float* __restrict__ s1,
                         const float* __restrict__ fb1,
                         const float* __restrict__ d1,
                         float* __restrict__ h3) {
    __shared__ float bs[I1_];
    int tid = threadIdx.x;
    if (tid < I1_) bs[tid] = fb1[tid] + d1[tid];
    __syncthreads();

    int bq = blockIdx.y, b = bq >> 4;
    int nu = blockIdx.x * 256 + tid;
    size_t o = ((size_t)b * N1_ + nu) * 3;
    int j0 = idx[o], j1 = idx[o + 1], j2 = idx[o + 2];
    float w0 = wt[o], w1 = wt[o + 1], w2 = wt[o + 2];
    const float4* p0 = (const float4*)(T2t + ((size_t)bq * N2_ + j0) * I1_);
    const float4* p1 = (const float4*)(T2t + ((size_t)bq * N2_ + j1) * I1_);
    const float4* p2 = (const float4*)(T2t + ((size_t)bq * N2_ + j2) * I1_);
    const float* s1b = s1 + (size_t)b * I1_ * N1_ + nu;
    float* outb = h3 + (size_t)bq * I1_ * N1_ + nu;
#pragma unroll 9
    for (int cc = 0; cc < 36; cc++) {
        float4 a0 = p0[cc], a1 = p1[cc], a2 = p2[cc];
        int c = cc * 4;
        outb[(size_t)(c + 0) * N1_] = fmaxf(w0 * a0.x + w1 * a1.x + w2 * a2.x + s1b[(size_t)(c + 0) * N1_] + bs[c + 0], 0.f);
        outb[(size_t)(c + 1) * N1_] = fmaxf(w0 * a0.y + w1 * a1.y + w2 * a2.y + s1b[(size_t)(c + 1) * N1_] + bs[c + 1], 0.f);
        outb[(size_t)(c + 2) * N1_] = fmaxf(w0 * a0.z + w1 * a1.z + w2 * a2.z + s1b[(size_t)(c + 2) * N1_] + bs[c + 2], 0.f);
        outb[(size_t)(c + 3) * N1_] = fmaxf(w0 * a0.w + w1 * a1.w + w2 * a2.w + s1b[(size_t)(c + 3) * N1_] + bs[c + 3], 0.f);
    }
}

// ---------------------------------------------------------------------------
// Fused final: interp(T4t)+skip+relu (FP2-L1), FP2-L2+relu, out projection
// ---------------------------------------------------------------------------
__global__ __launch_bounds__(256)
void final_fuse_kernel(const float* __restrict__ T4t,
                       const int* __restrict__ idx,
                       const float* __restrict__ wt,
                       const float* __restrict__ sa0f,
                       const float* __restrict__ C0,
                       const float* __restrict__ d0v,
                       const float* __restrict__ gb1,
                       const float* __restrict__ gW2,
                       const float* __restrict__ gb2,
                       const float* __restrict__ ow,
                       const float* __restrict__ ob,
                       float* __restrict__ out) {
    __shared__ float gT[I2_ * I3_];   // gT[c*36+m] = gW2[m][c]
    __shared__ float c0s[I2_ * 3];
    __shared__ float bs[I2_];
    __shared__ float gbs[I3_], ows[I3_];
    int tid = threadIdx.x;
    for (int e = tid; e < I2_ * I3_; e += 256) {
        int c = e / I3_, m = e % I3_;
        gT[e] = gW2[m * I2_ + c];
    }
    if (tid < I2_ * 3) c0s[tid] = C0[tid];
    if (tid < I2_) bs[tid] = d0v[tid] + gb1[tid];
    if (tid < I3_) { gbs[tid] = gb2[tid]; ows[tid] = ow[tid]; }
    __syncthreads();

    int bq = blockIdx.y, b = bq >> 4;
    int nu = blockIdx.x * 256 + tid;
    size_t o = ((size_t)b * N0_ + nu) * 3;
    int j0 = idx[o], j1 = idx[o + 1], j2 = idx[o + 2];
    float w0 = wt[o], w1 = wt[o + 1], w2 = wt[o + 2];
    const float4* p0 = (const float4*)(T4t + ((size_t)bq * N1_ + j0) * I2_);
    const float4* p1 = (const float4*)(T4t + ((size_t)bq * N1_ + j1) * I2_);
    const float4* p2 = (const float4*)(T4t + ((size_t)bq * N1_ + j2) * I2_);
    float f0 = sa0f[((size_t)b * 3 + 0) * N0_ + nu];
    float f1 = sa0f[((size_t)b * 3 + 1) * N0_ + nu];
    float f2 = sa0f[((size_t)b * 3 + 2) * N0_ + nu];

    float acc[I3_];
#pragma unroll
    for (int m = 0; m < I3_; m++) acc[m] = 0.f;

#pragma unroll 3
    for (int cc = 0; cc < 18; cc++) {
        float4 a0 = p0[cc], a1 = p1[cc], a2 = p2[cc];
        int c = cc * 4;
        float hv[4];
        hv[0] = fmaxf(w0 * a0.x + w1 * a1.x + w2 * a2.x + c0s[(c + 0) * 3] * f0 + c0s[(c + 0) * 3 + 1] * f1 + c0s[(c + 0) * 3 + 2] * f2 + bs[c + 0], 0.f);
        hv[1] = fmaxf(w0 * a0.y + w1 * a1.y + w2 * a2.y + c0s[(c + 1) * 3] * f0 + c0s[(c + 1) * 3 + 1] * f1 + c0s[(c + 1) * 3 + 2] * f2 + bs[c + 1], 0.f);
        hv[2] = fmaxf(w0 * a0.z + w1 * a1.z + w2 * a2.z + c0s[(c + 2) * 3] * f0 + c0s[(c + 2) * 3 + 1] * f1 + c0s[(c + 2) * 3 + 2] * f2 + bs[c + 2], 0.f);
        hv[3] = fmaxf(w0 * a0.w + w1 * a1.w + w2 * a2.w + c0s[(c + 3) * 3] * f0 + c0s[(c + 3) * 3 + 1] * f1 + c0s[(c + 3) * 3 + 2] * f2 + bs[c + 3], 0.f);
#pragma unroll
        for (int q = 0; q < 4; q++) {
            const float4* g4 = (const float4*)&gT[(c + q) * I3_];
#pragma unroll
            for (int mm = 0; mm < 9; mm++) {
                float4 g = g4[mm];
                acc[mm * 4 + 0] = fmaf(g.x, hv[q], acc[mm * 4 + 0]);
                acc[mm * 4 + 1] = fmaf(g.y, hv[q], acc[mm * 4 + 1]);
                acc[mm * 4 + 2] = fmaf(g.z, hv[q], acc[mm * 4 + 2]);
                acc[mm * 4 + 3] = fmaf(g.w, hv[q], acc[mm * 4 + 3]);
            }
        }
    }
    float r = ob[0];
#pragma unroll
    for (int m = 0; m < I3_; m++) r = fmaf(ows[m], fmaxf(acc[m] + gbs[m], 0.f), r);
    out[(size_t)bq * N0_ + nu] = r;
}

// ---------------------------------------------------------------------------
// Launch
// ---------------------------------------------------------------------------
static inline int cdiv(int a, int b) { return (a + b - 1) / b; }

extern "C" void kernel_launch(void* const* d_in, const int* in_sizes, int n_in,
                              void* d_out, int out_size) {
    const float* x        = (const float*)d_in[0];
    const float* mask     = (const float*)d_in[1];
    const float* sa0_feat = (const float*)d_in[2];
    const float* sa1_feat = (const float*)d_in[3];
    const float* sa0_xyz  = (const float*)d_in[4];
    const float* sa1_xyz  = (const float*)d_in[5];
    const float* sa2_xyz  = (const float*)d_in[6];
    const float* w1       = (const float*)d_in[7];
    const float* b1       = (const float*)d_in[8];
    const float* bn1      = (const float*)d_in[9];
    const float* w2       = (const float*)d_in[10];
    const float* b2       = (const float*)d_in[11];
    const float* bn2      = (const float*)d_in[12];
    const float* a1_w     = (const float*)d_in[13];
    const float* a1_b     = (const float*)d_in[14];
    const float* a2_w     = (const float*)d_in[15];
    const float* a2_b     = (const float*)d_in[16];
    const float* fp1_w1   = (const float*)d_in[17];
    const float* fp1_b1   = (const float*)d_in[18];
    const float* fp1_bn1  = (const float*)d_in[19];
    const float* fp1_w2   = (const float*)d_in[20];
    const float* fp1_b2   = (const float*)d_in[21];
    const float* fp1_bn2  = (const float*)d_in[22];
    const float* fp2_w1   = (const float*)d_in[23];
    const float* fp2_b1   = (const float*)d_in[24];
    const float* fp2_bn1  = (const float*)d_in[25];
    const float* fp2_w2   = (const float*)d_in[26];
    const float* fp2_b2   = (const float*)d_in[27];
    const float* fp2_bn2  = (const float*)d_in[28];
    const float* out_w    = (const float*)d_in[29];
    const float* out_b    = (const float*)d_in[30];
    float* out = (float*)d_out;

    float *W1f, *b1f, *W2c, *b2f, *fW1Ac, *fb1f, *fW2c, *fb2f, *gW1Ac, *gb1f, *gW2f, *gb2f;
    float *C1, *d1, *C0, *d0;
    float *Tx, *T2t, *s1, *h3, *T4t;
    int *idx1, *idx2;
    float *wt1, *wt2;
    cudaGetSymbolAddress((void**)&W1f, g_W1f);     cudaGetSymbolAddress((void**)&b1f, g_b1f);
    cudaGetSymbolAddress((void**)&W2c, g_W2c);     cudaGetSymbolAddress((void**)&b2f, g_b2f);
    cudaGetSymbolAddress((void**)&fW1Ac, g_fW1Ac); cudaGetSymbolAddress((void**)&fb1f, g_fb1f);
    cudaGetSymbolAddress((void**)&fW2c, g_fW2c);   cudaGetSymbolAddress((void**)&fb2f, g_fb2f);
    cudaGetSymbolAddress((void**)&gW1Ac, g_gW1Ac); cudaGetSymbolAddress((void**)&gb1f, g_gb1f);
    cudaGetSymbolAddress((void**)&gW2f, g_gW2f);   cudaGetSymbolAddress((void**)&gb2f, g_gb2f);
    cudaGetSymbolAddress((void**)&C1, g_C1);       cudaGetSymbolAddress((void**)&d1, g_d1);
    cudaGetSymbolAddress((void**)&C0, g_C0);       cudaGetSymbolAddress((void**)&d0, g_d0);
    cudaGetSymbolAddress((void**)&Tx, g_Tx);
    cudaGetSymbolAddress((void**)&T2t, g_T2t);
    cudaGetSymbolAddress((void**)&s1, g_s1);
    cudaGetSymbolAddress((void**)&h3, g_h3);
    cudaGetSymbolAddress((void**)&T4t, g_T4t);
    cudaGetSymbolAddress((void**)&idx1, g_idx1);   cudaGetSymbolAddress((void**)&wt1, g_wt1);
    cudaGetSymbolAddress((void**)&idx2, g_idx2);   cudaGetSymbolAddress((void**)&wt2, g_wt2);

    // 1) all weight prep in one launch
    {
        dim3 grid(cdiv(DIM_ * DIM_, 256), 8);
        prep_kernel<<<grid, 256>>>(w1, b1, bn1, w2, b2, bn2,
                                   fp1_w1, fp1_b1, fp1_bn1, fp1_w2, fp1_b2, fp1_bn2,
                                   fp2_w1, fp2_b1, fp2_bn1, fp2_w2, fp2_b2, fp2_bn2,
                                   a1_w, a1_b, a2_w, a2_b,
                                   W1f, b1f, W2c, b2f, fW1Ac, fb1f, fW2c, fb2f,
                                   gW1Ac, gb1f, gW2f, gb2f, C1, d1, C0, d0);
    }
    // 2) both three_nn levels
    {
        dim3 grid(N0_ / 64, B_, 2);
        three_nn_all_kernel<<<grid, 256>>>(sa0_xyz, sa1_xyz, sa2_xyz,
                                           idx1, wt1, idx2, wt2);
    }
    // 3) Tx = W1x * x (per batch)
    {
        dim3 grid(cdiv(N2_, 128), cdiv(DIM_, 64), B_);
        gemm_k<64, 128, 16, 16, 16, 4, 8><<<grid, 256>>>(
            W1f, DIM_, nullptr, x, Tx, DIM_, N2_, CTX_, 0);
    }
    // 4) s1 = C1 * sa1_feat (per batch)
    {
        dim3 grid(cdiv(N1_, 128), cdiv(I1_, 48), B_);
        gemm_k<48, 128, 16, 16, 16, 3, 8><<<grid, 256>>>(
            C1, 128, nullptr, sa1_feat, s1, I1_, N1_, 128, 0);
    }
    // 5) fusedA: T2t = fW1A * ReLU(W2*(h1 on the fly) + b2)
    {
        dim3 grid(N2_ / 64, BQ_);
        fusedA_kernel<<<grid, 256>>>(W2c, b2f, fW1Ac, Tx, mask, W1f, b1f, T2t);
    }
    // 6) h3 = ReLU(interp(T2t) + s1 + bias)
    {
        dim3 grid(N1_ / 256, BQ_);
        interp_fuse1_kernel<<<grid, 256>>>(T2t, idx1, wt1, s1, fb1f, d1, h3);
    }
    // 7) fusedB: T4t = gW1A * ReLU(fW2*h3 + fb2)
    {
        dim3 grid(N1_ / 128, BQ_);
        fusedB_kernel<<<grid, 256>>>(fW2c, fb2f, gW1Ac, h3, T4t);
    }
    // 8) fused final: interp + skip + L1-relu + L2 + projection
    {
        dim3 grid(N0_ / 256, BQ_);
        final_fuse_kernel<<<grid, 256>>>(T4t, idx2, wt2, sa0_feat, C0, d0, gb1f,
                                         gW2f, gb2f, out_w, out_b, out);
    }
}

// round 6
// speedup vs baseline: 4.1990x; 1.1145x over previous
#include <cuda_runtime.h>
#include <cuda_bf16.h>
#include <math.h>

// ---------------------------------------------------------------------------
// Problem constants
// ---------------------------------------------------------------------------
#define B_    2
#define Q_    16
#define BQ_   32
#define N0_   4096
#define N1_   1024
#define N2_   256
#define DIM_  296
#define CTX_  288
#define HEADS_ 8
#define I1_   144
#define I2_   72
#define I3_   36
#define EPS_  1e-5f

// ---------------------------------------------------------------------------
// Scratch (device globals)
// ---------------------------------------------------------------------------
__device__ float g_W1f[DIM_ * DIM_], g_b1f[DIM_];
__device__ float g_b2f[I1_], g_fb1f[I1_], g_fb2f[I2_], g_gb1f[I2_], g_gb2f[I3_];
__device__ float g_gW2f[I3_ * I2_];

// chunked k-major weights: [kc][m][k8]
__device__ float g_W2c[37 * I1_ * 8];     // W2 folded, K=296
__device__ float g_fW1Ac[18 * I1_ * 8];   // fW1 A-part, K=144
__device__ float g_fW2c[18 * I2_ * 8];    // fW2, K=144
__device__ float g_gW1Ac[9 * I2_ * 8];    // gW1 A-part, K=72

__device__ float g_C1[I1_ * 128], g_d1[I1_];
__device__ float g_C0[I2_ * 3],   g_d0[I2_];

__device__ float g_Tx[B_ * DIM_ * N2_];    // W1x * x per batch      (2,296,256)
__device__ float g_T2t[BQ_ * N2_ * I1_];   // fW1A*h2, n-major       (32,256,144)
__device__ float g_s1[B_ * I1_ * N1_];     // skip term FP1          (2,144,1024)
__device__ float g_T4t[BQ_ * N1_ * I2_];   // gW1A*h4, n-major       (32,1024,72)

__device__ int   g_idx1[B_ * N1_ * 3];
__device__ float g_wt1 [B_ * N1_ * 3];
__device__ int   g_idx2[B_ * N0_ * 3];
__device__ float g_wt2 [B_ * N0_ * 3];

// ---------------------------------------------------------------------------
// Prep kernel: BN folds + chunked layouts + adapter combines (one launch)
// ---------------------------------------------------------------------------
__global__ void prep_kernel(
    const float* __restrict__ w1, const float* __restrict__ b1, const float* __restrict__ bn1,
    const float* __restrict__ w2, const float* __restrict__ b2, const float* __restrict__ bn2,
    const float* __restrict__ fw1, const float* __restrict__ fb1, const float* __restrict__ fbn1,
    const float* __restrict__ fw2, const float* __restrict__ fb2, const float* __restrict__ fbn2,
    const float* __restrict__ gw1, const float* __restrict__ gb1, const float* __restrict__ gbn1,
    const float* __restrict__ gw2, const float* __restrict__ gb2, const float* __restrict__ gbn2,
    const float* __restrict__ a1_w, const float* __restrict__ a1_b,
    const float* __restrict__ a2_w, const float* __restrict__ a2_b,
    float* __restrict__ W1f, float* __restrict__ b1f,
    float* __restrict__ W2c, float* __restrict__ b2f,
    float* __restrict__ fW1Ac, float* __restrict__ fb1f,
    float* __restrict__ fW2c, float* __restrict__ fb2f,
    float* __restrict__ gW1Ac, float* __restrict__ gb1f,
    float* __restrict__ gW2f, float* __restrict__ gb2f,
    float* __restrict__ C1, float* __restrict__ d1,
    float* __restrict__ C0, float* __restrict__ d0)
{
    int t = blockIdx.x * 256 + threadIdx.x;
    switch (blockIdx.y) {
    case 0: {
        if (t < DIM_ * DIM_) {
            int m = t / DIM_;
            float s = bn1[m] * rsqrtf(bn1[3 * DIM_ + m] + EPS_);
            W1f[t] = w1[t] * s;
        }
        if (t < DIM_) {
            float s = bn1[t] * rsqrtf(bn1[3 * DIM_ + t] + EPS_);
            b1f[t] = s * (b1[t] - bn1[2 * DIM_ + t]) + bn1[DIM_ + t];
        }
    } break;
    case 1: {
        if (t < 37 * I1_ * 8) {
            int kc = t / (I1_ * 8), r = t % (I1_ * 8), m = r / 8, k = r % 8;
            int gk = kc * 8 + k;
            float s = bn2[m] * rsqrtf(bn2[3 * I1_ + m] + EPS_);
            W2c[t] = w2[m * DIM_ + gk] * s;
        }
        if (t < I1_) {
            float s = bn2[t] * rsqrtf(bn2[3 * I1_ + t] + EPS_);
            b2f[t] = s * (b2[t] - bn2[2 * I1_ + t]) + bn2[I1_ + t];
        }
    } break;
    case 2: {
        if (t < 18 * I1_ * 8) {
            int kc = t / (I1_ * 8), r = t % (I1_ * 8), m = r / 8, k = r % 8;
            int gk = kc * 8 + k;
            float s = fbn1[m] * rsqrtf(fbn1[3 * I1_ + m] + EPS_);
            fW1Ac[t] = fw1[m * (2 * I1_) + gk] * s;
        }
        if (t < I1_) {
            float s = fbn1[t] * rsqrtf(fbn1[3 * I1_ + t] + EPS_);
            fb1f[t] = s * (fb1[t] - fbn1[2 * I1_ + t]) + fbn1[I1_ + t];
        }
    } break;
    case 3: {
        if (t < 18 * I2_ * 8) {
            int kc = t / (I2_ * 8), r = t % (I2_ * 8), m = r / 8, k = r % 8;
            int gk = kc * 8 + k;
            float s = fbn2[m] * rsqrtf(fbn2[3 * I2_ + m] + EPS_);
            fW2c[t] = fw2[m * I1_ + gk] * s;
        }
        if (t < I2_) {
            float s = fbn2[t] * rsqrtf(fbn2[3 * I2_ + t] + EPS_);
            fb2f[t] = s * (fb2[t] - fbn2[2 * I2_ + t]) + fbn2[I2_ + t];
        }
    } break;
    case 4: {
        if (t < 9 * I2_ * 8) {
            int kc = t / (I2_ * 8), r = t % (I2_ * 8), m = r / 8, k = r % 8;
            int gk = kc * 8 + k;
            float s = gbn1[m] * rsqrtf(gbn1[3 * I2_ + m] + EPS_);
            gW1Ac[t] = gw1[m * (2 * I2_) + gk] * s;
        }
        if (t < I2_) {
            float s = gbn1[t] * rsqrtf(gbn1[3 * I2_ + t] + EPS_);
            gb1f[t] = s * (gb1[t] - gbn1[2 * I2_ + t]) + gbn1[I2_ + t];
        }
    } break;
    case 5: {
        if (t < I3_ * I2_) {
            int m = t / I2_;
            float s = gbn2[m] * rsqrtf(gbn2[3 * I3_ + m] + EPS_);
            gW2f[t] = gw2[t] * s;
        }
        if (t < I3_) {
            float s = gbn2[t] * rsqrtf(gbn2[3 * I3_ + t] + EPS_);
            gb2f[t] = s * (gb2[t] - gbn2[2 * I3_ + t]) + gbn2[I3_ + t];
        }
    } break;
    case 6: {
        if (t < I1_ * 128) {
            int o = t / 128, k = t % 128;
            float s = fbn1[o] * rsqrtf(fbn1[3 * I1_ + o] + EPS_);
            float acc = 0.f;
            for (int c = 0; c < I1_; c++)
                acc += fw1[o * (2 * I1_) + I1_ + c] * a2_w[c * 128 + k];
            C1[t] = acc * s;
        }
        if (t < I1_) {
            float s = fbn1[t] * rsqrtf(fbn1[3 * I1_ + t] + EPS_);
            float acc = 0.f;
            for (int c = 0; c < I1_; c++)
                acc += fw1[t * (2 * I1_) + I1_ + c] * a2_b[c];
            d1[t] = acc * s;
        }
    } break;
    case 7: {
        if (t < I2_ * 3) {
            int o = t / 3, k = t % 3;
            float s = gbn1[o] * rsqrtf(gbn1[3 * I2_ + o] + EPS_);
            float acc = 0.f;
            for (int c = 0; c < I2_; c++)
                acc += gw1[o * (2 * I2_) + I2_ + c] * a1_w[c * 3 + k];
            C0[t] = acc * s;
        }
        if (t >= I2_ * 3 && t < I2_ * 4) {
            int o = t - I2_ * 3;
            float s = gbn1[o] * rsqrtf(gbn1[3 * I2_ + o] + EPS_);
            float acc = 0.f;
            for (int c = 0; c < I2_; c++)
                acc += gw1[o * (2 * I2_) + I2_ + c] * a1_b[c];
            d0[o] = acc * s;
        }
    } break;
    }
}

// ---------------------------------------------------------------------------
// Both three_nn levels in ONE launch
// ---------------------------------------------------------------------------
__global__ __launch_bounds__(256)
void three_nn_all_kernel(const float* __restrict__ sa0_xyz,
                         const float* __restrict__ sa1_xyz,
                         const float* __restrict__ sa2_xyz,
                         int* __restrict__ idx1, float* __restrict__ wt1,
                         int* __restrict__ idx2, float* __restrict__ wt2) {
    __shared__ float kx[1024], ky[1024], kz[1024];
    __shared__ float cd[64][4][3];
    __shared__ int   ci[64][4][3];

    const int lvl = blockIdx.z;
    if (!lvl && blockIdx.x >= 16) return;
    const int NK = lvl ? 1024 : 256;
    const int Nu = lvl ? N0_ : N1_;
    const int CS = NK / 4;
    const float* unknown = lvl ? sa0_xyz : sa1_xyz;
    const float* known   = lvl ? sa1_xyz : sa2_xyz;
    int*   idx = lvl ? idx2 : idx1;
    float* w   = lvl ? wt2  : wt1;
    const int b = blockIdx.y;

    const float* kb = known + (size_t)b * NK * 3;
    for (int i = threadIdx.x; i < NK; i += 256) {
        kx[i] = kb[i * 3 + 0];
        ky[i] = kb[i * 3 + 1];
        kz[i] = kb[i * 3 + 2];
    }
    __syncthreads();

    int ul = threadIdx.x & 63;
    int ch = threadIdx.x >> 6;
    int u = blockIdx.x * 64 + ul;
    const float* up = unknown + ((size_t)b * Nu + u) * 3;
    float ux = up[0], uy = up[1], uz = up[2];

    float d0 = 3.4e38f, d1 = 3.4e38f, d2 = 3.4e38f;
    int i0 = 0, i1 = 0, i2 = 0;
    int base = ch * CS;
#pragma unroll 4
    for (int t = 0; t < CS; t++) {
        int i = base + t;
        float dx = ux - kx[i], dy = uy - ky[i], dz = uz - kz[i];
        float d = fmaf(dx, dx, fmaf(dy, dy, dz * dz));
        if (d < d2) {
            if (d < d0)      { d2 = d1; i2 = i1; d1 = d0; i1 = i0; d0 = d; i0 = i; }
            else if (d < d1) { d2 = d1; i2 = i1; d1 = d;  i1 = i; }
            else             { d2 = d;  i2 = i; }
        }
    }
    cd[ul][ch][0] = d0; cd[ul][ch][1] = d1; cd[ul][ch][2] = d2;
    ci[ul][ch][0] = i0; ci[ul][ch][1] = i1; ci[ul][ch][2] = i2;
    __syncthreads();

    if (threadIdx.x < 64) {
        int uu = blockIdx.x * 64 + threadIdx.x;
        float m0 = 3.4e38f, m1 = 3.4e38f, m2 = 3.4e38f;
        int j0 = 0, j1 = 0, j2 = 0;
#pragma unroll
        for (int c = 0; c < 4; c++) {
#pragma unroll
            for (int t = 0; t < 3; t++) {
                float d = cd[threadIdx.x][c][t];
                int i = ci[threadIdx.x][c][t];
                if (d < m2) {
                    if (d < m0)      { m2 = m1; j2 = j1; m1 = m0; j1 = j0; m0 = d; j0 = i; }
                    else if (d < m1) { m2 = m1; j2 = j1; m1 = d;  j1 = i; }
                    else             { m2 = d;  j2 = i; }
                }
            }
        }
        float w0 = 1.f / (m0 + 1e-8f);
        float w1 = 1.f / (m1 + 1e-8f);
        float w2 = 1.f / (m2 + 1e-8f);
        float ws = w0 + w1 + w2;
        size_t o = ((size_t)b * Nu + uu) * 3;
        idx[o] = j0; idx[o + 1] = j1; idx[o + 2] = j2;
        w[o] = w0 / ws; w[o + 1] = w1 / ws; w[o + 2] = w2 / ws;
    }
}

// ---------------------------------------------------------------------------
// Small GEMMs (Tx + s1) packed into one launch for full-chip coverage.
// 256 threads; TX = BN/TN, TY = BM/TM; TX*TY must be 256.
// ---------------------------------------------------------------------------
template <int BM, int BN, int BK, int TM, int TN>
__device__ __forceinline__
void gemm_body(float* sm,
               const float* __restrict__ W, int ldw,
               const float* __restrict__ X,
               float* __restrict__ Y,
               int M, int N, int K, int bx, int by, int b) {
    const int TX = BN / TN;
    float* Ws = sm;             // [BK][BM]
    float* Xs = sm + BK * BM;   // [BK][BN]
    const int m0 = by * BM;
    const int n0 = bx * BN;
    const float* Xb = X + (size_t)b * K * N;
    float* Yb = Y + (size_t)b * M * N;

    const int tid = threadIdx.x;
    const int tx = tid % TX, ty = tid / TX;
    const int tm = ty * TM, tn = tx * TN;

    float acc[TM][TN];
#pragma unroll
    for (int i = 0; i < TM; i++)
#pragma unroll
        for (int j = 0; j < TN; j++) acc[i][j] = 0.f;

    for (int k0 = 0; k0 < K; k0 += BK) {
#pragma unroll
        for (int i = tid; i < BM * BK; i += 256) {
            int m = i / BK, k = i % BK;
            int gm = m0 + m, gk = k0 + k;
            Ws[k * BM + m] = (gm < M) ? W[(size_t)gm * ldw + gk] : 0.f;
        }
#pragma unroll
        for (int i = tid; i < BK * BN; i += 256) {
            int k = i / BN, n = i % BN;
            Xs[k * BN + n] = Xb[(size_t)(k0 + k) * N + n0 + n];
        }
        __syncthreads();
#pragma unroll
        for (int kk = 0; kk < BK; kk++) {
            float a[TM], xv[TN];
#pragma unroll
            for (int i = 0; i < TM; i++) a[i] = Ws[kk * BM + tm + i];
#pragma unroll
            for (int j = 0; j < TN; j++) xv[j] = Xs[kk * BN + tn + j];
#pragma unroll
            for (int i = 0; i < TM; i++)
#pragma unroll
                for (int j = 0; j < TN; j++) acc[i][j] = fmaf(a[i], xv[j], acc[i][j]);
        }
        __syncthreads();
    }
#pragma unroll
    for (int i = 0; i < TM; i++) {
        int m = m0 + tm + i;
        if (m >= M) break;
#pragma unroll
        for (int j = 0; j < TN; j++)
            Yb[(size_t)m * N + n0 + tn + j] = acc[i][j];
    }
}

__global__ __launch_bounds__(256)
void small_gemms_kernel(const float* __restrict__ W1f,
                        const float* __restrict__ x,
                        float* __restrict__ Tx,
                        const float* __restrict__ C1,
                        const float* __restrict__ sa1f,
                        float* __restrict__ s1) {
    __shared__ float sm[16 * 64 + 16 * 64];
    int id = blockIdx.x;
    if (id < 40) {
        // Tx: M=296, N=256, K=288, BM=64, BN=64  -> 4 x 5 x 2 blocks
        int bx = id & 3, r = id >> 2, by = r % 5, b = r / 5;
        gemm_body<64, 64, 16, 4, 4>(sm, W1f, DIM_, x, Tx, DIM_, N2_, CTX_, bx, by, b);
    } else {
        // s1: M=144, N=1024, K=128, BM=48, BN=64 -> 16 x 3 x 2 blocks
        id -= 40;
        int bx = id & 15, r = id >> 4, by = r % 3, b = r / 3;
        gemm_body<48, 64, 16, 3, 4>(sm, C1, 128, sa1f, s1, I1_, N1_, 128, bx, by, b);
    }
}

// ---------------------------------------------------------------------------
// fusedA: T2t = fW1A * ReLU(W2 * h1 + b2),  h1 computed on the fly.
// n-tile 32, grid (8, 32) = 256 blocks, 256 threads, micro-tile 9x2.
// ---------------------------------------------------------------------------
__global__ __launch_bounds__(256)
void fusedA_kernel(const float* __restrict__ W2c,    // (37,144,8)
                   const float* __restrict__ b2f,
                   const float* __restrict__ fW1Ac,  // (18,144,8)
                   const float* __restrict__ Tx,     // (2,296,256)
                   const float* __restrict__ maskg,  // (32,8,256)
                   const float* __restrict__ W1f,    // (296,296)
                   const float* __restrict__ b1f,
                   float* __restrict__ T2t) {        // (32,256,144)
    __shared__ float Ws[1152];        // [m][k8]
    __shared__ float Xs[256];         // [k8][n32]
    __shared__ float Hs[144 * 36];    // [c][n32] pad 36

    const int bq = blockIdx.y, b = bq >> 4;
    const int n0 = blockIdx.x * 32;
    const int tid = threadIdx.x;
    const int tx = tid & 15, ty = tid >> 4;
    const int tm = ty * 9, tn = tx * 2;
    const int kl = tid >> 5, nl = tid & 31;   // Xs slot

    float mv[8];
#pragma unroll
    for (int j = 0; j < 8; j++)
        mv[j] = __ldg(maskg + ((size_t)bq * 8 + j) * N2_ + n0 + nl);
    const float* Txb = Tx + (size_t)b * DIM_ * N2_ + n0 + nl;

    float acc[9][2];
#pragma unroll
    for (int i = 0; i < 9; i++) { acc[i][0] = 0.f; acc[i][1] = 0.f; }

    // h1-on-the-fly evaluator for global k index gk (this thread's n slot)
    auto h1val = [&](int gk) -> float {
        const float4* wp = (const float4*)(W1f + (size_t)gk * DIM_ + CTX_);
        float4 wa = __ldg(wp), wb = __ldg(wp + 1);
        float v = __ldg(Txb + (size_t)gk * N2_) + __ldg(b1f + gk);
        v += wa.x * mv[0] + wa.y * mv[1] + wa.z * mv[2] + wa.w * mv[3]
           + wb.x * mv[4] + wb.y * mv[5] + wb.z * mv[6] + wb.w * mv[7];
        return fmaxf(v, 0.f);
    };

    // ---- phase 1: H = ReLU(W2*h1 + b2), 37 chunks of 8 k
    float4 w4[2];
    float xv;
    {
        int e4b = tid + 256;
        w4[0] = ((const float4*)W2c)[tid];
        if (e4b < 288) w4[1] = ((const float4*)W2c)[e4b];
        xv = h1val(kl);
    }
    for (int kc = 0; kc < 37; kc++) {
        __syncthreads();
        {
            int e4b = tid + 256;
            ((float4*)Ws)[tid] = w4[0];
            if (e4b < 288) ((float4*)Ws)[e4b] = w4[1];
            Xs[tid] = xv;
        }
        __syncthreads();
        if (kc + 1 < 37) {
            const float4* wc = (const float4*)(W2c + (size_t)(kc + 1) * 1152);
            int e4b = tid + 256;
            w4[0] = wc[tid];
            if (e4b < 288) w4[1] = wc[e4b];
            xv = h1val((kc + 1) * 8 + kl);
        }
#pragma unroll
        for (int g = 0; g < 2; g++) {
            float4 a4[9];
#pragma unroll
            for (int i = 0; i < 9; i++)
                a4[i] = *(const float4*)&Ws[(tm + i) * 8 + g * 4];
            float2 x0 = *(const float2*)&Xs[(g * 4 + 0) * 32 + tn];
            float2 x1 = *(const float2*)&Xs[(g * 4 + 1) * 32 + tn];
            float2 x2 = *(const float2*)&Xs[(g * 4 + 2) * 32 + tn];
            float2 x3 = *(const float2*)&Xs[(g * 4 + 3) * 32 + tn];
#pragma unroll
            for (int i = 0; i < 9; i++) {
                acc[i][0] = fmaf(a4[i].x, x0.x, acc[i][0]);
                acc[i][1] = fmaf(a4[i].x, x0.y, acc[i][1]);
                acc[i][0] = fmaf(a4[i].y, x1.x, acc[i][0]);
                acc[i][1] = fmaf(a4[i].y, x1.y, acc[i][1]);
                acc[i][0] = fmaf(a4[i].z, x2.x, acc[i][0]);
                acc[i][1] = fmaf(a4[i].z, x2.y, acc[i][1]);
                acc[i][0] = fmaf(a4[i].w, x3.x, acc[i][0]);
                acc[i][1] = fmaf(a4[i].w, x3.y, acc[i][1]);
            }
        }
    }
#pragma unroll
    for (int i = 0; i < 9; i++) {
        float bv = __ldg(b2f + tm + i);
        float2 hv;
        hv.x = fmaxf(acc[i][0] + bv, 0.f);
        hv.y = fmaxf(acc[i][1] + bv, 0.f);
        *(float2*)&Hs[(tm + i) * 36 + tn] = hv;
    }

    // ---- phase 2: T2 = fW1A * H, 18 chunks of 8
    float acc2[9][2];
#pragma unroll
    for (int i = 0; i < 9; i++) { acc2[i][0] = 0.f; acc2[i][1] = 0.f; }

    {
        int e4b = tid + 256;
        w4[0] = ((const float4*)fW1Ac)[tid];
        if (e4b < 288) w4[1] = ((const float4*)fW1Ac)[e4b];
    }
    for (int kc = 0; kc < 18; kc++) {
        __syncthreads();
        {
            int e4b = tid + 256;
            ((float4*)Ws)[tid] = w4[0];
            if (e4b < 288) ((float4*)Ws)[e4b] = w4[1];
        }
        __syncthreads();
        if (kc + 1 < 18) {
            const float4* wc = (const float4*)(fW1Ac + (size_t)(kc + 1) * 1152);
            int e4b = tid + 256;
            w4[0] = wc[tid];
            if (e4b < 288) w4[1] = wc[e4b];
        }
        int kb = kc * 8;
#pragma unroll
        for (int g = 0; g < 2; g++) {
            float4 a4[9];
#pragma unroll
            for (int i = 0; i < 9; i++)
                a4[i] = *(const float4*)&Ws[(tm + i) * 8 + g * 4];
            float2 x0 = *(const float2*)&Hs[(kb + g * 4 + 0) * 36 + tn];
            float2 x1 = *(const float2*)&Hs[(kb + g * 4 + 1) * 36 + tn];
            float2 x2 = *(const float2*)&Hs[(kb + g * 4 + 2) * 36 + tn];
            float2 x3 = *(const float2*)&Hs[(kb + g * 4 + 3) * 36 + tn];
#pragma unroll
            for (int i = 0; i < 9; i++) {
                acc2[i][0] = fmaf(a4[i].x, x0.x, acc2[i][0]);
                acc2[i][1] = fmaf(a4[i].x, x0.y, acc2[i][1]);
                acc2[i][0] = fmaf(a4[i].y, x1.x, acc2[i][0]);
                acc2[i][1] = fmaf(a4[i].y, x1.y, acc2[i][1]);
                acc2[i][0] = fmaf(a4[i].z, x2.x, acc2[i][0]);
                acc2[i][1] = fmaf(a4[i].z, x2.y, acc2[i][1]);
                acc2[i][0] = fmaf(a4[i].w, x3.x, acc2[i][0]);
                acc2[i][1] = fmaf(a4[i].w, x3.y, acc2[i][1]);
            }
        }
    }
#pragma unroll
    for (int j = 0; j < 2; j++) {
        size_t base = ((size_t)bq * N2_ + n0 + tn + j) * I1_ + tm;
#pragma unroll
        for (int i = 0; i < 9; i++) T2t[base + i] = acc2[i][j];
    }
}

// ---------------------------------------------------------------------------
// fusedB with inline FP1 interpolation:
//   H3[c][nu] = ReLU(interp(T2t) + s1 + fb1 + d1)    (smem, no global h3)
//   T4t = gW1A * ReLU(fW2 * H3 + fb2), n-major (32,1024,72)
// n-tile 64, grid (16, 32) = 512 blocks, 256 threads. Dynamic smem ~64.5KB.
// ---------------------------------------------------------------------------
__global__ __launch_bounds__(256)
void fusedB_kernel(const float* __restrict__ T2t,    // (32,256,144)
                   const int* __restrict__ idx1,
                   const float* __restrict__ wt1,
                   const float* __restrict__ s1,     // (2,144,1024)
                   const float* __restrict__ fb1f,
                   const float* __restrict__ d1v,
                   const float* __restrict__ fW2c,   // (18,72,8)
                   const float* __restrict__ fb2f,
                   const float* __restrict__ gW1Ac,  // (9,72,8)
                   float* __restrict__ T4t) {        // (32,1024,72)
    extern __shared__ float smem[];
    float* Ws  = smem;                 // 576
    float* H3s = smem + 576;           // 144 x 72 (pad)
    float* Hs  = H3s + 144 * 72;       // 72 x 72 (pad)

    const int bq = blockIdx.y, b = bq >> 4;
    const int n0 = blockIdx.x * 64;
    const int tid = threadIdx.x;

    // ---- gather phase: build H3s[c][nu] for 64 nu, 144 channels
    {
        int nu = tid & 63, cg = tid >> 6;      // 4 channel-groups of 36
        size_t o = ((size_t)b * N1_ + n0 + nu) * 3;
        int j0 = idx1[o], j1 = idx1[o + 1], j2 = idx1[o + 2];
        float w0 = wt1[o], w1 = wt1[o + 1], w2 = wt1[o + 2];
        const float4* p0 = (const float4*)(T2t + ((size_t)bq * N2_ + j0) * I1_ + cg * 36);
        const float4* p1 = (const float4*)(T2t + ((size_t)bq * N2_ + j1) * I1_ + cg * 36);
        const float4* p2 = (const float4*)(T2t + ((size_t)bq * N2_ + j2) * I1_ + cg * 36);
        const float* s1b = s1 + ((size_t)b * I1_ + cg * 36) * N1_ + n0 + nu;
#pragma unroll
        for (int cc = 0; cc < 9; cc++) {
            float4 a0 = p0[cc], a1 = p1[cc], a2 = p2[cc];
            int c = cg * 36 + cc * 4;
            float v0 = w0 * a0.x + w1 * a1.x + w2 * a2.x + s1b[(size_t)(cc * 4 + 0) * N1_] + __ldg(fb1f + c + 0) + __ldg(d1v + c + 0);
            float v1 = w0 * a0.y + w1 * a1.y + w2 * a2.y + s1b[(size_t)(cc * 4 + 1) * N1_] + __ldg(fb1f + c + 1) + __ldg(d1v + c + 1);
            float v2 = w0 * a0.z + w1 * a1.z + w2 * a2.z + s1b[(size_t)(cc * 4 + 2) * N1_] + __ldg(fb1f + c + 2) + __ldg(d1v + c + 2);
            float v3 = w0 * a0.w + w1 * a1.w + w2 * a2.w + s1b[(size_t)(cc * 4 + 3) * N1_] + __ldg(fb1f + c + 3) + __ldg(d1v + c + 3);
            H3s[(c + 0) * 72 + nu] = fmaxf(v0, 0.f);
            H3s[(c + 1) * 72 + nu] = fmaxf(v1, 0.f);
            H3s[(c + 2) * 72 + nu] = fmaxf(v2, 0.f);
            H3s[(c + 3) * 72 + nu] = fmaxf(v3, 0.f);
        }
    }
    __syncthreads();

    const int tx = tid & 31, ty = tid >> 5;   // 32 x 8
    const int tm = ty * 9, tn = tx * 2;

    // ---- phase 1: Hs = ReLU(fW2 * H3 + fb2), K=144 (18 chunks of 8)
    float acc[9][2];
#pragma unroll
    for (int i = 0; i < 9; i++) { acc[i][0] = 0.f; acc[i][1] = 0.f; }

    float4 w4;
    if (tid < 144) w4 = ((const float4*)fW2c)[tid];
    for (int kc = 0; kc < 18; kc++) {
        __syncthreads();
        if (tid < 144) ((float4*)Ws)[tid] = w4;
        __syncthreads();
        if (kc + 1 < 18 && tid < 144)
            w4 = ((const float4*)(fW2c + (size_t)(kc + 1) * 576))[tid];
        int kb = kc * 8;
#pragma unroll
        for (int g = 0; g < 2; g++) {
            float4 a4[9];
#pragma unroll
            for (int i = 0; i < 9; i++)
                a4[i] = *(const float4*)&Ws[(tm + i) * 8 + g * 4];
            float2 x0 = *(const float2*)&H3s[(kb + g * 4 + 0) * 72 + tn];
            float2 x1 = *(const float2*)&H3s[(kb + g * 4 + 1) * 72 + tn];
            float2 x2 = *(const float2*)&H3s[(kb + g * 4 + 2) * 72 + tn];
            float2 x3 = *(const float2*)&H3s[(kb + g * 4 + 3) * 72 + tn];
#pragma unroll
            for (int i = 0; i < 9; i++) {
                acc[i][0] = fmaf(a4[i].x, x0.x, acc[i][0]);
                acc[i][1] = fmaf(a4[i].x, x0.y, acc[i][1]);
                acc[i][0] = fmaf(a4[i].y, x1.x, acc[i][0]);
                acc[i][1] = fmaf(a4[i].y, x1.y, acc[i][1]);
                acc[i][0] = fmaf(a4[i].z, x2.x, acc[i][0]);
                acc[i][1] = fmaf(a4[i].z, x2.y, acc[i][1]);
                acc[i][0] = fmaf(a4[i].w, x3.x, acc[i][0]);
                acc[i][1] = fmaf(a4[i].w, x3.y, acc[i][1]);
            }
        }
    }
#pragma unroll
    for (int i = 0; i < 9; i++) {
        float bv = __ldg(fb2f + tm + i);
        float2 hv;
        hv.x = fmaxf(acc[i][0] + bv, 0.f);
        hv.y = fmaxf(acc[i][1] + bv, 0.f);
        *(float2*)&Hs[(tm + i) * 72 + tn] = hv;
    }

    // ---- phase 2: T4 = gW1A * Hs, K=72 (9 chunks of 8)
    float acc2[9][2];
#pragma unroll
    for (int i = 0; i < 9; i++) { acc2[i][0] = 0.f; acc2[i][1] = 0.f; }

    if (tid < 144) w4 = ((const float4*)gW1Ac)[tid];
    for (int kc = 0; kc < 9; kc++) {
        __syncthreads();
        if (tid < 144) ((float4*)Ws)[tid] = w4;
        __syncthreads();
        if (kc + 1 < 9 && tid < 144)
            w4 = ((const float4*)(gW1Ac + (size_t)(kc + 1) * 576))[tid];
        int kb = kc * 8;
#pragma unroll
        for (int g = 0; g < 2; g++) {
            float4 a4[9];
#pragma unroll
            for (int i = 0; i < 9; i++)
                a4[i] = *(const float4*)&Ws[(tm + i) * 8 + g * 4];
            float2 x0 = *(const float2*)&Hs[(kb + g * 4 + 0) * 72 + tn];
            float2 x1 = *(const float2*)&Hs[(kb + g * 4 + 1) * 72 + tn];
            float2 x2 = *(const float2*)&Hs[(kb + g * 4 + 2) * 72 + tn];
            float2 x3 = *(const float2*)&Hs[(kb + g * 4 + 3) * 72 + tn];
#pragma unroll
            for (int i = 0; i < 9; i++) {
                acc2[i][0] = fmaf(a4[i].x, x0.x, acc2[i][0]);
                acc2[i][1] = fmaf(a4[i].x, x0.y, acc2[i][1]);
                acc2[i][0] = fmaf(a4[i].y, x1.x, acc2[i][0]);
                acc2[i][1] = fmaf(a4[i].y, x1.y, acc2[i][1]);
                acc2[i][0] = fmaf(a4[i].z, x2.x, acc2[i][0]);
                acc2[i][1] = fmaf(a4[i].z, x2.y, acc2[i][1]);
                acc2[i][0] = fmaf(a4[i].w, x3.x, acc2[i][0]);
                acc2[i][1] = fmaf(a4[i].w, x3.y, acc2[i][1]);
            }
        }
    }
#pragma unroll
    for (int j = 0; j < 2; j++) {
        size_t base = ((size_t)bq * N1_ + n0 + tn + j) * I2_ + tm;
#pragma unroll
        for (int i = 0; i < 9; i++) T4t[base + i] = acc2[i][j];
    }
}

// ---------------------------------------------------------------------------
// Fused final: interp(T4t)+skip+relu (FP2-L1), FP2-L2+relu, out projection
// ---------------------------------------------------------------------------
__global__ __launch_bounds__(256)
void final_fuse_kernel(const float* __restrict__ T4t,
                       const int* __restrict__ idx,
                       const float* __restrict__ wt,
                       const float* __restrict__ sa0f,
                       const float* __restrict__ C0,
                       const float* __restrict__ d0v,
                       const float* __restrict__ gb1,
                       const float* __restrict__ gW2,
                       const float* __restrict__ gb2,
                       const float* __restrict__ ow,
                       const float* __restrict__ ob,
                       float* __restrict__ out) {
    __shared__ float gT[I2_ * I3_];   // gT[c*36+m] = gW2[m][c]
    __shared__ float c0s[I2_ * 3];
    __shared__ float bs[I2_];
    __shared__ float gbs[I3_], ows[I3_];
    int tid = threadIdx.x;
    for (int e = tid; e < I2_ * I3_; e += 256) {
        int c = e / I3_, m = e % I3_;
        gT[e] = gW2[m * I2_ + c];
    }
    if (tid < I2_ * 3) c0s[tid] = C0[tid];
    if (tid < I2_) bs[tid] = d0v[tid] + gb1[tid];
    if (tid < I3_) { gbs[tid] = gb2[tid]; ows[tid] = ow[tid]; }
    __syncthreads();

    int bq = blockIdx.y, b = bq >> 4;
    int nu = blockIdx.x * 256 + tid;
    size_t o = ((size_t)b * N0_ + nu) * 3;
    int j0 = idx[o], j1 = idx[o + 1], j2 = idx[o + 2];
    float w0 = wt[o], w1 = wt[o + 1], w2 = wt[o + 2];
    const float4* p0 = (const float4*)(T4t + ((size_t)bq * N1_ + j0) * I2_);
    const float4* p1 = (const float4*)(T4t + ((size_t)bq * N1_ + j1) * I2_);
    const float4* p2 = (const float4*)(T4t + ((size_t)bq * N1_ + j2) * I2_);
    float f0 = sa0f[((size_t)b * 3 + 0) * N0_ + nu];
    float f1 = sa0f[((size_t)b * 3 + 1) * N0_ + nu];
    float f2 = sa0f[((size_t)b * 3 + 2) * N0_ + nu];

    float acc[I3_];
#pragma unroll
    for (int m = 0; m < I3_; m++) acc[m] = 0.f;

#pragma unroll 3
    for (int cc = 0; cc < 18; cc++) {
        float4 a0 = p0[cc], a1 = p1[cc], a2 = p2[cc];
        int c = cc * 4;
        float hv[4];
        hv[0] = fmaxf(w0 * a0.x + w1 * a1.x + w2 * a2.x + c0s[(c + 0) * 3] * f0 + c0s[(c + 0) * 3 + 1] * f1 + c0s[(c + 0) * 3 + 2] * f2 + bs[c + 0], 0.f);
        hv[1] = fmaxf(w0 * a0.y + w1 * a1.y + w2 * a2.y + c0s[(c + 1) * 3] * f0 + c0s[(c + 1) * 3 + 1] * f1 + c0s[(c + 1) * 3 + 2] * f2 + bs[c + 1], 0.f);
        hv[2] = fmaxf(w0 * a0.z + w1 * a1.z + w2 * a2.z + c0s[(c + 2) * 3] * f0 + c0s[(c + 2) * 3 + 1] * f1 + c0s[(c + 2) * 3 + 2] * f2 + bs[c + 2], 0.f);
        hv[3] = fmaxf(w0 * a0.w + w1 * a1.w + w2 * a2.w + c0s[(c + 3) * 3] * f0 + c0s[(c + 3) * 3 + 1] * f1 + c0s[(c + 3) * 3 + 2] * f2 + bs[c + 3], 0.f);
#pragma unroll
        for (int q = 0; q < 4; q++) {
            const float4* g4 = (const float4*)&gT[(c + q) * I3_];
#pragma unroll
            for (int mm = 0; mm < 9; mm++) {
                float4 g = g4[mm];
                acc[mm * 4 + 0] = fmaf(g.x, hv[q], acc[mm * 4 + 0]);
                acc[mm * 4 + 1] = fmaf(g.y, hv[q], acc[mm * 4 + 1]);
                acc[mm * 4 + 2] = fmaf(g.z, hv[q], acc[mm * 4 + 2]);
                acc[mm * 4 + 3] = fmaf(g.w, hv[q], acc[mm * 4 + 3]);
            }
        }
    }
    float r = ob[0];
#pragma unroll
    for (int m = 0; m < I3_; m++) r = fmaf(ows[m], fmaxf(acc[m] + gbs[m], 0.f), r);
    out[(size_t)bq * N0_ + nu] = r;
}

// ---------------------------------------------------------------------------
// Launch
// ---------------------------------------------------------------------------
static inline int cdiv(int a, int b) { return (a + b - 1) / b; }

extern "C" void kernel_launch(void* const* d_in, const int* in_sizes, int n_in,
                              void* d_out, int out_size) {
    const float* x        = (const float*)d_in[0];
    const float* mask     = (const float*)d_in[1];
    const float* sa0_feat = (const float*)d_in[2];
    const float* sa1_feat = (const float*)d_in[3];
    const float* sa0_xyz  = (const float*)d_in[4];
    const float* sa1_xyz  = (const float*)d_in[5];
    const float* sa2_xyz  = (const float*)d_in[6];
    const float* w1       = (const float*)d_in[7];
    const float* b1       = (const float*)d_in[8];
    const float* bn1      = (const float*)d_in[9];
    const float* w2       = (const float*)d_in[10];
    const float* b2       = (const float*)d_in[11];
    const float* bn2      = (const float*)d_in[12];
    const float* a1_w     = (const float*)d_in[13];
    const float* a1_b     = (const float*)d_in[14];
    const float* a2_w     = (const float*)d_in[15];
    const float* a2_b     = (const float*)d_in[16];
    const float* fp1_w1   = (const float*)d_in[17];
    const float* fp1_b1   = (const float*)d_in[18];
    const float* fp1_bn1  = (const float*)d_in[19];
    const float* fp1_w2   = (const float*)d_in[20];
    const float* fp1_b2   = (const float*)d_in[21];
    const float* fp1_bn2  = (const float*)d_in[22];
    const float* fp2_w1   = (const float*)d_in[23];
    const float* fp2_b1   = (const float*)d_in[24];
    const float* fp2_bn1  = (const float*)d_in[25];
    const float* fp2_w2   = (const float*)d_in[26];
    const float* fp2_b2   = (const float*)d_in[27];
    const float* fp2_bn2  = (const float*)d_in[28];
    const float* out_w    = (const float*)d_in[29];
    const float* out_b    = (const float*)d_in[30];
    float* out = (float*)d_out;

    float *W1f, *b1f, *W2c, *b2f, *fW1Ac, *fb1f, *fW2c, *fb2f, *gW1Ac, *gb1f, *gW2f, *gb2f;
    float *C1, *d1, *C0, *d0;
    float *Tx, *T2t, *s1, *T4t;
    int *idx1, *idx2;
    float *wt1, *wt2;
    cudaGetSymbolAddress((void**)&W1f, g_W1f);     cudaGetSymbolAddress((void**)&b1f, g_b1f);
    cudaGetSymbolAddress((void**)&W2c, g_W2c);     cudaGetSymbolAddress((void**)&b2f, g_b2f);
    cudaGetSymbolAddress((void**)&fW1Ac, g_fW1Ac); cudaGetSymbolAddress((void**)&fb1f, g_fb1f);
    cudaGetSymbolAddress((void**)&fW2c, g_fW2c);   cudaGetSymbolAddress((void**)&fb2f, g_fb2f);
    cudaGetSymbolAddress((void**)&gW1Ac, g_gW1Ac); cudaGetSymbolAddress((void**)&gb1f, g_gb1f);
    cudaGetSymbolAddress((void**)&gW2f, g_gW2f);   cudaGetSymbolAddress((void**)&gb2f, g_gb2f);
    cudaGetSymbolAddress((void**)&C1, g_C1);       cudaGetSymbolAddress((void**)&d1, g_d1);
    cudaGetSymbolAddress((void**)&C0, g_C0);       cudaGetSymbolAddress((void**)&d0, g_d0);
    cudaGetSymbolAddress((void**)&Tx, g_Tx);
    cudaGetSymbolAddress((void**)&T2t, g_T2t);
    cudaGetSymbolAddress((void**)&s1, g_s1);
    cudaGetSymbolAddress((void**)&T4t, g_T4t);
    cudaGetSymbolAddress((void**)&idx1, g_idx1);   cudaGetSymbolAddress((void**)&wt1, g_wt1);
    cudaGetSymbolAddress((void**)&idx2, g_idx2);   cudaGetSymbolAddress((void**)&wt2, g_wt2);

    // 1) weight prep
    {
        dim3 grid(cdiv(DIM_ * DIM_, 256), 8);
        prep_kernel<<<grid, 256>>>(w1, b1, bn1, w2, b2, bn2,
                                   fp1_w1, fp1_b1, fp1_bn1, fp1_w2, fp1_b2, fp1_bn2,
                                   fp2_w1, fp2_b1, fp2_bn1, fp2_w2, fp2_b2, fp2_bn2,
                                   a1_w, a1_b, a2_w, a2_b,
                                   W1f, b1f, W2c, b2f, fW1Ac, fb1f, fW2c, fb2f,
                                   gW1Ac, gb1f, gW2f, gb2f, C1, d1, C0, d0);
    }
    // 2) Tx + s1 small GEMMs (136 blocks, one launch)
    small_gemms_kernel<<<136, 256>>>(W1f, x, Tx, C1, sa1_feat, s1);
    // 3) both three_nn levels
    {
        dim3 grid(N0_ / 64, B_, 2);
        three_nn_all_kernel<<<grid, 256>>>(sa0_xyz, sa1_xyz, sa2_xyz,
                                           idx1, wt1, idx2, wt2);
    }
    // 4) fusedA: T2t = fW1A * ReLU(W2*(h1 on the fly) + b2)
    {
        dim3 grid(N2_ / 32, BQ_);
        fusedA_kernel<<<grid, 256>>>(W2c, b2f, fW1Ac, Tx, mask, W1f, b1f, T2t);
    }
    // 5) fusedB (inline FP1 interp): T4t = gW1A * ReLU(fW2*H3 + fb2)
    {
        const int smem_bytes = (576 + 144 * 72 + 72 * 72) * 4;
        cudaFuncSetAttribute(fusedB_kernel,
                             cudaFuncAttributeMaxDynamicSharedMemorySize, smem_bytes);
        dim3 grid(N1_ / 64, BQ_);
        fusedB_kernel<<<grid, 256, smem_bytes>>>(T2t, idx1, wt1, s1, fb1f, d1,
                                                 fW2c, fb2f, gW1Ac, T4t);
    }
    // 6) fused final: interp + skip + L1-relu + L2 + projection
    {
        dim3 grid(N0_ / 256, BQ_);
        final_fuse_kernel<<<grid, 256>>>(T4t, idx2, wt2, sa0_feat, C0, d0, gb1f,
                                         gW2f, gb2f, out_w, out_b, out);
    }
}

// round 7
// speedup vs baseline: 4.6311x; 1.1029x over previous
#include <cuda_runtime.h>
#include <cuda_bf16.h>
#include <math.h>

// ---------------------------------------------------------------------------
// Problem constants
// ---------------------------------------------------------------------------
#define B_    2
#define Q_    16
#define BQ_   32
#define N0_   4096
#define N1_   1024
#define N2_   256
#define DIM_  296
#define CTX_  288
#define HEADS_ 8
#define I1_   144
#define I2_   72
#define I3_   36
#define EPS_  1e-5f

// ---------------------------------------------------------------------------
// Scratch (device globals)
// ---------------------------------------------------------------------------
__device__ float g_W1f[DIM_ * DIM_], g_b1f[DIM_];
__device__ float g_b2f[I1_], g_fb1f[I1_], g_fb2f[I2_], g_gb1f[I2_], g_gb2f[I3_];
__device__ float g_gW2f[I3_ * I2_];

// chunked k-major weights: [kc][m][k8]
__device__ float g_W2c[37 * I1_ * 8];
__device__ float g_fW1Ac[18 * I1_ * 8];
__device__ float g_fW2c[18 * I2_ * 8];
__device__ float g_gW1Ac[9 * I2_ * 8];

__device__ float g_C1[I1_ * 128], g_d1[I1_];
__device__ float g_C0[I2_ * 3],   g_d0[I2_];

__device__ float g_Tx[B_ * DIM_ * N2_];
__device__ float g_T2t[BQ_ * N2_ * I1_];
__device__ float g_s1[B_ * I1_ * N1_];
__device__ float g_T4t[BQ_ * N1_ * I2_];

__device__ int   g_idx1[B_ * N1_ * 3];
__device__ float g_wt1 [B_ * N1_ * 3];
__device__ int   g_idx2[B_ * N0_ * 3];
__device__ float g_wt2 [B_ * N0_ * 3];

// ---------------------------------------------------------------------------
// Prep kernel (unchanged semantics)
// ---------------------------------------------------------------------------
__global__ void prep_kernel(
    const float* __restrict__ w1, const float* __restrict__ b1, const float* __restrict__ bn1,
    const float* __restrict__ w2, const float* __restrict__ b2, const float* __restrict__ bn2,
    const float* __restrict__ fw1, const float* __restrict__ fb1, const float* __restrict__ fbn1,
    const float* __restrict__ fw2, const float* __restrict__ fb2, const float* __restrict__ fbn2,
    const float* __restrict__ gw1, const float* __restrict__ gb1, const float* __restrict__ gbn1,
    const float* __restrict__ gw2, const float* __restrict__ gb2, const float* __restrict__ gbn2,
    const float* __restrict__ a1_w, const float* __restrict__ a1_b,
    const float* __restrict__ a2_w, const float* __restrict__ a2_b,
    float* __restrict__ W1f, float* __restrict__ b1f,
    float* __restrict__ W2c, float* __restrict__ b2f,
    float* __restrict__ fW1Ac, float* __restrict__ fb1f,
    float* __restrict__ fW2c, float* __restrict__ fb2f,
    float* __restrict__ gW1Ac, float* __restrict__ gb1f,
    float* __restrict__ gW2f, float* __restrict__ gb2f,
    float* __restrict__ C1, float* __restrict__ d1,
    float* __restrict__ C0, float* __restrict__ d0)
{
    int t = blockIdx.x * 256 + threadIdx.x;
    switch (blockIdx.y) {
    case 0: {
        if (t < DIM_ * DIM_) {
            int m = t / DIM_;
            float s = bn1[m] * rsqrtf(bn1[3 * DIM_ + m] + EPS_);
            W1f[t] = w1[t] * s;
        }
        if (t < DIM_) {
            float s = bn1[t] * rsqrtf(bn1[3 * DIM_ + t] + EPS_);
            b1f[t] = s * (b1[t] - bn1[2 * DIM_ + t]) + bn1[DIM_ + t];
        }
    } break;
    case 1: {
        if (t < 37 * I1_ * 8) {
            int kc = t / (I1_ * 8), r = t % (I1_ * 8), m = r / 8, k = r % 8;
            int gk = kc * 8 + k;
            float s = bn2[m] * rsqrtf(bn2[3 * I1_ + m] + EPS_);
            W2c[t] = w2[m * DIM_ + gk] * s;
        }
        if (t < I1_) {
            float s = bn2[t] * rsqrtf(bn2[3 * I1_ + t] + EPS_);
            b2f[t] = s * (b2[t] - bn2[2 * I1_ + t]) + bn2[I1_ + t];
        }
    } break;
    case 2: {
        if (t < 18 * I1_ * 8) {
            int kc = t / (I1_ * 8), r = t % (I1_ * 8), m = r / 8, k = r % 8;
            int gk = kc * 8 + k;
            float s = fbn1[m] * rsqrtf(fbn1[3 * I1_ + m] + EPS_);
            fW1Ac[t] = fw1[m * (2 * I1_) + gk] * s;
        }
        if (t < I1_) {
            float s = fbn1[t] * rsqrtf(fbn1[3 * I1_ + t] + EPS_);
            fb1f[t] = s * (fb1[t] - fbn1[2 * I1_ + t]) + fbn1[I1_ + t];
        }
    } break;
    case 3: {
        if (t < 18 * I2_ * 8) {
            int kc = t / (I2_ * 8), r = t % (I2_ * 8), m = r / 8, k = r % 8;
            int gk = kc * 8 + k;
            float s = fbn2[m] * rsqrtf(fbn2[3 * I2_ + m] + EPS_);
            fW2c[t] = fw2[m * I1_ + gk] * s;
        }
        if (t < I2_) {
            float s = fbn2[t] * rsqrtf(fbn2[3 * I2_ + t] + EPS_);
            fb2f[t] = s * (fb2[t] - fbn2[2 * I2_ + t]) + fbn2[I2_ + t];
        }
    } break;
    case 4: {
        if (t < 9 * I2_ * 8) {
            int kc = t / (I2_ * 8), r = t % (I2_ * 8), m = r / 8, k = r % 8;
            int gk = kc * 8 + k;
            float s = gbn1[m] * rsqrtf(gbn1[3 * I2_ + m] + EPS_);
            gW1Ac[t] = gw1[m * (2 * I2_) + gk] * s;
        }
        if (t < I2_) {
            float s = gbn1[t] * rsqrtf(gbn1[3 * I2_ + t] + EPS_);
            gb1f[t] = s * (gb1[t] - gbn1[2 * I2_ + t]) + gbn1[I2_ + t];
        }
    } break;
    case 5: {
        if (t < I3_ * I2_) {
            int m = t / I2_;
            float s = gbn2[m] * rsqrtf(gbn2[3 * I3_ + m] + EPS_);
            gW2f[t] = gw2[t] * s;
        }
        if (t < I3_) {
            float s = gbn2[t] * rsqrtf(gbn2[3 * I3_ + t] + EPS_);
            gb2f[t] = s * (gb2[t] - gbn2[2 * I3_ + t]) + gbn2[I3_ + t];
        }
    } break;
    case 6: {
        if (t < I1_ * 128) {
            int o = t / 128, k = t % 128;
            float s = fbn1[o] * rsqrtf(fbn1[3 * I1_ + o] + EPS_);
            float acc = 0.f;
            for (int c = 0; c < I1_; c++)
                acc += fw1[o * (2 * I1_) + I1_ + c] * a2_w[c * 128 + k];
            C1[t] = acc * s;
        }
        if (t < I1_) {
            float s = fbn1[t] * rsqrtf(fbn1[3 * I1_ + t] + EPS_);
            float acc = 0.f;
            for (int c = 0; c < I1_; c++)
                acc += fw1[t * (2 * I1_) + I1_ + c] * a2_b[c];
            d1[t] = acc * s;
        }
    } break;
    case 7: {
        if (t < I2_ * 3) {
            int o = t / 3, k = t % 3;
            float s = gbn1[o] * rsqrtf(gbn1[3 * I2_ + o] + EPS_);
            float acc = 0.f;
            for (int c = 0; c < I2_; c++)
                acc += gw1[o * (2 * I2_) + I2_ + c] * a1_w[c * 3 + k];
            C0[t] = acc * s;
        }
        if (t >= I2_ * 3 && t < I2_ * 4) {
            int o = t - I2_ * 3;
            float s = gbn1[o] * rsqrtf(gbn1[3 * I2_ + o] + EPS_);
            float acc = 0.f;
            for (int c = 0; c < I2_; c++)
                acc += gw1[o * (2 * I2_) + I2_ + c] * a1_b[c];
            d0[o] = acc * s;
        }
    } break;
    }
}

// ---------------------------------------------------------------------------
// GEMM body for the util kernel (256 threads)
// ---------------------------------------------------------------------------
template <int BM, int BN, int BK, int TM, int TN>
__device__ __forceinline__
void gemm_body(float* sm,
               const float* __restrict__ W, int ldw,
               const float* __restrict__ X,
               float* __restrict__ Y,
               int M, int N, int K, int bx, int by, int b) {
    const int TX = BN / TN;
    float* Ws = sm;
    float* Xs = sm + BK * BM;
    const int m0 = by * BM;
    const int n0 = bx * BN;
    const float* Xb = X + (size_t)b * K * N;
    float* Yb = Y + (size_t)b * M * N;

    const int tid = threadIdx.x;
    const int tx = tid % TX, ty = tid / TX;
    const int tm = ty * TM, tn = tx * TN;

    float acc[TM][TN];
#pragma unroll
    for (int i = 0; i < TM; i++)
#pragma unroll
        for (int j = 0; j < TN; j++) acc[i][j] = 0.f;

    for (int k0 = 0; k0 < K; k0 += BK) {
#pragma unroll
        for (int i = tid; i < BM * BK; i += 256) {
            int m = i / BK, k = i % BK;
            int gm = m0 + m, gk = k0 + k;
            Ws[k * BM + m] = (gm < M) ? W[(size_t)gm * ldw + gk] : 0.f;
        }
#pragma unroll
        for (int i = tid; i < BK * BN; i += 256) {
            int k = i / BN, n = i % BN;
            Xs[k * BN + n] = Xb[(size_t)(k0 + k) * N + n0 + n];
        }
        __syncthreads();
#pragma unroll
        for (int kk = 0; kk < BK; kk++) {
            float a[TM], xv[TN];
#pragma unroll
            for (int i = 0; i < TM; i++) a[i] = Ws[kk * BM + tm + i];
#pragma unroll
            for (int j = 0; j < TN; j++) xv[j] = Xs[kk * BN + tn + j];
#pragma unroll
            for (int i = 0; i < TM; i++)
#pragma unroll
                for (int j = 0; j < TN; j++) acc[i][j] = fmaf(a[i], xv[j], acc[i][j]);
        }
        __syncthreads();
    }
#pragma unroll
    for (int i = 0; i < TM; i++) {
        int m = m0 + tm + i;
        if (m >= M) break;
#pragma unroll
        for (int j = 0; j < TN; j++)
            Yb[(size_t)m * N + n0 + tn + j] = acc[i][j];
    }
}

// ---------------------------------------------------------------------------
// three_nn body (256 threads), smem provided by caller
// ---------------------------------------------------------------------------
__device__ __forceinline__
void three_nn_body(float* sm, int id2,
                   const float* __restrict__ sa0_xyz,
                   const float* __restrict__ sa1_xyz,
                   const float* __restrict__ sa2_xyz,
                   int* __restrict__ idx1, float* __restrict__ wt1,
                   int* __restrict__ idx2, float* __restrict__ wt2) {
    float* kx = sm;
    float* ky = sm + 1024;
    float* kz = sm + 2048;
    float* cd = sm + 3072;            // 64*4*3 = 768
    int*   ci = (int*)(sm + 3840);    // 768

    int lvl, bx, b;
    if (id2 < 32) { lvl = 0; bx = id2 & 15; b = id2 >> 4; }
    else          { int id3 = id2 - 32; lvl = 1; bx = id3 & 63; b = id3 >> 6; }
    const int NK = lvl ? 1024 : 256;
    const int Nu = lvl ? N0_ : N1_;
    const int CS = NK / 4;
    const float* unknown = lvl ? sa0_xyz : sa1_xyz;
    const float* known   = lvl ? sa1_xyz : sa2_xyz;
    int*   idx = lvl ? idx2 : idx1;
    float* w   = lvl ? wt2  : wt1;

    const float* kb = known + (size_t)b * NK * 3;
    for (int i = threadIdx.x; i < NK; i += 256) {
        kx[i] = kb[i * 3 + 0];
        ky[i] = kb[i * 3 + 1];
        kz[i] = kb[i * 3 + 2];
    }
    __syncthreads();

    int ul = threadIdx.x & 63;
    int ch = threadIdx.x >> 6;
    int u = bx * 64 + ul;
    const float* up = unknown + ((size_t)b * Nu + u) * 3;
    float ux = up[0], uy = up[1], uz = up[2];

    float d0 = 3.4e38f, d1 = 3.4e38f, d2 = 3.4e38f;
    int i0 = 0, i1 = 0, i2 = 0;
    int base = ch * CS;
#pragma unroll 4
    for (int t = 0; t < CS; t++) {
        int i = base + t;
        float dx = ux - kx[i], dy = uy - ky[i], dz = uz - kz[i];
        float d = fmaf(dx, dx, fmaf(dy, dy, dz * dz));
        if (d < d2) {
            if (d < d0)      { d2 = d1; i2 = i1; d1 = d0; i1 = i0; d0 = d; i0 = i; }
            else if (d < d1) { d2 = d1; i2 = i1; d1 = d;  i1 = i; }
            else             { d2 = d;  i2 = i; }
        }
    }
    cd[(ul * 4 + ch) * 3 + 0] = d0; cd[(ul * 4 + ch) * 3 + 1] = d1; cd[(ul * 4 + ch) * 3 + 2] = d2;
    ci[(ul * 4 + ch) * 3 + 0] = i0; ci[(ul * 4 + ch) * 3 + 1] = i1; ci[(ul * 4 + ch) * 3 + 2] = i2;
    __syncthreads();

    if (threadIdx.x < 64) {
        int uu = bx * 64 + threadIdx.x;
        float m0 = 3.4e38f, m1 = 3.4e38f, m2 = 3.4e38f;
        int j0 = 0, j1 = 0, j2 = 0;
#pragma unroll
        for (int c = 0; c < 4; c++) {
#pragma unroll
            for (int t = 0; t < 3; t++) {
                float d = cd[(threadIdx.x * 4 + c) * 3 + t];
                int i = ci[(threadIdx.x * 4 + c) * 3 + t];
                if (d < m2) {
                    if (d < m0)      { m2 = m1; j2 = j1; m1 = m0; j1 = j0; m0 = d; j0 = i; }
                    else if (d < m1) { m2 = m1; j2 = j1; m1 = d;  j1 = i; }
                    else             { m2 = d;  j2 = i; }
                }
            }
        }
        float w0 = 1.f / (m0 + 1e-8f);
        float w1 = 1.f / (m1 + 1e-8f);
        float w2 = 1.f / (m2 + 1e-8f);
        float ws = w0 + w1 + w2;
        size_t o = ((size_t)b * Nu + uu) * 3;
        idx[o] = j0; idx[o + 1] = j1; idx[o + 2] = j2;
        w[o] = w0 / ws; w[o + 1] = w1 / ws; w[o + 2] = w2 / ws;
    }
}

// ---------------------------------------------------------------------------
// util kernel: Tx GEMM (40) + s1 GEMM (96) + three_nn (160) = 296 blocks
// ---------------------------------------------------------------------------
__global__ __launch_bounds__(256)
void util_kernel(const float* __restrict__ W1f,
                 const float* __restrict__ x,
                 float* __restrict__ Tx,
                 const float* __restrict__ C1,
                 const float* __restrict__ sa1f,
                 float* __restrict__ s1,
                 const float* __restrict__ sa0_xyz,
                 const float* __restrict__ sa1_xyz,
                 const float* __restrict__ sa2_xyz,
                 int* __restrict__ idx1, float* __restrict__ wt1,
                 int* __restrict__ idx2, float* __restrict__ wt2) {
    __shared__ float sm[4608];
    int id = blockIdx.x;
    if (id < 40) {
        int bx = id & 3, r = id >> 2, by = r % 5, b = r / 5;
        gemm_body<64, 64, 16, 4, 4>(sm, W1f, DIM_, x, Tx, DIM_, N2_, CTX_, bx, by, b);
    } else if (id < 136) {
        int id1 = id - 40;
        int bx = id1 & 15, r = id1 >> 4, by = r % 3, b = r / 3;
        gemm_body<48, 64, 16, 3, 4>(sm, C1, 128, sa1f, s1, I1_, N1_, 128, bx, by, b);
    } else {
        three_nn_body(sm, id - 136, sa0_xyz, sa1_xyz, sa2_xyz, idx1, wt1, idx2, wt2);
    }
}

// ---------------------------------------------------------------------------
// fusedA: 128 threads, micro-tile 9x4 (TX=8, TY=16), n-tile 32, grid (8,32)
// ---------------------------------------------------------------------------
__global__ __launch_bounds__(128)
void fusedA_kernel(const float* __restrict__ W2c,    // (37,144,8)
                   const float* __restrict__ b2f,
                   const float* __restrict__ fW1Ac,  // (18,144,8)
                   const float* __restrict__ Tx,     // (2,296,256)
                   const float* __restrict__ maskg,  // (32,8,256)
                   const float* __restrict__ W1f,    // (296,296)
                   const float* __restrict__ b1f,
                   float* __restrict__ T2t) {        // (32,256,144)
    __shared__ float Ws[1152];        // [m][k8]
    __shared__ float Xs[256];         // [k8][n32]
    __shared__ float Hs[144 * 36];    // [c][n32] pad 36

    const int bq = blockIdx.y, b = bq >> 4;
    const int n0 = blockIdx.x * 32;
    const int tid = threadIdx.x;
    const int tx = tid & 7, ty = tid >> 3;
    const int tm = ty * 9, tn = tx * 4;

    // each thread owns 2 Xs slots
    const int kl0 = tid >> 5,           nl0 = tid & 31;
    const int kl1 = (tid + 128) >> 5,   nl1 = (tid + 128) & 31;
    float mv0[8], mv1[8];
#pragma unroll
    for (int j = 0; j < 8; j++) {
        mv0[j] = __ldg(maskg + ((size_t)bq * 8 + j) * N2_ + n0 + nl0);
        mv1[j] = __ldg(maskg + ((size_t)bq * 8 + j) * N2_ + n0 + nl1);
    }
    const float* Txb = Tx + (size_t)b * DIM_ * N2_ + n0;

    float acc[9][4];
#pragma unroll
    for (int i = 0; i < 9; i++)
#pragma unroll
        for (int j = 0; j < 4; j++) acc[i][j] = 0.f;

    auto h1v = [&](int gk, int nl, const float* mv) -> float {
        const float4* wp = (const float4*)(W1f + (size_t)gk * DIM_ + CTX_);
        float4 wa = __ldg(wp), wb = __ldg(wp + 1);
        float v = __ldg(Txb + (size_t)gk * N2_ + nl) + __ldg(b1f + gk);
        v += wa.x * mv[0] + wa.y * mv[1] + wa.z * mv[2] + wa.w * mv[3]
           + wb.x * mv[4] + wb.y * mv[5] + wb.z * mv[6] + wb.w * mv[7];
        return fmaxf(v, 0.f);
    };

    // ---- phase 1: H = ReLU(W2*h1 + b2), 37 chunks of 8 k
    float4 w4[3];
    float xv0, xv1;
    {
#pragma unroll
        for (int r = 0; r < 3; r++) {
            int e = tid + r * 128;
            if (e < 288) w4[r] = ((const float4*)W2c)[e];
        }
        xv0 = h1v(kl0, nl0, mv0);
        xv1 = h1v(kl1, nl1, mv1);
    }
    for (int kc = 0; kc < 37; kc++) {
        __syncthreads();
        {
#pragma unroll
            for (int r = 0; r < 3; r++) {
                int e = tid + r * 128;
                if (e < 288) ((float4*)Ws)[e] = w4[r];
            }
            Xs[tid] = xv0;
            Xs[tid + 128] = xv1;
        }
        __syncthreads();
        if (kc + 1 < 37) {
            const float4* wc = (const float4*)(W2c + (size_t)(kc + 1) * 1152);
#pragma unroll
            for (int r = 0; r < 3; r++) {
                int e = tid + r * 128;
                if (e < 288) w4[r] = wc[e];
            }
            xv0 = h1v((kc + 1) * 8 + kl0, nl0, mv0);
            xv1 = h1v((kc + 1) * 8 + kl1, nl1, mv1);
        }
#pragma unroll
        for (int g = 0; g < 2; g++) {
            float4 a4[9];
#pragma unroll
            for (int i = 0; i < 9; i++)
                a4[i] = *(const float4*)&Ws[(tm + i) * 8 + g * 4];
            float4 x0 = *(const float4*)&Xs[(g * 4 + 0) * 32 + tn];
            float4 x1 = *(const float4*)&Xs[(g * 4 + 1) * 32 + tn];
            float4 x2 = *(const float4*)&Xs[(g * 4 + 2) * 32 + tn];
            float4 x3 = *(const float4*)&Xs[(g * 4 + 3) * 32 + tn];
#pragma unroll
            for (int i = 0; i < 9; i++) {
                acc[i][0] = fmaf(a4[i].x, x0.x, acc[i][0]);
                acc[i][1] = fmaf(a4[i].x, x0.y, acc[i][1]);
                acc[i][2] = fmaf(a4[i].x, x0.z, acc[i][2]);
                acc[i][3] = fmaf(a4[i].x, x0.w, acc[i][3]);
                acc[i][0] = fmaf(a4[i].y, x1.x, acc[i][0]);
                acc[i][1] = fmaf(a4[i].y, x1.y, acc[i][1]);
                acc[i][2] = fmaf(a4[i].y, x1.z, acc[i][2]);
                acc[i][3] = fmaf(a4[i].y, x1.w, acc[i][3]);
                acc[i][0] = fmaf(a4[i].z, x2.x, acc[i][0]);
                acc[i][1] = fmaf(a4[i].z, x2.y, acc[i][1]);
                acc[i][2] = fmaf(a4[i].z, x2.z, acc[i][2]);
                acc[i][3] = fmaf(a4[i].z, x2.w, acc[i][3]);
                acc[i][0] = fmaf(a4[i].w, x3.x, acc[i][0]);
                acc[i][1] = fmaf(a4[i].w, x3.y, acc[i][1]);
                acc[i][2] = fmaf(a4[i].w, x3.z, acc[i][2]);
                acc[i][3] = fmaf(a4[i].w, x3.w, acc[i][3]);
            }
        }
    }
#pragma unroll
    for (int i = 0; i < 9; i++) {
        float bv = __ldg(b2f + tm + i);
        float4 hv;
        hv.x = fmaxf(acc[i][0] + bv, 0.f);
        hv.y = fmaxf(acc[i][1] + bv, 0.f);
        hv.z = fmaxf(acc[i][2] + bv, 0.f);
        hv.w = fmaxf(acc[i][3] + bv, 0.f);
        *(float4*)&Hs[(tm + i) * 36 + tn] = hv;
    }

    // ---- phase 2: T2 = fW1A * H, 18 chunks of 8
    float acc2[9][4];
#pragma unroll
    for (int i = 0; i < 9; i++)
#pragma unroll
        for (int j = 0; j < 4; j++) acc2[i][j] = 0.f;

#pragma unroll
    for (int r = 0; r < 3; r++) {
        int e = tid + r * 128;
        if (e < 288) w4[r] = ((const float4*)fW1Ac)[e];
    }
    for (int kc = 0; kc < 18; kc++) {
        __syncthreads();
#pragma unroll
        for (int r = 0; r < 3; r++) {
            int e = tid + r * 128;
            if (e < 288) ((float4*)Ws)[e] = w4[r];
        }
        __syncthreads();
        if (kc + 1 < 18) {
            const float4* wc = (const float4*)(fW1Ac + (size_t)(kc + 1) * 1152);
#pragma unroll
            for (int r = 0; r < 3; r++) {
                int e = tid + r * 128;
                if (e < 288) w4[r] = wc[e];
            }
        }
        int kb = kc * 8;
#pragma unroll
        for (int g = 0; g < 2; g++) {
            float4 a4[9];
#pragma unroll
            for (int i = 0; i < 9; i++)
                a4[i] = *(const float4*)&Ws[(tm + i) * 8 + g * 4];
            float4 x0 = *(const float4*)&Hs[(kb + g * 4 + 0) * 36 + tn];
            float4 x1 = *(const float4*)&Hs[(kb + g * 4 + 1) * 36 + tn];
            float4 x2 = *(const float4*)&Hs[(kb + g * 4 + 2) * 36 + tn];
            float4 x3 = *(const float4*)&Hs[(kb + g * 4 + 3) * 36 + tn];
#pragma unroll
            for (int i = 0; i < 9; i++) {
                acc2[i][0] = fmaf(a4[i].x, x0.x, acc2[i][0]);
                acc2[i][1] = fmaf(a4[i].x, x0.y, acc2[i][1]);
                acc2[i][2] = fmaf(a4[i].x, x0.z, acc2[i][2]);
                acc2[i][3] = fmaf(a4[i].x, x0.w, acc2[i][3]);
                acc2[i][0] = fmaf(a4[i].y, x1.x, acc2[i][0]);
                acc2[i][1] = fmaf(a4[i].y, x1.y, acc2[i][1]);
                acc2[i][2] = fmaf(a4[i].y, x1.z, acc2[i][2]);
                acc2[i][3] = fmaf(a4[i].y, x1.w, acc2[i][3]);
                acc2[i][0] = fmaf(a4[i].z, x2.x, acc2[i][0]);
                acc2[i][1] = fmaf(a4[i].z, x2.y, acc2[i][1]);
                acc2[i][2] = fmaf(a4[i].z, x2.z, acc2[i][2]);
                acc2[i][3] = fmaf(a4[i].z, x2.w, acc2[i][3]);
                acc2[i][0] = fmaf(a4[i].w, x3.x, acc2[i][0]);
                acc2[i][1] = fmaf(a4[i].w, x3.y, acc2[i][1]);
                acc2[i][2] = fmaf(a4[i].w, x3.z, acc2[i][2]);
                acc2[i][3] = fmaf(a4[i].w, x3.w, acc2[i][3]);
            }
        }
    }
#pragma unroll
    for (int j = 0; j < 4; j++) {
        size_t base = ((size_t)bq * N2_ + n0 + tn + j) * I1_ + tm;
#pragma unroll
        for (int i = 0; i < 9; i++) T2t[base + i] = acc2[i][j];
    }
}

// ---------------------------------------------------------------------------
// fusedB: 128 threads, micro-tile 9x4 (TX=16, TY=8), n-tile 64, grid (16,32)
// Inline FP1 interpolation into smem (no global h3).
// ---------------------------------------------------------------------------
__global__ __launch_bounds__(128)
void fusedB_kernel(const float* __restrict__ T2t,    // (32,256,144)
                   const int* __restrict__ idx1,
                   const float* __restrict__ wt1,
                   const float* __restrict__ s1,     // (2,144,1024)
                   const float* __restrict__ fb1f,
                   const float* __restrict__ d1v,
                   const float* __restrict__ fW2c,   // (18,72,8)
                   const float* __restrict__ fb2f,
                   const float* __restrict__ gW1Ac,  // (9,72,8)
                   float* __restrict__ T4t) {        // (32,1024,72)
    extern __shared__ float smem[];
    float* Ws  = smem;                 // 576
    float* H3s = smem + 576;           // 144 x 72
    float* Hs  = H3s + 144 * 72;       // 72 x 72

    const int bq = blockIdx.y, b = bq >> 4;
    const int n0 = blockIdx.x * 64;
    const int tid = threadIdx.x;

    // ---- gather: H3s[c][nu], 64 nu x 144 c; 128 threads = 64 nu x 2 cgroups
    {
        int nu = tid & 63, cg = tid >> 6;     // cg in {0,1}, 72 channels each
        size_t o = ((size_t)b * N1_ + n0 + nu) * 3;
        int j0 = idx1[o], j1 = idx1[o + 1], j2 = idx1[o + 2];
        float w0 = wt1[o], w1 = wt1[o + 1], w2 = wt1[o + 2];
        const float4* p0 = (const float4*)(T2t + ((size_t)bq * N2_ + j0) * I1_ + cg * 72);
        const float4* p1 = (const float4*)(T2t + ((size_t)bq * N2_ + j1) * I1_ + cg * 72);
        const float4* p2 = (const float4*)(T2t + ((size_t)bq * N2_ + j2) * I1_ + cg * 72);
        const float* s1b = s1 + ((size_t)b * I1_ + cg * 72) * N1_ + n0 + nu;
#pragma unroll
        for (int cc = 0; cc < 18; cc++) {
            float4 a0 = p0[cc], a1 = p1[cc], a2 = p2[cc];
            int c = cg * 72 + cc * 4;
            float v0 = w0 * a0.x + w1 * a1.x + w2 * a2.x + s1b[(size_t)(cc * 4 + 0) * N1_] + __ldg(fb1f + c + 0) + __ldg(d1v + c + 0);
            float v1 = w0 * a0.y + w1 * a1.y + w2 * a2.y + s1b[(size_t)(cc * 4 + 1) * N1_] + __ldg(fb1f + c + 1) + __ldg(d1v + c + 1);
            float v2 = w0 * a0.z + w1 * a1.z + w2 * a2.z + s1b[(size_t)(cc * 4 + 2) * N1_] + __ldg(fb1f + c + 2) + __ldg(d1v + c + 2);
            float v3 = w0 * a0.w + w1 * a1.w + w2 * a2.w + s1b[(size_t)(cc * 4 + 3) * N1_] + __ldg(fb1f + c + 3) + __ldg(d1v + c + 3);
            H3s[(c + 0) * 72 + nu] = fmaxf(v0, 0.f);
            H3s[(c + 1) * 72 + nu] = fmaxf(v1, 0.f);
            H3s[(c + 2) * 72 + nu] = fmaxf(v2, 0.f);
            H3s[(c + 3) * 72 + nu] = fmaxf(v3, 0.f);
        }
    }
    __syncthreads();

    const int tx = tid & 15, ty = tid >> 4;   // 16 x 8
    const int tm = ty * 9, tn = tx * 4;

    // ---- phase 1: Hs = ReLU(fW2 * H3 + fb2), K=144 (18 chunks)
    float acc[9][4];
#pragma unroll
    for (int i = 0; i < 9; i++)
#pragma unroll
        for (int j = 0; j < 4; j++) acc[i][j] = 0.f;

    float4 w4[2];
#pragma unroll
    for (int r = 0; r < 2; r++) {
        int e = tid + r * 128;
        if (e < 144) w4[r] = ((const float4*)fW2c)[e];
    }
    for (int kc = 0; kc < 18; kc++) {
        __syncthreads();
#pragma unroll
        for (int r = 0; r < 2; r++) {
            int e = tid + r * 128;
            if (e < 144) ((float4*)Ws)[e] = w4[r];
        }
        __syncthreads();
        if (kc + 1 < 18) {
            const float4* wc = (const float4*)(fW2c + (size_t)(kc + 1) * 576);
#pragma unroll
            for (int r = 0; r < 2; r++) {
                int e = tid + r * 128;
                if (e < 144) w4[r] = wc[e];
            }
        }
        int kb = kc * 8;
#pragma unroll
        for (int g = 0; g < 2; g++) {
            float4 a4[9];
#pragma unroll
            for (int i = 0; i < 9; i++)
                a4[i] = *(const float4*)&Ws[(tm + i) * 8 + g * 4];
            float4 x0 = *(const float4*)&H3s[(kb + g * 4 + 0) * 72 + tn];
            float4 x1 = *(const float4*)&H3s[(kb + g * 4 + 1) * 72 + tn];
            float4 x2 = *(const float4*)&H3s[(kb + g * 4 + 2) * 72 + tn];
            float4 x3 = *(const float4*)&H3s[(kb + g * 4 + 3) * 72 + tn];
#pragma unroll
            for (int i = 0; i < 9; i++) {
                acc[i][0] = fmaf(a4[i].x, x0.x, acc[i][0]);
                acc[i][1] = fmaf(a4[i].x, x0.y, acc[i][1]);
                acc[i][2] = fmaf(a4[i].x, x0.z, acc[i][2]);
                acc[i][3] = fmaf(a4[i].x, x0.w, acc[i][3]);
                acc[i][0] = fmaf(a4[i].y, x1.x, acc[i][0]);
                acc[i][1] = fmaf(a4[i].y, x1.y, acc[i][1]);
                acc[i][2] = fmaf(a4[i].y, x1.z, acc[i][2]);
                acc[i][3] = fmaf(a4[i].y, x1.w, acc[i][3]);
                acc[i][0] = fmaf(a4[i].z, x2.x, acc[i][0]);
                acc[i][1] = fmaf(a4[i].z, x2.y, acc[i][1]);
                acc[i][2] = fmaf(a4[i].z, x2.z, acc[i][2]);
                acc[i][3] = fmaf(a4[i].z, x2.w, acc[i][3]);
                acc[i][0] = fmaf(a4[i].w, x3.x, acc[i][0]);
                acc[i][1] = fmaf(a4[i].w, x3.y, acc[i][1]);
                acc[i][2] = fmaf(a4[i].w, x3.z, acc[i][2]);
                acc[i][3] = fmaf(a4[i].w, x3.w, acc[i][3]);
            }
        }
    }
#pragma unroll
    for (int i = 0; i < 9; i++) {
        float bv = __ldg(fb2f + tm + i);
        float4 hv;
        hv.x = fmaxf(acc[i][0] + bv, 0.f);
        hv.y = fmaxf(acc[i][1] + bv, 0.f);
        hv.z = fmaxf(acc[i][2] + bv, 0.f);
        hv.w = fmaxf(acc[i][3] + bv, 0.f);
        *(float4*)&Hs[(tm + i) * 72 + tn] = hv;
    }

    // ---- phase 2: T4 = gW1A * Hs, K=72 (9 chunks)
    float acc2[9][4];
#pragma unroll
    for (int i = 0; i < 9; i++)
#pragma unroll
        for (int j = 0; j < 4; j++) acc2[i][j] = 0.f;

#pragma unroll
    for (int r = 0; r < 2; r++) {
        int e = tid + r * 128;
        if (e < 144) w4[r] = ((const float4*)gW1Ac)[e];
    }
    for (int kc = 0; kc < 9; kc++) {
        __syncthreads();
#pragma unroll
        for (int r = 0; r < 2; r++) {
            int e = tid + r * 128;
            if (e < 144) ((float4*)Ws)[e] = w4[r];
        }
        __syncthreads();
        if (kc + 1 < 9) {
            const float4* wc = (const float4*)(gW1Ac + (size_t)(kc + 1) * 576);
#pragma unroll
            for (int r = 0; r < 2; r++) {
                int e = tid + r * 128;
                if (e < 144) w4[r] = wc[e];
            }
        }
        int kb = kc * 8;
#pragma unroll
        for (int g = 0; g < 2; g++) {
            float4 a4[9];
#pragma unroll
            for (int i = 0; i < 9; i++)
                a4[i] = *(const float4*)&Ws[(tm + i) * 8 + g * 4];
            float4 x0 = *(const float4*)&Hs[(kb + g * 4 + 0) * 72 + tn];
            float4 x1 = *(const float4*)&Hs[(kb + g * 4 + 1) * 72 + tn];
            float4 x2 = *(const float4*)&Hs[(kb + g * 4 + 2) * 72 + tn];
            float4 x3 = *(const float4*)&Hs[(kb + g * 4 + 3) * 72 + tn];
#pragma unroll
            for (int i = 0; i < 9; i++) {
                acc2[i][0] = fmaf(a4[i].x, x0.x, acc2[i][0]);
                acc2[i][1] = fmaf(a4[i].x, x0.y, acc2[i][1]);
                acc2[i][2] = fmaf(a4[i].x, x0.z, acc2[i][2]);
                acc2[i][3] = fmaf(a4[i].x, x0.w, acc2[i][3]);
                acc2[i][0] = fmaf(a4[i].y, x1.x, acc2[i][0]);
                acc2[i][1] = fmaf(a4[i].y, x1.y, acc2[i][1]);
                acc2[i][2] = fmaf(a4[i].y, x1.z, acc2[i][2]);
                acc2[i][3] = fmaf(a4[i].y, x1.w, acc2[i][3]);
                acc2[i][0] = fmaf(a4[i].z, x2.x, acc2[i][0]);
                acc2[i][1] = fmaf(a4[i].z, x2.y, acc2[i][1]);
                acc2[i][2] = fmaf(a4[i].z, x2.z, acc2[i][2]);
                acc2[i][3] = fmaf(a4[i].z, x2.w, acc2[i][3]);
                acc2[i][0] = fmaf(a4[i].w, x3.x, acc2[i][0]);
                acc2[i][1] = fmaf(a4[i].w, x3.y, acc2[i][1]);
                acc2[i][2] = fmaf(a4[i].w, x3.z, acc2[i][2]);
                acc2[i][3] = fmaf(a4[i].w, x3.w, acc2[i][3]);
            }
        }
    }
#pragma unroll
    for (int j = 0; j < 4; j++) {
        size_t base = ((size_t)bq * N1_ + n0 + tn + j) * I2_ + tm;
#pragma unroll
        for (int i = 0; i < 9; i++) T4t[base + i] = acc2[i][j];
    }
}

// ---------------------------------------------------------------------------
// Fused final: interp(T4t)+skip+relu (FP2-L1), FP2-L2+relu, out projection
// ---------------------------------------------------------------------------
__global__ __launch_bounds__(256)
void final_fuse_kernel(const float* __restrict__ T4t,
                       const int* __restrict__ idx,
                       const float* __restrict__ wt,
                       const float* __restrict__ sa0f,
                       const float* __restrict__ C0,
                       const float* __restrict__ d0v,
                       const float* __restrict__ gb1,
                       const float* __restrict__ gW2,
                       const float* __restrict__ gb2,
                       const float* __restrict__ ow,
                       const float* __restrict__ ob,
                       float* __restrict__ out) {
    __shared__ float gT[I2_ * I3_];   // gT[c*36+m] = gW2[m][c]
    __shared__ float c0s[I2_ * 3];
    __shared__ float bs[I2_];
    __shared__ float gbs[I3_], ows[I3_];
    int tid = threadIdx.x;
    for (int e = tid; e < I2_ * I3_; e += 256) {
        int c = e / I3_, m = e % I3_;
        gT[e] = gW2[m * I2_ + c];
    }
    if (tid < I2_ * 3) c0s[tid] = C0[tid];
    if (tid < I2_) bs[tid] = d0v[tid] + gb1[tid];
    if (tid < I3_) { gbs[tid] = gb2[tid]; ows[tid] = ow[tid]; }
    __syncthreads();

    int bq = blockIdx.y, b = bq >> 4;
    int nu = blockIdx.x * 256 + tid;
    size_t o = ((size_t)b * N0_ + nu) * 3;
    int j0 = idx[o], j1 = idx[o + 1], j2 = idx[o + 2];
    float w0 = wt[o], w1 = wt[o + 1], w2 = wt[o + 2];
    const float4* p0 = (const float4*)(T4t + ((size_t)bq * N1_ + j0) * I2_);
    const float4* p1 = (const float4*)(T4t + ((size_t)bq * N1_ + j1) * I2_);
    const float4* p2 = (const float4*)(T4t + ((size_t)bq * N1_ + j2) * I2_);
    float f0 = sa0f[((size_t)b * 3 + 0) * N0_ + nu];
    float f1 = sa0f[((size_t)b * 3 + 1) * N0_ + nu];
    float f2 = sa0f[((size_t)b * 3 + 2) * N0_ + nu];

    float acc[I3_];
#pragma unroll
    for (int m = 0; m < I3_; m++) acc[m] = 0.f;

#pragma unroll 3
    for (int cc = 0; cc < 18; cc++) {
        float4 a0 = p0[cc], a1 = p1[cc], a2 = p2[cc];
        int c = cc * 4;
        float hv[4];
        hv[0] = fmaxf(w0 * a0.x + w1 * a1.x + w2 * a2.x + c0s[(c + 0) * 3] * f0 + c0s[(c + 0) * 3 + 1] * f1 + c0s[(c + 0) * 3 + 2] * f2 + bs[c + 0], 0.f);
        hv[1] = fmaxf(w0 * a0.y + w1 * a1.y + w2 * a2.y + c0s[(c + 1) * 3] * f0 + c0s[(c + 1) * 3 + 1] * f1 + c0s[(c + 1) * 3 + 2] * f2 + bs[c + 1], 0.f);
        hv[2] = fmaxf(w0 * a0.z + w1 * a1.z + w2 * a2.z + c0s[(c + 2) * 3] * f0 + c0s[(c + 2) * 3 + 1] * f1 + c0s[(c + 2) * 3 + 2] * f2 + bs[c + 2], 0.f);
        hv[3] = fmaxf(w0 * a0.w + w1 * a1.w + w2 * a2.w + c0s[(c + 3) * 3] * f0 + c0s[(c + 3) * 3 + 1] * f1 + c0s[(c + 3) * 3 + 2] * f2 + bs[c + 3], 0.f);
#pragma unroll
        for (int q = 0; q < 4; q++) {
            const float4* g4 = (const float4*)&gT[(c + q) * I3_];
#pragma unroll
            for (int mm = 0; mm < 9; mm++) {
                float4 g = g4[mm];
                acc[mm * 4 + 0] = fmaf(g.x, hv[q], acc[mm * 4 + 0]);
                acc[mm * 4 + 1] = fmaf(g.y, hv[q], acc[mm * 4 + 1]);
                acc[mm * 4 + 2] = fmaf(g.z, hv[q], acc[mm * 4 + 2]);
                acc[mm * 4 + 3] = fmaf(g.w, hv[q], acc[mm * 4 + 3]);
            }
        }
    }
    float r = ob[0];
#pragma unroll
    for (int m = 0; m < I3_; m++) r = fmaf(ows[m], fmaxf(acc[m] + gbs[m], 0.f), r);
    out[(size_t)bq * N0_ + nu] = r;
}

// ---------------------------------------------------------------------------
// Launch
// ---------------------------------------------------------------------------
static inline int cdiv(int a, int b) { return (a + b - 1) / b; }

extern "C" void kernel_launch(void* const* d_in, const int* in_sizes, int n_in,
                              void* d_out, int out_size) {
    const float* x        = (const float*)d_in[0];
    const float* mask     = (const float*)d_in[1];
    const float* sa0_feat = (const float*)d_in[2];
    const float* sa1_feat = (const float*)d_in[3];
    const float* sa0_xyz  = (const float*)d_in[4];
    const float* sa1_xyz  = (const float*)d_in[5];
    const float* sa2_xyz  = (const float*)d_in[6];
    const float* w1       = (const float*)d_in[7];
    const float* b1       = (const float*)d_in[8];
    const float* bn1      = (const float*)d_in[9];
    const float* w2       = (const float*)d_in[10];
    const float* b2       = (const float*)d_in[11];
    const float* bn2      = (const float*)d_in[12];
    const float* a1_w     = (const float*)d_in[13];
    const float* a1_b     = (const float*)d_in[14];
    const float* a2_w     = (const float*)d_in[15];
    const float* a2_b     = (const float*)d_in[16];
    const float* fp1_w1   = (const float*)d_in[17];
    const float* fp1_b1   = (const float*)d_in[18];
    const float* fp1_bn1  = (const float*)d_in[19];
    const float* fp1_w2   = (const float*)d_in[20];
    const float* fp1_b2   = (const float*)d_in[21];
    const float* fp1_bn2  = (const float*)d_in[22];
    const float* fp2_w1   = (const float*)d_in[23];
    const float* fp2_b1   = (const float*)d_in[24];
    const float* fp2_bn1  = (const float*)d_in[25];
    const float* fp2_w2   = (const float*)d_in[26];
    const float* fp2_b2   = (const float*)d_in[27];
    const float* fp2_bn2  = (const float*)d_in[28];
    const float* out_w    = (const float*)d_in[29];
    const float* out_b    = (const float*)d_in[30];
    float* out = (float*)d_out;

    float *W1f, *b1f, *W2c, *b2f, *fW1Ac, *fb1f, *fW2c, *fb2f, *gW1Ac, *gb1f, *gW2f, *gb2f;
    float *C1, *d1, *C0, *d0;
    float *Tx, *T2t, *s1, *T4t;
    int *idx1, *idx2;
    float *wt1, *wt2;
    cudaGetSymbolAddress((void**)&W1f, g_W1f);     cudaGetSymbolAddress((void**)&b1f, g_b1f);
    cudaGetSymbolAddress((void**)&W2c, g_W2c);     cudaGetSymbolAddress((void**)&b2f, g_b2f);
    cudaGetSymbolAddress((void**)&fW1Ac, g_fW1Ac); cudaGetSymbolAddress((void**)&fb1f, g_fb1f);
    cudaGetSymbolAddress((void**)&fW2c, g_fW2c);   cudaGetSymbolAddress((void**)&fb2f, g_fb2f);
    cudaGetSymbolAddress((void**)&gW1Ac, g_gW1Ac); cudaGetSymbolAddress((void**)&gb1f, g_gb1f);
    cudaGetSymbolAddress((void**)&gW2f, g_gW2f);   cudaGetSymbolAddress((void**)&gb2f, g_gb2f);
    cudaGetSymbolAddress((void**)&C1, g_C1);       cudaGetSymbolAddress((void**)&d1, g_d1);
    cudaGetSymbolAddress((void**)&C0, g_C0);       cudaGetSymbolAddress((void**)&d0, g_d0);
    cudaGetSymbolAddress((void**)&Tx, g_Tx);
    cudaGetSymbolAddress((void**)&T2t, g_T2t);
    cudaGetSymbolAddress((void**)&s1, g_s1);
    cudaGetSymbolAddress((void**)&T4t, g_T4t);
    cudaGetSymbolAddress((void**)&idx1, g_idx1);   cudaGetSymbolAddress((void**)&wt1, g_wt1);
    cudaGetSymbolAddress((void**)&idx2, g_idx2);   cudaGetSymbolAddress((void**)&wt2, g_wt2);

    // 1) weight prep
    {
        dim3 grid(cdiv(DIM_ * DIM_, 256), 8);
        prep_kernel<<<grid, 256>>>(w1, b1, bn1, w2, b2, bn2,
                                   fp1_w1, fp1_b1, fp1_bn1, fp1_w2, fp1_b2, fp1_bn2,
                                   fp2_w1, fp2_b1, fp2_bn1, fp2_w2, fp2_b2, fp2_bn2,
                                   a1_w, a1_b, a2_w, a2_b,
                                   W1f, b1f, W2c, b2f, fW1Ac, fb1f, fW2c, fb2f,
                                   gW1Ac, gb1f, gW2f, gb2f, C1, d1, C0, d0);
    }
    // 2) util: Tx GEMM + s1 GEMM + both three_nn levels (296 blocks)
    util_kernel<<<296, 256>>>(W1f, x, Tx, C1, sa1_feat, s1,
                              sa0_xyz, sa1_xyz, sa2_xyz,
                              idx1, wt1, idx2, wt2);
    // 3) fusedA
    {
        dim3 grid(N2_ / 32, BQ_);
        fusedA_kernel<<<grid, 128>>>(W2c, b2f, fW1Ac, Tx, mask, W1f, b1f, T2t);
    }
    // 4) fusedB (inline FP1 interp)
    {
        const int smem_bytes = (576 + 144 * 72 + 72 * 72) * 4;
        cudaFuncSetAttribute(fusedB_kernel,
                             cudaFuncAttributeMaxDynamicSharedMemorySize, smem_bytes);
        dim3 grid(N1_ / 64, BQ_);
        fusedB_kernel<<<grid, 128, smem_bytes>>>(T2t, idx1, wt1, s1, fb1f, d1,
                                                 fW2c, fb2f, gW1Ac, T4t);
    }
    // 5) fused final
    {
        dim3 grid(N0_ / 256, BQ_);
        final_fuse_kernel<<<grid, 256>>>(T4t, idx2, wt2, sa0_feat, C0, d0, gb1f,
                                         gW2f, gb2f, out_w, out_b, out);
    }
}